// round 6
// baseline (speedup 1.0000x reference)
#include <cuda_runtime.h>
#include <math_constants.h>
#include <cstdint>

// Problem constants
#define Bsz 2
#define Sq  2048
#define Dm  2048
#define Hh  16
#define Ll  512
#define HDm 128
#define Mrows (Bsz*Sq)      // 4096

// ---------------------------------------------------------------------------
// Scratch (static device globals — no runtime allocation allowed)
// ---------------------------------------------------------------------------
__device__ float g_qlat [(size_t)Mrows * Ll];       //  8 MB
__device__ float g_q    [(size_t)Mrows * Dm];       // 32 MB
__device__ float g_kvlat[(size_t)Mrows * Ll];       //  8 MB
__device__ float g_kv   [(size_t)Mrows * 2 * Dm];   // 64 MB
__device__ float g_attn [(size_t)Mrows * Dm];       // 32 MB

// ---------------------------------------------------------------------------
// Helpers
// ---------------------------------------------------------------------------
__device__ __forceinline__ uint32_t smem_u32(const void* p) {
    uint32_t a;
    asm("{ .reg .u64 t; cvta.to.shared.u64 t, %1; cvt.u32.u64 %0, t; }"
        : "=r"(a) : "l"(p));
    return a;
}
__device__ __forceinline__ void cp16(uint32_t dst, const void* src) {
    asm volatile("cp.async.cg.shared.global [%0], [%1], 16;"
                 :: "r"(dst), "l"(src) : "memory");
}
__device__ __forceinline__ float rna_tf32(float a) {
    float r;
    asm("cvt.rna.tf32.f32 %0, %1;" : "=f"(r) : "f"(a));
    return r;
}
// mma.sync m16n8k8 tf32 (baseline PTX since sm_80 — compiles on sm_103)
__device__ __forceinline__ void mma_tf32(
    float c[4], uint32_t a0, uint32_t a1, uint32_t a2, uint32_t a3,
    uint32_t b0, uint32_t b1)
{
    asm volatile(
        "mma.sync.aligned.m16n8k8.row.col.f32.tf32.tf32.f32 "
        "{%0,%1,%2,%3}, {%4,%5,%6,%7}, {%8,%9}, {%0,%1,%2,%3};"
        : "+f"(c[0]), "+f"(c[1]), "+f"(c[2]), "+f"(c[3])
        : "r"(a0), "r"(a1), "r"(a2), "r"(a3), "r"(b0), "r"(b1));
}

// ---------------------------------------------------------------------------
// 3xTF32 GEMM body: C[M,N] = A[M,K] @ W[K,N] + bias[N]
// CTA tile 128x128, BK=16, 256 threads (8 warps, warp tile 64x32).
// ---------------------------------------------------------------------------
#define ASTR 20
#define BSTR 136

__device__ __forceinline__ void gemm_body(
    int M, int N, int K,
    const float* __restrict__ A,
    const float* __restrict__ W,
    const float* __restrict__ bias,
    float* __restrict__ C,
    int m0, int n0,
    float* As, float* Bs)
{
    const int tid = threadIdx.x;
    const int wid = tid >> 5, lid = tid & 31;
    const int g = lid >> 2, lq = lid & 3;
    const int warp_m = (wid & 1) * 64;
    const int warp_n = (wid >> 1) * 32;
    const int nc = K >> 4;

    const uint32_t sA0 = smem_u32(As);
    const uint32_t sB0 = smem_u32(Bs);

    float acc[4][4][4];
    #pragma unroll
    for (int mt = 0; mt < 4; mt++)
        #pragma unroll
        for (int nt = 0; nt < 4; nt++)
            #pragma unroll
            for (int e = 0; e < 4; e++) acc[mt][nt][e] = 0.f;

    auto load_tile = [&](int c, int stg) {
        const int k0 = c << 4;
        const uint32_t sa = sA0 + stg * (128 * ASTR * 4);
        const uint32_t sb = sB0 + stg * (16 * BSTR * 4);
        #pragma unroll
        for (int t = 0; t < 2; t++) {
            int idx = tid + t * 256;
            int m = idx >> 2, k4 = idx & 3;
            cp16(sa + (m * ASTR + k4 * 4) * 4,
                 A + (size_t)(m0 + m) * K + k0 + k4 * 4);
        }
        #pragma unroll
        for (int t = 0; t < 2; t++) {
            int idx = tid + t * 256;
            int k = idx >> 5, nq = idx & 31;
            cp16(sb + (k * BSTR + nq * 4) * 4,
                 W + (size_t)(k0 + k) * N + n0 + nq * 4);
        }
        asm volatile("cp.async.commit_group;" ::: "memory");
    };

    load_tile(0, 0);
    if (nc > 1) load_tile(1, 1);

    for (int c = 0; c < nc; ++c) {
        const int cur = c & 1;
        if (c + 1 < nc) { asm volatile("cp.async.wait_group 1;" ::: "memory"); }
        else            { asm volatile("cp.async.wait_group 0;" ::: "memory"); }
        __syncthreads();

        const float* as = As + cur * (128 * ASTR);
        const float* bs = Bs + cur * (16 * BSTR);

        #pragma unroll
        for (int ks = 0; ks < 2; ks++) {
            const int kb = ks * 8;
            uint32_t Ah[4][4], Al[4][4];
            #pragma unroll
            for (int mt = 0; mt < 4; mt++) {
                const int rbase = warp_m + mt * 16 + g;
                #pragma unroll
                for (int e = 0; e < 4; e++) {
                    const int row = rbase + (e & 1) * 8;
                    const int col = kb + lq + (e >> 1) * 4;
                    float a = as[row * ASTR + col];
                    float h = rna_tf32(a);
                    Ah[mt][e] = __float_as_uint(h);
                    Al[mt][e] = __float_as_uint(rna_tf32(a - h));
                }
            }
            uint32_t Bh[4][2], Bl[4][2];
            #pragma unroll
            for (int nt = 0; nt < 4; nt++) {
                const int nn = warp_n + nt * 8 + g;
                #pragma unroll
                for (int e = 0; e < 2; e++) {
                    const int kk = kb + lq + e * 4;
                    float b = bs[kk * BSTR + nn];
                    float h = rna_tf32(b);
                    Bh[nt][e] = __float_as_uint(h);
                    Bl[nt][e] = __float_as_uint(rna_tf32(b - h));
                }
            }
            #pragma unroll
            for (int mt = 0; mt < 4; mt++)
                #pragma unroll
                for (int nt = 0; nt < 4; nt++) {
                    mma_tf32(acc[mt][nt], Ah[mt][0], Ah[mt][1], Ah[mt][2], Ah[mt][3],
                             Bl[nt][0], Bl[nt][1]);
                    mma_tf32(acc[mt][nt], Al[mt][0], Al[mt][1], Al[mt][2], Al[mt][3],
                             Bh[nt][0], Bh[nt][1]);
                    mma_tf32(acc[mt][nt], Ah[mt][0], Ah[mt][1], Ah[mt][2], Ah[mt][3],
                             Bh[nt][0], Bh[nt][1]);
                }
        }
        __syncthreads();
        if (c + 2 < nc) load_tile(c + 2, cur);
    }

    #pragma unroll
    for (int mt = 0; mt < 4; mt++) {
        const int r0 = m0 + warp_m + mt * 16 + g;
        #pragma unroll
        for (int nt = 0; nt < 4; nt++) {
            const int col = n0 + warp_n + nt * 8 + lq * 2;
            const float2 b2 = *(const float2*)(bias + col);
            float2 o;
            o.x = acc[mt][nt][0] + b2.x;
            o.y = acc[mt][nt][1] + b2.y;
            *(float2*)(C + (size_t)r0 * N + col) = o;
            o.x = acc[mt][nt][2] + b2.x;
            o.y = acc[mt][nt][3] + b2.y;
            *(float2*)(C + (size_t)(r0 + 8) * N + col) = o;
        }
    }
}

__global__ __launch_bounds__(256, 2) void gemm_mma3(
    int M, int N, int K,
    const float* __restrict__ A,
    const float* __restrict__ W,
    const float* __restrict__ bias,
    float* __restrict__ C)
{
    __shared__ __align__(16) float As[2][128 * ASTR];
    __shared__ __align__(16) float Bs[2][16 * BSTR];
    gemm_body(M, N, K, A, W, bias, C,
              blockIdx.y * 128, blockIdx.x * 128, &As[0][0], &Bs[0][0]);
}

// Dual-output variant: two GEMMs sharing the same A (x), different W/bias/C.
// blockIdx.x < nx1 -> output 1, else output 2. Both have width N.
__global__ __launch_bounds__(256, 2) void gemm_mma3_dual(
    int M, int N, int K,
    const float* __restrict__ A,
    const float* __restrict__ W1, const float* __restrict__ b1, float* __restrict__ C1,
    const float* __restrict__ W2, const float* __restrict__ b2, float* __restrict__ C2,
    int nx1)
{
    __shared__ __align__(16) float As[2][128 * ASTR];
    __shared__ __align__(16) float Bs[2][16 * BSTR];
    const int bx = blockIdx.x;
    const bool first = bx < nx1;
    const float* W    = first ? W1 : W2;
    const float* bias = first ? b1 : b2;
    float*       C    = first ? C1 : C2;
    const int n0 = (first ? bx : bx - nx1) * 128;
    gemm_body(M, N, K, A, W, bias, C,
              blockIdx.y * 128, n0, &As[0][0], &Bs[0][0]);
}

// ---------------------------------------------------------------------------
// LayerNorm over last dim (512), in place. One block (256 threads) per row.
// ---------------------------------------------------------------------------
__global__ __launch_bounds__(256) void ln512(
    float* __restrict__ x,
    const float* __restrict__ g,
    const float* __restrict__ b)
{
    const int row = blockIdx.x;
    float* xr = x + (size_t)row * Ll;
    const int tid = threadIdx.x;

    float v0 = xr[tid];
    float v1 = xr[tid + 256];
    float s  = v0 + v1;
    float sq = v0 * v0 + v1 * v1;

    #pragma unroll
    for (int o = 16; o > 0; o >>= 1) {
        s  += __shfl_xor_sync(0xffffffffu, s,  o);
        sq += __shfl_xor_sync(0xffffffffu, sq, o);
    }
    __shared__ float ss[8], ssq[8];
    __shared__ float mean_sh, inv_sh;
    const int w = tid >> 5;
    if ((tid & 31) == 0) { ss[w] = s; ssq[w] = sq; }
    __syncthreads();
    if (tid == 0) {
        float S = 0.f, SQ = 0.f;
        #pragma unroll
        for (int i = 0; i < 8; i++) { S += ss[i]; SQ += ssq[i]; }
        float m = S * (1.f / Ll);
        float var = SQ * (1.f / Ll) - m * m;
        mean_sh = m;
        inv_sh = rsqrtf(var + 1e-5f);
    }
    __syncthreads();
    const float m = mean_sh, inv = inv_sh;
    xr[tid]       = (v0 - m) * inv * g[tid]       + b[tid];
    xr[tid + 256] = (v1 - m) * inv * g[tid + 256] + b[tid + 256];
}

// ---------------------------------------------------------------------------
// Flash attention via mma.sync tf32 (3xTF32), causal + padding mask.
// CTA: 128 queries (8 warps x m16), key tiles of 64, HD=128.  (unchanged R5)
// ---------------------------------------------------------------------------
#define KSTR 132
#define VSTR 136
#define PSTR 68
#define AKS_OFF(s) ((s) * 8448)
#define AVS_OFF(s) (16896 + (s) * 8704)
#define APS_OFF 34304
#define AMASK_BYTE_OFF 172032
#define ATT_SMEM (172032 + 128)

__global__ __launch_bounds__(256, 1) void attn_mma(
    const float* __restrict__ q,
    const float* __restrict__ kv,
    const unsigned char* __restrict__ mask,
    float* __restrict__ out)
{
    extern __shared__ float sm[];
    unsigned char* smb = (unsigned char*)sm;

    const int bh = blockIdx.y;
    const int b = bh >> 4, h = bh & 15;
    const int qb = gridDim.x - 1 - blockIdx.x;   // heavy blocks first
    const int q0 = qb * 128;
    const int ktmax = 2 * qb + 1;

    const int tid = threadIdx.x;
    const int wid = tid >> 5, lid = tid & 31;
    const int g = lid >> 2, lq = lid & 3;
    const int warp_m = wid * 16;

    const float* Qp = q  + (size_t)b * Sq * Dm       + (size_t)h * HDm;
    const float* Kp = kv + (size_t)b * Sq * (2 * Dm) + (size_t)h * HDm;
    const float* Vp = Kp + Dm;
    const unsigned char* mp = mask + (size_t)b * Sq;

    const uint32_t smu = smem_u32(sm);

    // stage Q (128x128) through the K buffers, then pull to registers
    #pragma unroll
    for (int t = 0; t < 16; t++) {
        int idx = tid + t * 256;
        int row = idx >> 5, c4 = (idx & 31) << 2;
        cp16(smu + (row * KSTR + c4) * 4, Qp + (size_t)(q0 + row) * Dm + c4);
    }
    asm volatile("cp.async.commit_group;" ::: "memory");
    asm volatile("cp.async.wait_group 0;" ::: "memory");
    __syncthreads();

    float Qr[16][4];
    #pragma unroll
    for (int c = 0; c < 16; c++)
        #pragma unroll
        for (int e = 0; e < 4; e++)
            Qr[c][e] = sm[(warp_m + g + (e & 1) * 8) * KSTR + c * 8 + lq + (e >> 1) * 4];
    __syncthreads();

    auto load_stage = [&](int kt, int s) {
        const int k0 = kt * 64;
        #pragma unroll
        for (int t = 0; t < 8; t++) {
            int idx = tid + t * 256;
            int row = idx >> 5, c4 = (idx & 31) << 2;
            size_t base = (size_t)(k0 + row) * (2 * Dm) + c4;
            cp16(smu + (AKS_OFF(s) + row * KSTR + c4) * 4, Kp + base);
            cp16(smu + (AVS_OFF(s) + row * VSTR + c4) * 4, Vp + base);
        }
        if (tid < 4)
            cp16(smu + AMASK_BYTE_OFF + s * 64 + tid * 16, mp + k0 + tid * 16);
        asm volatile("cp.async.commit_group;" ::: "memory");
    };

    load_stage(0, 0);

    const int row0 = q0 + warp_m + g;
    const int row1 = row0 + 8;
    float m_i0 = -CUDART_INF_F, m_i1 = -CUDART_INF_F;
    float l0 = 0.f, l1 = 0.f;
    float acc[16][4];
    #pragma unroll
    for (int nt = 0; nt < 16; nt++)
        #pragma unroll
        for (int e = 0; e < 4; e++) acc[nt][e] = 0.f;

    const float scale = 0.08838834764831845f;   // 1/sqrt(128)

    for (int kt = 0; kt <= ktmax; ++kt) {
        const int st = kt & 1;
        asm volatile("cp.async.wait_group 0;" ::: "memory");
        __syncthreads();
        if (kt < ktmax) load_stage(kt + 1, st ^ 1);

        const float* ks = sm + AKS_OFF(st);
        const float* vs = sm + AVS_OFF(st);
        float* psm = sm + APS_OFF;
        const unsigned char* mk = smb + AMASK_BYTE_OFF + st * 64;

        // ---- scores: S = Q @ K^T  (3xTF32) ----
        float sc[8][4];
        #pragma unroll
        for (int nt = 0; nt < 8; nt++)
            #pragma unroll
            for (int e = 0; e < 4; e++) sc[nt][e] = 0.f;

        #pragma unroll 4
        for (int k8 = 0; k8 < 16; k8++) {
            const int kc = k8 * 8;
            uint32_t qh[4], qlo[4];
            #pragma unroll
            for (int e = 0; e < 4; e++) {
                float a = Qr[k8][e];
                float hh = rna_tf32(a);
                qh[e]  = __float_as_uint(hh);
                qlo[e] = __float_as_uint(rna_tf32(a - hh));
            }
            #pragma unroll
            for (int nt = 0; nt < 8; nt++) {
                const float* kr = ks + (nt * 8 + g) * KSTR + kc + lq;
                float b0 = kr[0], b1 = kr[4];
                float h0 = rna_tf32(b0), h1 = rna_tf32(b1);
                uint32_t bh0 = __float_as_uint(h0), bh1 = __float_as_uint(h1);
                uint32_t bl0 = __float_as_uint(rna_tf32(b0 - h0));
                uint32_t bl1 = __float_as_uint(rna_tf32(b1 - h1));
                mma_tf32(sc[nt], qh[0], qh[1], qh[2], qh[3], bl0, bl1);
                mma_tf32(sc[nt], qlo[0], qlo[1], qlo[2], qlo[3], bh0, bh1);
                mma_tf32(sc[nt], qh[0], qh[1], qh[2], qh[3], bh0, bh1);
            }
        }

        // ---- mask + scale + row max ----
        const bool diag = (kt >= 2 * qb);
        float m0 = -CUDART_INF_F, m1 = -CUDART_INF_F;
        #pragma unroll
        for (int nt = 0; nt < 8; nt++) {
            const int cl = nt * 8 + 2 * lq;
            const int cg = kt * 64 + cl;
            const bool pk0 = mk[cl] != 0, pk1 = mk[cl + 1] != 0;
            float v0 = (pk0 || (diag && cg     > row0)) ? -CUDART_INF_F : sc[nt][0] * scale;
            float v1 = (pk1 || (diag && cg + 1 > row0)) ? -CUDART_INF_F : sc[nt][1] * scale;
            float v2 = (pk0 || (diag && cg     > row1)) ? -CUDART_INF_F : sc[nt][2] * scale;
            float v3 = (pk1 || (diag && cg + 1 > row1)) ? -CUDART_INF_F : sc[nt][3] * scale;
            sc[nt][0] = v0; sc[nt][1] = v1; sc[nt][2] = v2; sc[nt][3] = v3;
            m0 = fmaxf(m0, fmaxf(v0, v1));
            m1 = fmaxf(m1, fmaxf(v2, v3));
        }
        m0 = fmaxf(m0, __shfl_xor_sync(0xffffffffu, m0, 1));
        m0 = fmaxf(m0, __shfl_xor_sync(0xffffffffu, m0, 2));
        m1 = fmaxf(m1, __shfl_xor_sync(0xffffffffu, m1, 1));
        m1 = fmaxf(m1, __shfl_xor_sync(0xffffffffu, m1, 2));

        const float mn0 = fmaxf(m_i0, m0), mn1 = fmaxf(m_i1, m1);
        const float corr0 = (mn0 == -CUDART_INF_F) ? 1.f : __expf(m_i0 - mn0);
        const float corr1 = (mn1 == -CUDART_INF_F) ? 1.f : __expf(m_i1 - mn1);
        const float base0 = (mn0 == -CUDART_INF_F) ? 0.f : mn0;
        const float base1 = (mn1 == -CUDART_INF_F) ? 0.f : mn1;

        float psum0 = 0.f, psum1 = 0.f;
        #pragma unroll
        for (int nt = 0; nt < 8; nt++) {
            float p0 = (sc[nt][0] == -CUDART_INF_F) ? 0.f : __expf(sc[nt][0] - base0);
            float p1 = (sc[nt][1] == -CUDART_INF_F) ? 0.f : __expf(sc[nt][1] - base0);
            float p2 = (sc[nt][2] == -CUDART_INF_F) ? 0.f : __expf(sc[nt][2] - base1);
            float p3 = (sc[nt][3] == -CUDART_INF_F) ? 0.f : __expf(sc[nt][3] - base1);
            sc[nt][0] = p0; sc[nt][1] = p1; sc[nt][2] = p2; sc[nt][3] = p3;
            psum0 += p0 + p1;
            psum1 += p2 + p3;
        }
        psum0 += __shfl_xor_sync(0xffffffffu, psum0, 1);
        psum0 += __shfl_xor_sync(0xffffffffu, psum0, 2);
        psum1 += __shfl_xor_sync(0xffffffffu, psum1, 1);
        psum1 += __shfl_xor_sync(0xffffffffu, psum1, 2);
        l0 = l0 * corr0 + psum0;
        l1 = l1 * corr1 + psum1;
        m_i0 = mn0; m_i1 = mn1;

        #pragma unroll
        for (int nt = 0; nt < 16; nt++) {
            acc[nt][0] *= corr0; acc[nt][1] *= corr0;
            acc[nt][2] *= corr1; acc[nt][3] *= corr1;
        }

        // ---- stage P (per-warp private rows) ----
        __syncwarp();
        #pragma unroll
        for (int nt = 0; nt < 8; nt++) {
            const int cl = nt * 8 + 2 * lq;
            *(float2*)&psm[(warp_m + g) * PSTR + cl]     = make_float2(sc[nt][0], sc[nt][1]);
            *(float2*)&psm[(warp_m + g + 8) * PSTR + cl] = make_float2(sc[nt][2], sc[nt][3]);
        }
        __syncwarp();

        // ---- O += P @ V  (3xTF32) ----
        #pragma unroll 2
        for (int k8 = 0; k8 < 8; k8++) {
            const int kc = k8 * 8;
            uint32_t ph[4], plo[4];
            #pragma unroll
            for (int e = 0; e < 4; e++) {
                float a = psm[(warp_m + g + (e & 1) * 8) * PSTR + kc + lq + (e >> 1) * 4];
                float hh = rna_tf32(a);
                ph[e]  = __float_as_uint(hh);
                plo[e] = __float_as_uint(rna_tf32(a - hh));
            }
            #pragma unroll
            for (int nt = 0; nt < 16; nt++) {
                const float* vr = vs + (kc + lq) * VSTR + nt * 8 + g;
                float b0 = vr[0], b1 = vr[4 * VSTR];
                float h0 = rna_tf32(b0), h1 = rna_tf32(b1);
                uint32_t bh0 = __float_as_uint(h0), bh1 = __float_as_uint(h1);
                uint32_t bl0 = __float_as_uint(rna_tf32(b0 - h0));
                uint32_t bl1 = __float_as_uint(rna_tf32(b1 - h1));
                mma_tf32(acc[nt], ph[0], ph[1], ph[2], ph[3], bl0, bl1);
                mma_tf32(acc[nt], plo[0], plo[1], plo[2], plo[3], bh0, bh1);
                mma_tf32(acc[nt], ph[0], ph[1], ph[2], ph[3], bh0, bh1);
            }
        }
        __syncthreads();
    }

    // ---- epilogue ----
    const float inv0 = (l0 > 0.f) ? (1.f / l0) : 0.f;
    const float inv1 = (l1 > 0.f) ? (1.f / l1) : 0.f;
    float* o0 = out + (size_t)(b * Sq + row0) * Dm + (size_t)h * HDm;
    float* o1 = out + (size_t)(b * Sq + row1) * Dm + (size_t)h * HDm;
    #pragma unroll
    for (int nt = 0; nt < 16; nt++) {
        const int cl = nt * 8 + 2 * lq;
        *(float2*)(o0 + cl) = make_float2(acc[nt][0] * inv0, acc[nt][1] * inv0);
        *(float2*)(o1 + cl) = make_float2(acc[nt][2] * inv1, acc[nt][3] * inv1);
    }
}

// ---------------------------------------------------------------------------
// Launch
// ---------------------------------------------------------------------------
extern "C" void kernel_launch(void* const* d_in, const int* in_sizes, int n_in,
                              void* d_out, int out_size)
{
    const float*         x        = (const float*)d_in[0];
    const unsigned char* mask     = (const unsigned char*)d_in[1];
    const float*         wq_down  = (const float*)d_in[2];
    const float*         bq_down  = (const float*)d_in[3];
    const float*         gq_ln    = (const float*)d_in[4];
    const float*         bq_ln    = (const float*)d_in[5];
    const float*         wq_up    = (const float*)d_in[6];
    const float*         bq_up    = (const float*)d_in[7];
    const float*         wkv_down = (const float*)d_in[8];
    const float*         bkv_down = (const float*)d_in[9];
    const float*         gkv_ln   = (const float*)d_in[10];
    const float*         bkv_ln   = (const float*)d_in[11];
    const float*         wkv_up   = (const float*)d_in[12];
    const float*         bkv_up   = (const float*)d_in[13];
    const float*         w_out    = (const float*)d_in[14];
    const float*         b_out    = (const float*)d_in[15];
    float* out = (float*)d_out;

    float *qlat, *qb, *kvlat, *kvb, *attnb;
    cudaGetSymbolAddress((void**)&qlat,  g_qlat);
    cudaGetSymbolAddress((void**)&qb,    g_q);
    cudaGetSymbolAddress((void**)&kvlat, g_kvlat);
    cudaGetSymbolAddress((void**)&kvb,   g_kv);
    cudaGetSymbolAddress((void**)&attnb, g_attn);

    cudaFuncSetAttribute(attn_mma,
                         cudaFuncAttributeMaxDynamicSharedMemorySize, ATT_SMEM);

    // Fused down-projections (shared input x): qlat | kvlat in one launch
    gemm_mma3_dual<<<dim3(2 * Ll / 128, Mrows / 128), 256>>>(
        Mrows, Ll, Dm, x,
        wq_down, bq_down, qlat,
        wkv_down, bkv_down, kvlat,
        Ll / 128);

    ln512<<<Mrows, 256>>>(qlat, gq_ln, bq_ln);
    ln512<<<Mrows, 256>>>(kvlat, gkv_ln, bkv_ln);

    // Up-projections
    gemm_mma3<<<dim3(Dm / 128, Mrows / 128), 256>>>(Mrows, Dm, Ll, qlat, wq_up, bq_up, qb);
    gemm_mma3<<<dim3(2 * Dm / 128, Mrows / 128), 256>>>(Mrows, 2 * Dm, Ll, kvlat, wkv_up, bkv_up, kvb);

    // Causal multi-head attention (flash, tensor cores, 128q x 8 warps)
    attn_mma<<<dim3(Sq / 128, Bsz * Hh), 256, ATT_SMEM>>>(qb, kvb, mask, attnb);

    // Output projection
    gemm_mma3<<<dim3(Dm / 128, Mrows / 128), 256>>>(Mrows, Dm, Dm, attnb, w_out, b_out, out);
}

// round 7
// speedup vs baseline: 1.1847x; 1.1847x over previous
#include <cuda_runtime.h>
#include <math_constants.h>
#include <cstdint>

// Problem constants
#define Bsz 2
#define Sq  2048
#define Dm  2048
#define Hh  16
#define Ll  512
#define HDm 128
#define Mrows (Bsz*Sq)      // 4096

// ---------------------------------------------------------------------------
// Scratch (static device globals — no runtime allocation allowed)
// ---------------------------------------------------------------------------
__device__ float g_qlat [(size_t)Mrows * Ll];       //  8 MB
__device__ float g_q    [(size_t)Mrows * Dm];       // 32 MB
__device__ float g_kvlat[(size_t)Mrows * Ll];       //  8 MB
__device__ float g_kv   [(size_t)Mrows * 2 * Dm];   // 64 MB
__device__ float g_attn [(size_t)Mrows * Dm];       // 32 MB

// ---------------------------------------------------------------------------
// Helpers
// ---------------------------------------------------------------------------
__device__ __forceinline__ uint32_t smem_u32(const void* p) {
    uint32_t a;
    asm("{ .reg .u64 t; cvta.to.shared.u64 t, %1; cvt.u32.u64 %0, t; }"
        : "=r"(a) : "l"(p));
    return a;
}
__device__ __forceinline__ void cp16(uint32_t dst, const void* src) {
    asm volatile("cp.async.cg.shared.global [%0], [%1], 16;"
                 :: "r"(dst), "l"(src) : "memory");
}
__device__ __forceinline__ float rna_tf32(float a) {
    float r;
    asm("cvt.rna.tf32.f32 %0, %1;" : "=f"(r) : "f"(a));
    return r;
}
// mma.sync m16n8k8 tf32 (baseline PTX since sm_80 — compiles on sm_103)
__device__ __forceinline__ void mma_tf32(
    float c[4], uint32_t a0, uint32_t a1, uint32_t a2, uint32_t a3,
    uint32_t b0, uint32_t b1)
{
    asm volatile(
        "mma.sync.aligned.m16n8k8.row.col.f32.tf32.tf32.f32 "
        "{%0,%1,%2,%3}, {%4,%5,%6,%7}, {%8,%9}, {%0,%1,%2,%3};"
        : "+f"(c[0]), "+f"(c[1]), "+f"(c[2]), "+f"(c[3])
        : "r"(a0), "r"(a1), "r"(a2), "r"(a3), "r"(b0), "r"(b1));
}

// ---------------------------------------------------------------------------
// 3xTF32 GEMM via mma.sync: C[M,N] = A[M,K] @ W[K,N] + bias[N]  (R5 config)
// ---------------------------------------------------------------------------
#define ASTR 20
#define BSTR 136

__global__ __launch_bounds__(256) void gemm_mma3(
    int M, int N, int K,
    const float* __restrict__ A,
    const float* __restrict__ W,
    const float* __restrict__ bias,
    float* __restrict__ C)
{
    __shared__ __align__(16) float As[2][128 * ASTR];
    __shared__ __align__(16) float Bs[2][16 * BSTR];

    const int tid = threadIdx.x;
    const int wid = tid >> 5, lid = tid & 31;
    const int g = lid >> 2, lq = lid & 3;
    const int m0 = blockIdx.y * 128, n0 = blockIdx.x * 128;
    const int warp_m = (wid & 1) * 64;
    const int warp_n = (wid >> 1) * 32;
    const int nc = K >> 4;

    const uint32_t sA0 = smem_u32(&As[0][0]);
    const uint32_t sB0 = smem_u32(&Bs[0][0]);

    float acc[4][4][4];
    #pragma unroll
    for (int mt = 0; mt < 4; mt++)
        #pragma unroll
        for (int nt = 0; nt < 4; nt++)
            #pragma unroll
            for (int e = 0; e < 4; e++) acc[mt][nt][e] = 0.f;

    auto load_tile = [&](int c, int stg) {
        const int k0 = c << 4;
        const uint32_t sa = sA0 + stg * (128 * ASTR * 4);
        const uint32_t sb = sB0 + stg * (16 * BSTR * 4);
        #pragma unroll
        for (int t = 0; t < 2; t++) {
            int idx = tid + t * 256;
            int m = idx >> 2, k4 = idx & 3;
            cp16(sa + (m * ASTR + k4 * 4) * 4,
                 A + (size_t)(m0 + m) * K + k0 + k4 * 4);
        }
        #pragma unroll
        for (int t = 0; t < 2; t++) {
            int idx = tid + t * 256;
            int k = idx >> 5, nq = idx & 31;
            cp16(sb + (k * BSTR + nq * 4) * 4,
                 W + (size_t)(k0 + k) * N + n0 + nq * 4);
        }
        asm volatile("cp.async.commit_group;" ::: "memory");
    };

    load_tile(0, 0);
    if (nc > 1) load_tile(1, 1);

    for (int c = 0; c < nc; ++c) {
        const int cur = c & 1;
        if (c + 1 < nc) { asm volatile("cp.async.wait_group 1;" ::: "memory"); }
        else            { asm volatile("cp.async.wait_group 0;" ::: "memory"); }
        __syncthreads();

        const float* as = &As[cur][0];
        const float* bs = &Bs[cur][0];

        #pragma unroll
        for (int ks = 0; ks < 2; ks++) {
            const int kb = ks * 8;
            uint32_t Ah[4][4], Al[4][4];
            #pragma unroll
            for (int mt = 0; mt < 4; mt++) {
                const int rbase = warp_m + mt * 16 + g;
                #pragma unroll
                for (int e = 0; e < 4; e++) {
                    const int row = rbase + (e & 1) * 8;
                    const int col = kb + lq + (e >> 1) * 4;
                    float a = as[row * ASTR + col];
                    float h = rna_tf32(a);
                    Ah[mt][e] = __float_as_uint(h);
                    Al[mt][e] = __float_as_uint(rna_tf32(a - h));
                }
            }
            uint32_t Bh[4][2], Bl[4][2];
            #pragma unroll
            for (int nt = 0; nt < 4; nt++) {
                const int nn = warp_n + nt * 8 + g;
                #pragma unroll
                for (int e = 0; e < 2; e++) {
                    const int kk = kb + lq + e * 4;
                    float b = bs[kk * BSTR + nn];
                    float h = rna_tf32(b);
                    Bh[nt][e] = __float_as_uint(h);
                    Bl[nt][e] = __float_as_uint(rna_tf32(b - h));
                }
            }
            #pragma unroll
            for (int mt = 0; mt < 4; mt++)
                #pragma unroll
                for (int nt = 0; nt < 4; nt++) {
                    mma_tf32(acc[mt][nt], Ah[mt][0], Ah[mt][1], Ah[mt][2], Ah[mt][3],
                             Bl[nt][0], Bl[nt][1]);
                    mma_tf32(acc[mt][nt], Al[mt][0], Al[mt][1], Al[mt][2], Al[mt][3],
                             Bh[nt][0], Bh[nt][1]);
                    mma_tf32(acc[mt][nt], Ah[mt][0], Ah[mt][1], Ah[mt][2], Ah[mt][3],
                             Bh[nt][0], Bh[nt][1]);
                }
        }
        __syncthreads();
        if (c + 2 < nc) load_tile(c + 2, cur);
    }

    #pragma unroll
    for (int mt = 0; mt < 4; mt++) {
        const int r0 = m0 + warp_m + mt * 16 + g;
        #pragma unroll
        for (int nt = 0; nt < 4; nt++) {
            const int col = n0 + warp_n + nt * 8 + lq * 2;
            const float2 b2 = *(const float2*)(bias + col);
            float2 o;
            o.x = acc[mt][nt][0] + b2.x;
            o.y = acc[mt][nt][1] + b2.y;
            *(float2*)(C + (size_t)r0 * N + col) = o;
            o.x = acc[mt][nt][2] + b2.x;
            o.y = acc[mt][nt][3] + b2.y;
            *(float2*)(C + (size_t)(r0 + 8) * N + col) = o;
        }
    }
}

// ---------------------------------------------------------------------------
// LayerNorm over last dim (512), in place. One block (256 threads) per row.
// ---------------------------------------------------------------------------
__global__ __launch_bounds__(256) void ln512(
    float* __restrict__ x,
    const float* __restrict__ g,
    const float* __restrict__ b)
{
    const int row = blockIdx.x;
    float* xr = x + (size_t)row * Ll;
    const int tid = threadIdx.x;

    float v0 = xr[tid];
    float v1 = xr[tid + 256];
    float s  = v0 + v1;
    float sq = v0 * v0 + v1 * v1;

    #pragma unroll
    for (int o = 16; o > 0; o >>= 1) {
        s  += __shfl_xor_sync(0xffffffffu, s,  o);
        sq += __shfl_xor_sync(0xffffffffu, sq, o);
    }
    __shared__ float ss[8], ssq[8];
    __shared__ float mean_sh, inv_sh;
    const int w = tid >> 5;
    if ((tid & 31) == 0) { ss[w] = s; ssq[w] = sq; }
    __syncthreads();
    if (tid == 0) {
        float S = 0.f, SQ = 0.f;
        #pragma unroll
        for (int i = 0; i < 8; i++) { S += ss[i]; SQ += ssq[i]; }
        float m = S * (1.f / Ll);
        float var = SQ * (1.f / Ll) - m * m;
        mean_sh = m;
        inv_sh = rsqrtf(var + 1e-5f);
    }
    __syncthreads();
    const float m = mean_sh, inv = inv_sh;
    xr[tid]       = (v0 - m) * inv * g[tid]       + b[tid];
    xr[tid + 256] = (v1 - m) * inv * g[tid + 256] + b[tid + 256];
}

// ---------------------------------------------------------------------------
// Flash attention, mma.sync tf32. CTA: 128 queries (8 warps x m16), key
// tiles of 64, HD=128. QK^T = 3xTF32 with K pre-split once per tile into
// packed smem fragments (LDS.128 feeds). PV = 1xTF32 with V pre-rounded
// and pair-packed (LDS.64 feeds). P stored tf32-rounded.
// ---------------------------------------------------------------------------
#define KRSTR 132            // raw K/V row stride (floats)
#define KPK_LQS 66           // Kpk per-(k8,lq) group stride (float4 units)
#define VPK_LQS 132          // Vpk per-(k8v,lq) group stride (float2 units)
#define PSTR 68
// float offsets
#define KRAW_F 0             // 64 x 132        = 8448
#define VRAW_F 8448          // 64 x 132        = 8448
#define KPK_F  16896         // 64 x 66 float4  = 16896 floats
#define VPK_F  33792         // 32 x 132 float2 = 8448 floats
#define P_F    42240         // 128 x 68        = 8704
#define MASK_B 203776        // bytes; 2 x 64-byte slots
#define ATT_SMEM 203904

__global__ __launch_bounds__(256, 1) void attn_mma(
    const float* __restrict__ q,
    const float* __restrict__ kv,
    const unsigned char* __restrict__ mask,
    float* __restrict__ out)
{
    extern __shared__ float sm[];
    unsigned char* smb = (unsigned char*)sm;

    const int bh = blockIdx.y;
    const int b = bh >> 4, h = bh & 15;
    const int qb = gridDim.x - 1 - blockIdx.x;   // heavy blocks first
    const int q0 = qb * 128;
    const int ktmax = 2 * qb + 1;

    const int tid = threadIdx.x;
    const int wid = tid >> 5, lid = tid & 31;
    const int g = lid >> 2, lq = lid & 3;
    const int warp_m = wid * 16;

    const float* Qp = q  + (size_t)b * Sq * Dm       + (size_t)h * HDm;
    const float* Kp = kv + (size_t)b * Sq * (2 * Dm) + (size_t)h * HDm;
    const float* Vp = Kp + Dm;
    const unsigned char* mp = mask + (size_t)b * Sq;

    const uint32_t smu = smem_u32(sm);
    const float scale = 0.08838834764831845f;    // 1/sqrt(128), folded into Q

    // ---- stage Q (128x128) through the raw K buffer, pull to registers ----
    #pragma unroll
    for (int t = 0; t < 16; t++) {
        int idx = tid + t * 256;
        int row = idx >> 5, c4 = (idx & 31) << 2;
        cp16(smu + (KRAW_F + row * KRSTR + c4) * 4, Qp + (size_t)(q0 + row) * Dm + c4);
    }
    asm volatile("cp.async.commit_group;" ::: "memory");
    asm volatile("cp.async.wait_group 0;" ::: "memory");
    __syncthreads();

    float Qr[16][4];
    #pragma unroll
    for (int c = 0; c < 16; c++)
        #pragma unroll
        for (int e = 0; e < 4; e++)
            Qr[c][e] = sm[(warp_m + g + (e & 1) * 8) * KRSTR + c * 8 + lq + (e >> 1) * 4]
                       * scale;
    __syncthreads();

    auto load_kv = [&](int kt, int slot) {
        const int k0 = kt * 64;
        #pragma unroll
        for (int t = 0; t < 8; t++) {
            int idx = tid + t * 256;
            int row = idx >> 5, c4 = (idx & 31) << 2;
            size_t base = (size_t)(k0 + row) * (2 * Dm) + c4;
            cp16(smu + (KRAW_F + row * KRSTR + c4) * 4, Kp + base);
            cp16(smu + (VRAW_F + row * KRSTR + c4) * 4, Vp + base);
        }
        if (tid < 4)
            cp16(smu + MASK_B + slot * 64 + tid * 16, mp + k0 + tid * 16);
        asm volatile("cp.async.commit_group;" ::: "memory");
    };

    load_kv(0, 0);

    const int row0 = q0 + warp_m + g;
    const int row1 = row0 + 8;
    float m_i0 = -CUDART_INF_F, m_i1 = -CUDART_INF_F;
    float l0 = 0.f, l1 = 0.f;
    float acc[16][4];
    #pragma unroll
    for (int nt = 0; nt < 16; nt++)
        #pragma unroll
        for (int e = 0; e < 4; e++) acc[nt][e] = 0.f;

    float4* kpk = (float4*)(sm + KPK_F);
    float2* vpk = (float2*)(sm + VPK_F);
    float*  psm = sm + P_F;

    for (int kt = 0; kt <= ktmax; ++kt) {
        const int st = kt & 1;
        asm volatile("cp.async.wait_group 0;" ::: "memory");
        __syncthreads();

        // ---- convert K -> packed tf32 hi/lo fragments (once per tile) ----
        #pragma unroll
        for (int t = 0; t < 16; t++) {
            int idx = tid + t * 256;
            int gg = idx & 7, nt = (idx >> 3) & 7, lqq = (idx >> 6) & 3, k8 = idx >> 8;
            int n = nt * 8 + gg, k = k8 * 8 + lqq;
            float a0 = sm[KRAW_F + n * KRSTR + k];
            float a1 = sm[KRAW_F + n * KRSTR + k + 4];
            float h0 = rna_tf32(a0), h1 = rna_tf32(a1);
            kpk[(k8 * 4 + lqq) * KPK_LQS + nt * 8 + gg] =
                make_float4(h0, h1, rna_tf32(a0 - h0), rna_tf32(a1 - h1));
        }
        // ---- convert V -> packed tf32 pairs ----
        #pragma unroll
        for (int t = 0; t < 16; t++) {
            int idx = tid + t * 256;
            int d = idx & 127, lqq = (idx >> 7) & 3, k8v = idx >> 9;
            int k = k8v * 8 + lqq;
            vpk[(k8v * 4 + lqq) * VPK_LQS + d] =
                make_float2(rna_tf32(sm[VRAW_F + k * KRSTR + d]),
                            rna_tf32(sm[VRAW_F + (k + 4) * KRSTR + d]));
        }
        __syncthreads();
        if (kt < ktmax) load_kv(kt + 1, st ^ 1);

        const unsigned char* mk = smb + MASK_B + st * 64;

        // ---- scores: S = Q @ K^T  (3xTF32, packed K) ----
        float sc[8][4];
        #pragma unroll
        for (int nt = 0; nt < 8; nt++)
            #pragma unroll
            for (int e = 0; e < 4; e++) sc[nt][e] = 0.f;

        #pragma unroll 4
        for (int k8 = 0; k8 < 16; k8++) {
            uint32_t qh[4], qlo[4];
            #pragma unroll
            for (int e = 0; e < 4; e++) {
                float a = Qr[k8][e];
                float hh = rna_tf32(a);
                qh[e]  = __float_as_uint(hh);
                qlo[e] = __float_as_uint(rna_tf32(a - hh));
            }
            const float4* kp = kpk + (k8 * 4 + lq) * KPK_LQS;
            #pragma unroll
            for (int nt = 0; nt < 8; nt++) {
                float4 kk = kp[nt * 8 + g];
                uint32_t bh0 = __float_as_uint(kk.x), bh1 = __float_as_uint(kk.y);
                uint32_t bl0 = __float_as_uint(kk.z), bl1 = __float_as_uint(kk.w);
                mma_tf32(sc[nt], qh[0], qh[1], qh[2], qh[3], bl0, bl1);
                mma_tf32(sc[nt], qlo[0], qlo[1], qlo[2], qlo[3], bh0, bh1);
                mma_tf32(sc[nt], qh[0], qh[1], qh[2], qh[3], bh0, bh1);
            }
        }

        // ---- mask + row max (scale already folded into Q) ----
        const bool diag = (kt >= 2 * qb);
        float m0 = -CUDART_INF_F, m1 = -CUDART_INF_F;
        #pragma unroll
        for (int nt = 0; nt < 8; nt++) {
            const int cl = nt * 8 + 2 * lq;
            const int cg = kt * 64 + cl;
            const bool pk0 = mk[cl] != 0, pk1 = mk[cl + 1] != 0;
            float v0 = (pk0 || (diag && cg     > row0)) ? -CUDART_INF_F : sc[nt][0];
            float v1 = (pk1 || (diag && cg + 1 > row0)) ? -CUDART_INF_F : sc[nt][1];
            float v2 = (pk0 || (diag && cg     > row1)) ? -CUDART_INF_F : sc[nt][2];
            float v3 = (pk1 || (diag && cg + 1 > row1)) ? -CUDART_INF_F : sc[nt][3];
            sc[nt][0] = v0; sc[nt][1] = v1; sc[nt][2] = v2; sc[nt][3] = v3;
            m0 = fmaxf(m0, fmaxf(v0, v1));
            m1 = fmaxf(m1, fmaxf(v2, v3));
        }
        m0 = fmaxf(m0, __shfl_xor_sync(0xffffffffu, m0, 1));
        m0 = fmaxf(m0, __shfl_xor_sync(0xffffffffu, m0, 2));
        m1 = fmaxf(m1, __shfl_xor_sync(0xffffffffu, m1, 1));
        m1 = fmaxf(m1, __shfl_xor_sync(0xffffffffu, m1, 2));

        const float mn0 = fmaxf(m_i0, m0), mn1 = fmaxf(m_i1, m1);
        const float corr0 = (mn0 == -CUDART_INF_F) ? 1.f : __expf(m_i0 - mn0);
        const float corr1 = (mn1 == -CUDART_INF_F) ? 1.f : __expf(m_i1 - mn1);
        const float base0 = (mn0 == -CUDART_INF_F) ? 0.f : mn0;
        const float base1 = (mn1 == -CUDART_INF_F) ? 0.f : mn1;

        float psum0 = 0.f, psum1 = 0.f;
        #pragma unroll
        for (int nt = 0; nt < 8; nt++) {
            float p0 = (sc[nt][0] == -CUDART_INF_F) ? 0.f : __expf(sc[nt][0] - base0);
            float p1 = (sc[nt][1] == -CUDART_INF_F) ? 0.f : __expf(sc[nt][1] - base0);
            float p2 = (sc[nt][2] == -CUDART_INF_F) ? 0.f : __expf(sc[nt][2] - base1);
            float p3 = (sc[nt][3] == -CUDART_INF_F) ? 0.f : __expf(sc[nt][3] - base1);
            sc[nt][0] = p0; sc[nt][1] = p1; sc[nt][2] = p2; sc[nt][3] = p3;
            psum0 += p0 + p1;
            psum1 += p2 + p3;
        }
        psum0 += __shfl_xor_sync(0xffffffffu, psum0, 1);
        psum0 += __shfl_xor_sync(0xffffffffu, psum0, 2);
        psum1 += __shfl_xor_sync(0xffffffffu, psum1, 1);
        psum1 += __shfl_xor_sync(0xffffffffu, psum1, 2);
        l0 = l0 * corr0 + psum0;
        l1 = l1 * corr1 + psum1;
        m_i0 = mn0; m_i1 = mn1;

        #pragma unroll
        for (int nt = 0; nt < 16; nt++) {
            acc[nt][0] *= corr0; acc[nt][1] *= corr0;
            acc[nt][2] *= corr1; acc[nt][3] *= corr1;
        }

        // ---- stage P (tf32-rounded, per-warp private rows) ----
        __syncwarp();
        #pragma unroll
        for (int nt = 0; nt < 8; nt++) {
            const int cl = nt * 8 + 2 * lq;
            *(float2*)&psm[(warp_m + g) * PSTR + cl] =
                make_float2(rna_tf32(sc[nt][0]), rna_tf32(sc[nt][1]));
            *(float2*)&psm[(warp_m + g + 8) * PSTR + cl] =
                make_float2(rna_tf32(sc[nt][2]), rna_tf32(sc[nt][3]));
        }
        __syncwarp();

        // ---- O += P @ V  (1xTF32, packed V) ----
        #pragma unroll 2
        for (int k8v = 0; k8v < 8; k8v++) {
            const int kc = k8v * 8;
            uint32_t pa[4];
            #pragma unroll
            for (int e = 0; e < 4; e++)
                pa[e] = __float_as_uint(
                    psm[(warp_m + g + (e & 1) * 8) * PSTR + kc + lq + (e >> 1) * 4]);
            const float2* vp = vpk + (k8v * 4 + lq) * VPK_LQS;
            #pragma unroll
            for (int nt = 0; nt < 16; nt++) {
                float2 vv = vp[nt * 8 + g];
                mma_tf32(acc[nt], pa[0], pa[1], pa[2], pa[3],
                         __float_as_uint(vv.x), __float_as_uint(vv.y));
            }
        }
        __syncthreads();
    }

    // ---- epilogue ----
    const float inv0 = (l0 > 0.f) ? (1.f / l0) : 0.f;
    const float inv1 = (l1 > 0.f) ? (1.f / l1) : 0.f;
    float* o0 = out + (size_t)(b * Sq + row0) * Dm + (size_t)h * HDm;
    float* o1 = out + (size_t)(b * Sq + row1) * Dm + (size_t)h * HDm;
    #pragma unroll
    for (int nt = 0; nt < 16; nt++) {
        const int cl = nt * 8 + 2 * lq;
        *(float2*)(o0 + cl) = make_float2(acc[nt][0] * inv0, acc[nt][1] * inv0);
        *(float2*)(o1 + cl) = make_float2(acc[nt][2] * inv1, acc[nt][3] * inv1);
    }
}

// ---------------------------------------------------------------------------
// Launch
// ---------------------------------------------------------------------------
extern "C" void kernel_launch(void* const* d_in, const int* in_sizes, int n_in,
                              void* d_out, int out_size)
{
    const float*         x        = (const float*)d_in[0];
    const unsigned char* mask     = (const unsigned char*)d_in[1];
    const float*         wq_down  = (const float*)d_in[2];
    const float*         bq_down  = (const float*)d_in[3];
    const float*         gq_ln    = (const float*)d_in[4];
    const float*         bq_ln    = (const float*)d_in[5];
    const float*         wq_up    = (const float*)d_in[6];
    const float*         bq_up    = (const float*)d_in[7];
    const float*         wkv_down = (const float*)d_in[8];
    const float*         bkv_down = (const float*)d_in[9];
    const float*         gkv_ln   = (const float*)d_in[10];
    const float*         bkv_ln   = (const float*)d_in[11];
    const float*         wkv_up   = (const float*)d_in[12];
    const float*         bkv_up   = (const float*)d_in[13];
    const float*         w_out    = (const float*)d_in[14];
    const float*         b_out    = (const float*)d_in[15];
    float* out = (float*)d_out;

    float *qlat, *qb, *kvlat, *kvb, *attnb;
    cudaGetSymbolAddress((void**)&qlat,  g_qlat);
    cudaGetSymbolAddress((void**)&qb,    g_q);
    cudaGetSymbolAddress((void**)&kvlat, g_kvlat);
    cudaGetSymbolAddress((void**)&kvb,   g_kv);
    cudaGetSymbolAddress((void**)&attnb, g_attn);

    cudaFuncSetAttribute(attn_mma,
                         cudaFuncAttributeMaxDynamicSharedMemorySize, ATT_SMEM);

    // Q path: down-proj -> LN -> up-proj
    gemm_mma3<<<dim3(Ll / 128, Mrows / 128), 256>>>(Mrows, Ll, Dm, x, wq_down, bq_down, qlat);
    ln512<<<Mrows, 256>>>(qlat, gq_ln, bq_ln);
    gemm_mma3<<<dim3(Dm / 128, Mrows / 128), 256>>>(Mrows, Dm, Ll, qlat, wq_up, bq_up, qb);

    // KV path: down-proj -> LN -> up-proj (k | v concatenated)
    gemm_mma3<<<dim3(Ll / 128, Mrows / 128), 256>>>(Mrows, Ll, Dm, x, wkv_down, bkv_down, kvlat);
    ln512<<<Mrows, 256>>>(kvlat, gkv_ln, bkv_ln);
    gemm_mma3<<<dim3(2 * Dm / 128, Mrows / 128), 256>>>(Mrows, 2 * Dm, Ll, kvlat, wkv_up, bkv_up, kvb);

    // Causal multi-head attention (flash, tensor cores, packed operands)
    attn_mma<<<dim3(Sq / 128, Bsz * Hh), 256, ATT_SMEM>>>(qb, kvb, mask, attnb);

    // Output projection
    gemm_mma3<<<dim3(Dm / 128, Mrows / 128), 256>>>(Mrows, Dm, Dm, attnb, w_out, b_out, out);
}

// round 8
// speedup vs baseline: 1.9095x; 1.6117x over previous
#include <cuda_runtime.h>
#include <cuda_fp16.h>
#include <math_constants.h>
#include <cstdint>

// Problem constants
#define Bsz 2
#define Sq  2048
#define Dm  2048
#define Hh  16
#define Ll  512
#define HDm 128
#define Mrows (Bsz*Sq)      // 4096

// ---------------------------------------------------------------------------
// Scratch (static device globals — no runtime allocation allowed)
// ---------------------------------------------------------------------------
__device__ float g_qlat [(size_t)Mrows * Ll];
__device__ float g_q    [(size_t)Mrows * Dm];
__device__ float g_kvlat[(size_t)Mrows * Ll];
__device__ float g_kv   [(size_t)Mrows * 2 * Dm];
__device__ float g_attn [(size_t)Mrows * Dm];

// ---------------------------------------------------------------------------
// Helpers
// ---------------------------------------------------------------------------
__device__ __forceinline__ uint32_t smem_u32(const void* p) {
    uint32_t a;
    asm("{ .reg .u64 t; cvta.to.shared.u64 t, %1; cvt.u32.u64 %0, t; }"
        : "=r"(a) : "l"(p));
    return a;
}
__device__ __forceinline__ void cp16(uint32_t dst, const void* src) {
    asm volatile("cp.async.cg.shared.global [%0], [%1], 16;"
                 :: "r"(dst), "l"(src) : "memory");
}
__device__ __forceinline__ float h2pack(float a, float b) {
    __half2 h = __halves2half2(__float2half_rn(a), __float2half_rn(b));
    return __uint_as_float(*(uint32_t*)&h);
}
// hi/lo split of 4 values (2 k-pairs) -> {hi01, hi23, lo01, lo23}
__device__ __forceinline__ float4 pack_hl4(float a0, float a1, float a2, float a3) {
    __half h0 = __float2half_rn(a0), h1 = __float2half_rn(a1);
    __half h2 = __float2half_rn(a2), h3 = __float2half_rn(a3);
    float l0 = a0 - __half2float(h0), l1 = a1 - __half2float(h1);
    float l2 = a2 - __half2float(h2), l3 = a3 - __half2float(h3);
    float4 r;
    __half2 p;
    p = __halves2half2(h0, h1); r.x = __uint_as_float(*(uint32_t*)&p);
    p = __halves2half2(h2, h3); r.y = __uint_as_float(*(uint32_t*)&p);
    r.z = h2pack(l0, l1);
    r.w = h2pack(l2, l3);
    return r;
}
// mma.sync m16n8k16 f16 with f32 accumulate (baseline PTX since sm_80)
__device__ __forceinline__ void mma_f16(
    float c[4], uint32_t a0, uint32_t a1, uint32_t a2, uint32_t a3,
    uint32_t b0, uint32_t b1)
{
    asm volatile(
        "mma.sync.aligned.m16n8k16.row.col.f32.f16.f16.f32 "
        "{%0,%1,%2,%3}, {%4,%5,%6,%7}, {%8,%9}, {%0,%1,%2,%3};"
        : "+f"(c[0]), "+f"(c[1]), "+f"(c[2]), "+f"(c[3])
        : "r"(a0), "r"(a1), "r"(a2), "r"(a3), "r"(b0), "r"(b1));
}
#define FU(x) __float_as_uint(x)

// ---------------------------------------------------------------------------
// fp16 3-term GEMM: C[M,N] = A[M,K] @ W[K,N] + bias[N]
// CTA tile 128x128, BK=16, 256 threads. Raw fp32 tiles converted once in
// smem to packed hi/lo half2 fragments. W scaled x256 (lo stays fp16-normal),
// undone in epilogue.
// ---------------------------------------------------------------------------
#define ASTR 20
#define BSTR 136

__global__ __launch_bounds__(256) void gemm_h3(
    int M, int N, int K,
    const float* __restrict__ A,
    const float* __restrict__ W,
    const float* __restrict__ bias,
    float* __restrict__ C)
{
    __shared__ __align__(16) float  Araw[2][128 * ASTR];
    __shared__ __align__(16) float  Braw[2][16 * BSTR];
    __shared__ __align__(16) float4 AP[128 * 4];     // [m][j] j=0..3
    __shared__ __align__(16) float4 BP[4 * 130];     // [j][n] stride 130

    const int tid = threadIdx.x;
    const int wid = tid >> 5, lid = tid & 31;
    const int g = lid >> 2, lq = lid & 3;
    const int m0 = blockIdx.y * 128, n0 = blockIdx.x * 128;
    const int warp_m = (wid & 1) * 64;
    const int warp_n = (wid >> 1) * 32;
    const int nc = K >> 4;

    const uint32_t sA0 = smem_u32(&Araw[0][0]);
    const uint32_t sB0 = smem_u32(&Braw[0][0]);

    float acc[4][4][4];
    #pragma unroll
    for (int mt = 0; mt < 4; mt++)
        #pragma unroll
        for (int nt = 0; nt < 4; nt++)
            #pragma unroll
            for (int e = 0; e < 4; e++) acc[mt][nt][e] = 0.f;

    auto load_tile = [&](int c, int stg) {
        const int k0 = c << 4;
        const uint32_t sa = sA0 + stg * (128 * ASTR * 4);
        const uint32_t sb = sB0 + stg * (16 * BSTR * 4);
        #pragma unroll
        for (int t = 0; t < 2; t++) {
            int idx = tid + t * 256;
            int m = idx >> 2, k4 = (idx & 3) * 4;
            cp16(sa + (m * ASTR + k4) * 4,
                 A + (size_t)(m0 + m) * K + k0 + k4);
        }
        #pragma unroll
        for (int t = 0; t < 2; t++) {
            int idx = tid + t * 256;
            int k = idx >> 5, nq = (idx & 31) * 4;
            cp16(sb + (k * BSTR + nq) * 4,
                 W + (size_t)(k0 + k) * N + n0 + nq);
        }
        asm volatile("cp.async.commit_group;" ::: "memory");
    };

    load_tile(0, 0);
    if (nc > 1) load_tile(1, 1);

    for (int c = 0; c < nc; ++c) {
        const int cur = c & 1;
        if (c + 1 < nc) { asm volatile("cp.async.wait_group 1;" ::: "memory"); }
        else            { asm volatile("cp.async.wait_group 0;" ::: "memory"); }
        __syncthreads();

        // ---- convert raw fp32 -> packed hi/lo half2 (once per tile) ----
        #pragma unroll
        for (int t = 0; t < 2; t++) {
            int idx = tid + t * 256;
            int m = idx >> 2, j = idx & 3;
            const float* ar = &Araw[cur][m * ASTR];
            AP[m * 4 + j] = pack_hl4(ar[2*j], ar[2*j+1], ar[2*j+8], ar[2*j+9]);
        }
        #pragma unroll
        for (int t = 0; t < 2; t++) {
            int idx = tid + t * 256;
            int n = idx & 127, j = idx >> 7;
            const float* br = &Braw[cur][n];
            BP[j * 130 + n] = pack_hl4(
                br[(2*j)*BSTR]   * 256.f, br[(2*j+1)*BSTR] * 256.f,
                br[(2*j+8)*BSTR] * 256.f, br[(2*j+9)*BSTR] * 256.f);
        }
        __syncthreads();
        if (c + 2 < nc) load_tile(c + 2, cur);

        // ---- fragments + mmas ----
        uint32_t Ah[4][4], Al[4][4];
        #pragma unroll
        for (int mt = 0; mt < 4; mt++) {
            float4 fa = AP[(warp_m + mt * 16 + g) * 4 + lq];
            float4 fb = AP[(warp_m + mt * 16 + g + 8) * 4 + lq];
            Ah[mt][0] = FU(fa.x); Ah[mt][1] = FU(fb.x);
            Ah[mt][2] = FU(fa.y); Ah[mt][3] = FU(fb.y);
            Al[mt][0] = FU(fa.z); Al[mt][1] = FU(fb.z);
            Al[mt][2] = FU(fa.w); Al[mt][3] = FU(fb.w);
        }
        uint32_t Bh[4][2], Bl[4][2];
        #pragma unroll
        for (int nt = 0; nt < 4; nt++) {
            float4 f = BP[lq * 130 + warp_n + nt * 8 + g];
            Bh[nt][0] = FU(f.x); Bh[nt][1] = FU(f.y);
            Bl[nt][0] = FU(f.z); Bl[nt][1] = FU(f.w);
        }
        #pragma unroll
        for (int mt = 0; mt < 4; mt++)
            #pragma unroll
            for (int nt = 0; nt < 4; nt++) {
                mma_f16(acc[mt][nt], Ah[mt][0], Ah[mt][1], Ah[mt][2], Ah[mt][3],
                        Bl[nt][0], Bl[nt][1]);
                mma_f16(acc[mt][nt], Al[mt][0], Al[mt][1], Al[mt][2], Al[mt][3],
                        Bh[nt][0], Bh[nt][1]);
                mma_f16(acc[mt][nt], Ah[mt][0], Ah[mt][1], Ah[mt][2], Ah[mt][3],
                        Bh[nt][0], Bh[nt][1]);
            }
        __syncthreads();
    }

    const float s = 1.f / 256.f;
    #pragma unroll
    for (int mt = 0; mt < 4; mt++) {
        const int r0 = m0 + warp_m + mt * 16 + g;
        #pragma unroll
        for (int nt = 0; nt < 4; nt++) {
            const int col = n0 + warp_n + nt * 8 + lq * 2;
            const float2 b2 = *(const float2*)(bias + col);
            float2 o;
            o.x = acc[mt][nt][0] * s + b2.x;
            o.y = acc[mt][nt][1] * s + b2.y;
            *(float2*)(C + (size_t)r0 * N + col) = o;
            o.x = acc[mt][nt][2] * s + b2.x;
            o.y = acc[mt][nt][3] * s + b2.y;
            *(float2*)(C + (size_t)(r0 + 8) * N + col) = o;
        }
    }
}

// ---------------------------------------------------------------------------
// LayerNorm over last dim (512), in place. One block (256 threads) per row.
// ---------------------------------------------------------------------------
__global__ __launch_bounds__(256) void ln512(
    float* __restrict__ x,
    const float* __restrict__ g,
    const float* __restrict__ b)
{
    const int row = blockIdx.x;
    float* xr = x + (size_t)row * Ll;
    const int tid = threadIdx.x;

    float v0 = xr[tid];
    float v1 = xr[tid + 256];
    float s  = v0 + v1;
    float sq = v0 * v0 + v1 * v1;

    #pragma unroll
    for (int o = 16; o > 0; o >>= 1) {
        s  += __shfl_xor_sync(0xffffffffu, s,  o);
        sq += __shfl_xor_sync(0xffffffffu, sq, o);
    }
    __shared__ float ss[8], ssq[8];
    __shared__ float mean_sh, inv_sh;
    const int w = tid >> 5;
    if ((tid & 31) == 0) { ss[w] = s; ssq[w] = sq; }
    __syncthreads();
    if (tid == 0) {
        float S = 0.f, SQ = 0.f;
        #pragma unroll
        for (int i = 0; i < 8; i++) { S += ss[i]; SQ += ssq[i]; }
        float m = S * (1.f / Ll);
        float var = SQ * (1.f / Ll) - m * m;
        mean_sh = m;
        inv_sh = rsqrtf(var + 1e-5f);
    }
    __syncthreads();
    const float m = mean_sh, inv = inv_sh;
    xr[tid]       = (v0 - m) * inv * g[tid]       + b[tid];
    xr[tid + 256] = (v1 - m) * inv * g[tid + 256] + b[tid + 256];
}

// ---------------------------------------------------------------------------
// Flash attention, fp16 mma. CTA: 128 queries (8 warps x m16), key tiles of
// 64, HD=128. QK^T = 3-term fp16 split (Q in regs, K packed in smem);
// PV = 1x fp16 (P and V packed as half2 pairs).
// ---------------------------------------------------------------------------
#define KRSTR 132
// float offsets
#define KRAW_F 0             // 64 x 132 = 8448
#define VRAW_F 8448          // 8448
#define KF4_F  16896         // 32 groups x 66 float4 = 8448 floats
#define VF2_F  25344         // 16 groups x 132 float2 = 4224 floats
#define PF2_F  29568         // 128 x 20 float2 = 5120 floats
#define MASK_B 138752        // = 34688 * 4 bytes
#define ATT_SMEM 138880

__global__ __launch_bounds__(256, 1) void attn_mma(
    const float* __restrict__ q,
    const float* __restrict__ kv,
    const unsigned char* __restrict__ mask,
    float* __restrict__ out)
{
    extern __shared__ float sm[];
    unsigned char* smb = (unsigned char*)sm;

    const int bh = blockIdx.y;
    const int b = bh >> 4, h = bh & 15;
    const int qb = gridDim.x - 1 - blockIdx.x;   // heavy blocks first
    const int q0 = qb * 128;
    const int ktmax = 2 * qb + 1;

    const int tid = threadIdx.x;
    const int wid = tid >> 5, lid = tid & 31;
    const int g = lid >> 2, lq = lid & 3;
    const int warp_m = wid * 16;

    const float* Qp = q  + (size_t)b * Sq * Dm       + (size_t)h * HDm;
    const float* Kp = kv + (size_t)b * Sq * (2 * Dm) + (size_t)h * HDm;
    const float* Vp = Kp + Dm;
    const unsigned char* mp = mask + (size_t)b * Sq;

    const uint32_t smu = smem_u32(sm);
    const float scale = 0.08838834764831845f;    // 1/sqrt(128)

    // ---- stage Q (128x128) through raw K buffer, split to fp16 regs ----
    #pragma unroll
    for (int t = 0; t < 16; t++) {
        int idx = tid + t * 256;
        int row = idx >> 5, c4 = (idx & 31) << 2;
        cp16(smu + (KRAW_F + row * KRSTR + c4) * 4, Qp + (size_t)(q0 + row) * Dm + c4);
    }
    asm volatile("cp.async.commit_group;" ::: "memory");
    asm volatile("cp.async.wait_group 0;" ::: "memory");
    __syncthreads();

    uint32_t Qh[8][4], Ql[8][4];
    #pragma unroll
    for (int c = 0; c < 8; c++)
        #pragma unroll
        for (int e = 0; e < 4; e++) {
            int row = warp_m + g + (e & 1) * 8;
            int col = c * 16 + 2 * lq + (e >> 1) * 8;
            float a0 = sm[KRAW_F + row * KRSTR + col];
            float a1 = sm[KRAW_F + row * KRSTR + col + 1];
            __half h0 = __float2half_rn(a0), h1 = __float2half_rn(a1);
            __half2 hp = __halves2half2(h0, h1);
            Qh[c][e] = *(uint32_t*)&hp;
            Ql[c][e] = FU(h2pack(a0 - __half2float(h0), a1 - __half2float(h1)));
        }
    __syncthreads();

    auto load_kv = [&](int kt, int slot) {
        const int k0 = kt * 64;
        #pragma unroll
        for (int t = 0; t < 8; t++) {
            int idx = tid + t * 256;
            int row = idx >> 5, c4 = (idx & 31) << 2;
            size_t base = (size_t)(k0 + row) * (2 * Dm) + c4;
            cp16(smu + (KRAW_F + row * KRSTR + c4) * 4, Kp + base);
            cp16(smu + (VRAW_F + row * KRSTR + c4) * 4, Vp + base);
        }
        if (tid < 4)
            cp16(smu + MASK_B + slot * 64 + tid * 16, mp + k0 + tid * 16);
        asm volatile("cp.async.commit_group;" ::: "memory");
    };

    load_kv(0, 0);

    const int row0 = q0 + warp_m + g;
    const int row1 = row0 + 8;
    float m_i0 = -CUDART_INF_F, m_i1 = -CUDART_INF_F;
    float l0 = 0.f, l1 = 0.f;
    float acc[16][4];
    #pragma unroll
    for (int nt = 0; nt < 16; nt++)
        #pragma unroll
        for (int e = 0; e < 4; e++) acc[nt][e] = 0.f;

    float4* kf4 = (float4*)(sm + KF4_F);
    float2* vf2 = (float2*)(sm + VF2_F);
    float2* pf2 = (float2*)(sm + PF2_F);

    for (int kt = 0; kt <= ktmax; ++kt) {
        const int st = kt & 1;
        asm volatile("cp.async.wait_group 0;" ::: "memory");
        __syncthreads();

        // ---- K -> packed fp16 hi/lo fragments (once per tile) ----
        #pragma unroll
        for (int t = 0; t < 8; t++) {
            int idx = tid + t * 256;
            int n = idx & 63, lqq = (idx >> 6) & 3, c = idx >> 8;
            const float* kr = sm + KRAW_F + n * KRSTR + c * 16 + 2 * lqq;
            kf4[(c * 4 + lqq) * 66 + n] = pack_hl4(kr[0], kr[1], kr[8], kr[9]);
        }
        // ---- V -> packed fp16 pairs ----
        #pragma unroll
        for (int t = 0; t < 8; t++) {
            int idx = tid + t * 256;
            int d = idx & 127, lqq = (idx >> 7) & 3, c = idx >> 9;
            const float* vr = sm + VRAW_F + (c * 16 + 2 * lqq) * KRSTR + d;
            vf2[(c * 4 + lqq) * 132 + d] =
                make_float2(h2pack(vr[0], vr[KRSTR]),
                            h2pack(vr[8 * KRSTR], vr[9 * KRSTR]));
        }
        __syncthreads();
        if (kt < ktmax) load_kv(kt + 1, st ^ 1);

        const unsigned char* mk = smb + MASK_B + st * 64;

        // ---- scores: S = Q @ K^T  (3-term fp16) ----
        float sc[8][4];
        #pragma unroll
        for (int nt = 0; nt < 8; nt++)
            #pragma unroll
            for (int e = 0; e < 4; e++) sc[nt][e] = 0.f;

        #pragma unroll 4
        for (int c = 0; c < 8; c++) {
            const float4* kp_ = kf4 + (c * 4 + lq) * 66;
            #pragma unroll
            for (int nt = 0; nt < 8; nt++) {
                float4 kk = kp_[nt * 8 + g];
                mma_f16(sc[nt], Qh[c][0], Qh[c][1], Qh[c][2], Qh[c][3],
                        FU(kk.z), FU(kk.w));
                mma_f16(sc[nt], Ql[c][0], Ql[c][1], Ql[c][2], Ql[c][3],
                        FU(kk.x), FU(kk.y));
                mma_f16(sc[nt], Qh[c][0], Qh[c][1], Qh[c][2], Qh[c][3],
                        FU(kk.x), FU(kk.y));
            }
        }

        // ---- mask + scale + row max ----
        const bool diag = (kt >= 2 * qb);
        float m0 = -CUDART_INF_F, m1 = -CUDART_INF_F;
        #pragma unroll
        for (int nt = 0; nt < 8; nt++) {
            const int cl = nt * 8 + 2 * lq;
            const int cg = kt * 64 + cl;
            const bool pk0 = mk[cl] != 0, pk1 = mk[cl + 1] != 0;
            float v0 = (pk0 || (diag && cg     > row0)) ? -CUDART_INF_F : sc[nt][0] * scale;
            float v1 = (pk1 || (diag && cg + 1 > row0)) ? -CUDART_INF_F : sc[nt][1] * scale;
            float v2 = (pk0 || (diag && cg     > row1)) ? -CUDART_INF_F : sc[nt][2] * scale;
            float v3 = (pk1 || (diag && cg + 1 > row1)) ? -CUDART_INF_F : sc[nt][3] * scale;
            sc[nt][0] = v0; sc[nt][1] = v1; sc[nt][2] = v2; sc[nt][3] = v3;
            m0 = fmaxf(m0, fmaxf(v0, v1));
            m1 = fmaxf(m1, fmaxf(v2, v3));
        }
        m0 = fmaxf(m0, __shfl_xor_sync(0xffffffffu, m0, 1));
        m0 = fmaxf(m0, __shfl_xor_sync(0xffffffffu, m0, 2));
        m1 = fmaxf(m1, __shfl_xor_sync(0xffffffffu, m1, 1));
        m1 = fmaxf(m1, __shfl_xor_sync(0xffffffffu, m1, 2));

        const float mn0 = fmaxf(m_i0, m0), mn1 = fmaxf(m_i1, m1);
        const float corr0 = (mn0 == -CUDART_INF_F) ? 1.f : __expf(m_i0 - mn0);
        const float corr1 = (mn1 == -CUDART_INF_F) ? 1.f : __expf(m_i1 - mn1);
        const float base0 = (mn0 == -CUDART_INF_F) ? 0.f : mn0;
        const float base1 = (mn1 == -CUDART_INF_F) ? 0.f : mn1;

        float psum0 = 0.f, psum1 = 0.f;
        uint32_t ptop_prev = 0, pbot_prev = 0;
        __syncwarp();
        #pragma unroll
        for (int nt = 0; nt < 8; nt++) {
            float p0 = (sc[nt][0] == -CUDART_INF_F) ? 0.f : __expf(sc[nt][0] - base0);
            float p1 = (sc[nt][1] == -CUDART_INF_F) ? 0.f : __expf(sc[nt][1] - base0);
            float p2 = (sc[nt][2] == -CUDART_INF_F) ? 0.f : __expf(sc[nt][2] - base1);
            float p3 = (sc[nt][3] == -CUDART_INF_F) ? 0.f : __expf(sc[nt][3] - base1);
            psum0 += p0 + p1;
            psum1 += p2 + p3;
            uint32_t top = FU(h2pack(p0, p1));
            uint32_t bot = FU(h2pack(p2, p3));
            if (nt & 1) {
                const int c = nt >> 1;
                pf2[(warp_m + g) * 20 + c * 4 + lq] =
                    make_float2(__uint_as_float(ptop_prev), __uint_as_float(top));
                pf2[(warp_m + g + 8) * 20 + c * 4 + lq] =
                    make_float2(__uint_as_float(pbot_prev), __uint_as_float(bot));
            } else { ptop_prev = top; pbot_prev = bot; }
        }
        psum0 += __shfl_xor_sync(0xffffffffu, psum0, 1);
        psum0 += __shfl_xor_sync(0xffffffffu, psum0, 2);
        psum1 += __shfl_xor_sync(0xffffffffu, psum1, 1);
        psum1 += __shfl_xor_sync(0xffffffffu, psum1, 2);
        l0 = l0 * corr0 + psum0;
        l1 = l1 * corr1 + psum1;
        m_i0 = mn0; m_i1 = mn1;

        #pragma unroll
        for (int nt = 0; nt < 16; nt++) {
            acc[nt][0] *= corr0; acc[nt][1] *= corr0;
            acc[nt][2] *= corr1; acc[nt][3] *= corr1;
        }
        __syncwarp();

        // ---- O += P @ V  (1x fp16, packed) ----
        #pragma unroll
        for (int c = 0; c < 4; c++) {
            float2 pa = pf2[(warp_m + g) * 20 + c * 4 + lq];
            float2 pb = pf2[(warp_m + g + 8) * 20 + c * 4 + lq];
            uint32_t A0 = FU(pa.x), A1 = FU(pb.x), A2 = FU(pa.y), A3 = FU(pb.y);
            const float2* vp = vf2 + (c * 4 + lq) * 132;
            #pragma unroll
            for (int nt = 0; nt < 16; nt++) {
                float2 vv = vp[nt * 8 + g];
                mma_f16(acc[nt], A0, A1, A2, A3, FU(vv.x), FU(vv.y));
            }
        }
        __syncthreads();
    }

    // ---- epilogue ----
    const float inv0 = (l0 > 0.f) ? (1.f / l0) : 0.f;
    const float inv1 = (l1 > 0.f) ? (1.f / l1) : 0.f;
    float* o0 = out + (size_t)(b * Sq + row0) * Dm + (size_t)h * HDm;
    float* o1 = out + (size_t)(b * Sq + row1) * Dm + (size_t)h * HDm;
    #pragma unroll
    for (int nt = 0; nt < 16; nt++) {
        const int cl = nt * 8 + 2 * lq;
        *(float2*)(o0 + cl) = make_float2(acc[nt][0] * inv0, acc[nt][1] * inv0);
        *(float2*)(o1 + cl) = make_float2(acc[nt][2] * inv1, acc[nt][3] * inv1);
    }
}

// ---------------------------------------------------------------------------
// Launch
// ---------------------------------------------------------------------------
extern "C" void kernel_launch(void* const* d_in, const int* in_sizes, int n_in,
                              void* d_out, int out_size)
{
    const float*         x        = (const float*)d_in[0];
    const unsigned char* mask     = (const unsigned char*)d_in[1];
    const float*         wq_down  = (const float*)d_in[2];
    const float*         bq_down  = (const float*)d_in[3];
    const float*         gq_ln    = (const float*)d_in[4];
    const float*         bq_ln    = (const float*)d_in[5];
    const float*         wq_up    = (const float*)d_in[6];
    const float*         bq_up    = (const float*)d_in[7];
    const float*         wkv_down = (const float*)d_in[8];
    const float*         bkv_down = (const float*)d_in[9];
    const float*         gkv_ln   = (const float*)d_in[10];
    const float*         bkv_ln   = (const float*)d_in[11];
    const float*         wkv_up   = (const float*)d_in[12];
    const float*         bkv_up   = (const float*)d_in[13];
    const float*         w_out    = (const float*)d_in[14];
    const float*         b_out    = (const float*)d_in[15];
    float* out = (float*)d_out;

    float *qlat, *qb, *kvlat, *kvb, *attnb;
    cudaGetSymbolAddress((void**)&qlat,  g_qlat);
    cudaGetSymbolAddress((void**)&qb,    g_q);
    cudaGetSymbolAddress((void**)&kvlat, g_kvlat);
    cudaGetSymbolAddress((void**)&kvb,   g_kv);
    cudaGetSymbolAddress((void**)&attnb, g_attn);

    cudaFuncSetAttribute(attn_mma,
                         cudaFuncAttributeMaxDynamicSharedMemorySize, ATT_SMEM);

    // Q path: down-proj -> LN -> up-proj
    gemm_h3<<<dim3(Ll / 128, Mrows / 128), 256>>>(Mrows, Ll, Dm, x, wq_down, bq_down, qlat);
    ln512<<<Mrows, 256>>>(qlat, gq_ln, bq_ln);
    gemm_h3<<<dim3(Dm / 128, Mrows / 128), 256>>>(Mrows, Dm, Ll, qlat, wq_up, bq_up, qb);

    // KV path: down-proj -> LN -> up-proj (k | v concatenated)
    gemm_h3<<<dim3(Ll / 128, Mrows / 128), 256>>>(Mrows, Ll, Dm, x, wkv_down, bkv_down, kvlat);
    ln512<<<Mrows, 256>>>(kvlat, gkv_ln, bkv_ln);
    gemm_h3<<<dim3(2 * Dm / 128, Mrows / 128), 256>>>(Mrows, 2 * Dm, Ll, kvlat, wkv_up, bkv_up, kvb);

    // Causal multi-head attention (flash, fp16 tensor cores)
    attn_mma<<<dim3(Sq / 128, Bsz * Hh), 256, ATT_SMEM>>>(qb, kvb, mask, attnb);

    // Output projection
    gemm_h3<<<dim3(Dm / 128, Mrows / 128), 256>>>(Mrows, Dm, Dm, attnb, w_out, b_out, out);
}

// round 9
// speedup vs baseline: 2.2914x; 1.2000x over previous
#include <cuda_runtime.h>
#include <cuda_fp16.h>
#include <math_constants.h>
#include <cstdint>

// Problem constants
#define Bsz 2
#define Sq  2048
#define Dm  2048
#define Hh  16
#define Ll  512
#define HDm 128
#define Mrows (Bsz*Sq)      // 4096

// ---------------------------------------------------------------------------
// Scratch (static device globals — no runtime allocation allowed)
// ---------------------------------------------------------------------------
__device__ float  g_qlat [(size_t)Mrows * Ll];
__device__ float  g_q    [(size_t)Mrows * Dm];
__device__ float  g_kvlat[(size_t)Mrows * Ll];
__device__ float  g_kv   [(size_t)Mrows * 2 * Dm];
__device__ float  g_attn [(size_t)Mrows * Dm];
__device__ float4 g_wpk  [(size_t)Dm * Dm / 4];      // packed weights (reused)
__device__ float4 g_apk  [(size_t)Mrows * Dm / 4];   // packed acts (x, attnb)
__device__ float4 g_lpk  [(size_t)Mrows * Ll / 4];   // packed latents (reused)
__device__ float4 g_kpk  [(size_t)Mrows * Dm / 4];   // packed K fragments
__device__ float2 g_vpk  [(size_t)Mrows * Dm / 4];   // packed V half2 pairs

// ---------------------------------------------------------------------------
// Helpers
// ---------------------------------------------------------------------------
__device__ __forceinline__ uint32_t smem_u32(const void* p) {
    uint32_t a;
    asm("{ .reg .u64 t; cvta.to.shared.u64 t, %1; cvt.u32.u64 %0, t; }"
        : "=r"(a) : "l"(p));
    return a;
}
__device__ __forceinline__ void cp16(uint32_t dst, const void* src) {
    asm volatile("cp.async.cg.shared.global [%0], [%1], 16;"
                 :: "r"(dst), "l"(src) : "memory");
}
__device__ __forceinline__ float h2pack(float a, float b) {
    __half2 h = __halves2half2(__float2half_rn(a), __float2half_rn(b));
    return __uint_as_float(*(uint32_t*)&h);
}
__device__ __forceinline__ float4 pack_hl4(float a0, float a1, float a2, float a3) {
    __half h0 = __float2half_rn(a0), h1 = __float2half_rn(a1);
    __half h2 = __float2half_rn(a2), h3 = __float2half_rn(a3);
    float4 r;
    __half2 p;
    p = __halves2half2(h0, h1); r.x = __uint_as_float(*(uint32_t*)&p);
    p = __halves2half2(h2, h3); r.y = __uint_as_float(*(uint32_t*)&p);
    r.z = h2pack(a0 - __half2float(h0), a1 - __half2float(h1));
    r.w = h2pack(a2 - __half2float(h2), a3 - __half2float(h3));
    return r;
}
__device__ __forceinline__ void mma_f16(
    float c[4], uint32_t a0, uint32_t a1, uint32_t a2, uint32_t a3,
    uint32_t b0, uint32_t b1)
{
    asm volatile(
        "mma.sync.aligned.m16n8k16.row.col.f32.f16.f16.f32 "
        "{%0,%1,%2,%3}, {%4,%5,%6,%7}, {%8,%9}, {%0,%1,%2,%3};"
        : "+f"(c[0]), "+f"(c[1]), "+f"(c[2]), "+f"(c[3])
        : "r"(a0), "r"(a1), "r"(a2), "r"(a3), "r"(b0), "r"(b1));
}
#define FU(x) __float_as_uint(x)

// ---------------------------------------------------------------------------
// Pack kernels — one-time fp32 -> packed fp16 hi/lo fragment layouts
// ---------------------------------------------------------------------------
// Activations: Apk[(m*(K/16)+jc)*4+lq] = pack of A[m, 16jc + {2lq,2lq+1,2lq+8,2lq+9}]
__global__ __launch_bounds__(256) void pack_act(
    const float* __restrict__ A, float4* __restrict__ out, int K, int total)
{
    int idx = blockIdx.x * 256 + threadIdx.x;
    if (idx >= total) return;
    int lq = idx & 3, rest = idx >> 2;
    int jc = rest % (K >> 4), m = rest / (K >> 4);
    const float* base = A + (size_t)m * K + 16 * jc + 2 * lq;
    float2 a = *(const float2*)base;
    float2 b = *(const float2*)(base + 8);
    out[idx] = pack_hl4(a.x, a.y, b.x, b.y);
}
// Weights (x256): Bpk[(jc*4+lq)*N+n] = pack of W[16jc + {2lq,2lq+1,2lq+8,2lq+9}, n]*256
__global__ __launch_bounds__(256) void pack_w(
    const float* __restrict__ W, float4* __restrict__ out, int N, int total)
{
    int idx = blockIdx.x * 256 + threadIdx.x;
    if (idx >= total) return;
    int n = idx % N, g2 = idx / N;
    int lq = g2 & 3, jc = g2 >> 2;
    size_t k = 16 * jc + 2 * lq;
    out[idx] = pack_hl4(W[k * N + n] * 256.f, W[(k + 1) * N + n] * 256.f,
                        W[(k + 8) * N + n] * 256.f, W[(k + 9) * N + n] * 256.f);
}
// KV pack: one block per (kt, bh) tile.
__global__ __launch_bounds__(256) void pack_kv(
    const float* __restrict__ kv, float4* __restrict__ kpk, float2* __restrict__ vpk)
{
    __shared__ float Kr[64 * 132];
    const int kt = blockIdx.x, bh = blockIdx.y;
    const int b = bh >> 4, h = bh & 15;
    const float* Kp = kv + (size_t)b * Sq * 2 * Dm + (size_t)h * HDm
                         + (size_t)kt * 64 * 2 * Dm;
    const float* Vp = Kp + Dm;
    const uint32_t smu = smem_u32(Kr);
    const int tid = threadIdx.x;

    #pragma unroll
    for (int t = 0; t < 8; t++) {
        int idx = tid + t * 256;
        int row = idx >> 5, c4 = (idx & 31) * 4;
        cp16(smu + (row * 132 + c4) * 4, Kp + (size_t)row * 2 * Dm + c4);
    }
    asm volatile("cp.async.commit_group;" ::: "memory");
    asm volatile("cp.async.wait_group 0;" ::: "memory");
    __syncthreads();

    const size_t obase = (size_t)(bh * 32 + kt) * 2048;
    #pragma unroll
    for (int t = 0; t < 8; t++) {
        int idx = tid + t * 256;
        int n = idx & 63, grp = idx >> 6;
        int c = grp >> 2, lqq = grp & 3;
        const float* kr = Kr + n * 132 + c * 16 + 2 * lqq;
        kpk[obase + grp * 64 + n] = pack_hl4(kr[0], kr[1], kr[8], kr[9]);
    }
    #pragma unroll
    for (int t = 0; t < 8; t++) {
        int idx = tid + t * 256;
        int d = idx & 127, grp = idx >> 7;
        int c = grp >> 2, lqq = grp & 3;
        const float* vr = Vp + (size_t)(c * 16 + 2 * lqq) * 2 * Dm + d;
        vpk[obase + grp * 128 + d] =
            make_float2(h2pack(vr[0], vr[2 * Dm]),
                        h2pack(vr[8 * 2 * Dm], vr[9 * 2 * Dm]));
    }
}

// ---------------------------------------------------------------------------
// fp16 3-term GEMM on pre-packed operands. CTA 128x128, BK=16, 256 threads,
// 3-stage cp.async pipeline, ONE syncthreads per chunk.
// ---------------------------------------------------------------------------
#define GSTG 1032            // float4 per stage: 512 A + 520 B (stride 130)
#define GEMM_SMEM (3 * GSTG * 16)

__global__ __launch_bounds__(256) void gemm_hp(
    int M, int N, int K,
    const float4* __restrict__ Apk,
    const float4* __restrict__ Bpk,
    const float* __restrict__ bias,
    float* __restrict__ C)
{
    extern __shared__ float4 gsm[];
    const uint32_t smu = smem_u32(gsm);
    const int tid = threadIdx.x;
    const int wid = tid >> 5, lid = tid & 31;
    const int g = lid >> 2, lq = lid & 3;
    const int m0 = blockIdx.y * 128, n0 = blockIdx.x * 128;
    const int warp_m = (wid & 1) * 64;
    const int warp_n = (wid >> 1) * 32;
    const int nc = K >> 4, K16 = K >> 4;

    float acc[4][4][4];
    #pragma unroll
    for (int mt = 0; mt < 4; mt++)
        #pragma unroll
        for (int nt = 0; nt < 4; nt++)
            #pragma unroll
            for (int e = 0; e < 4; e++) acc[mt][nt][e] = 0.f;

    auto load_tile = [&](int c, int s) {
        const uint32_t sb = smu + s * (GSTG * 16);
        #pragma unroll
        for (int t = 0; t < 2; t++) {
            int idx = tid + t * 256;
            int m = idx >> 2, j = idx & 3;
            cp16(sb + ((m * 4 + j) << 4),
                 Apk + ((size_t)(m0 + m) * K16 + c) * 4 + j);
        }
        #pragma unroll
        for (int t = 0; t < 2; t++) {
            int idx = tid + t * 256;
            int j = idx >> 7, n = idx & 127;
            cp16(sb + ((512 + j * 130 + n) << 4),
                 Bpk + (size_t)(c * 4 + j) * N + n0 + n);
        }
        asm volatile("cp.async.commit_group;" ::: "memory");
    };

    load_tile(0, 0);
    load_tile(1, 1);

    for (int c = 0; c < nc; ++c) {
        if (c + 1 < nc) { asm volatile("cp.async.wait_group 1;" ::: "memory"); }
        else            { asm volatile("cp.async.wait_group 0;" ::: "memory"); }
        __syncthreads();
        if (c + 2 < nc) load_tile(c + 2, (c + 2) % 3);

        const float4* AS_ = gsm + (c % 3) * GSTG;
        const float4* BS_ = AS_ + 512;

        uint32_t Ah[4][4], Al[4][4];
        #pragma unroll
        for (int mt = 0; mt < 4; mt++) {
            float4 fa = AS_[(warp_m + mt * 16 + g) * 4 + lq];
            float4 fb = AS_[(warp_m + mt * 16 + g + 8) * 4 + lq];
            Ah[mt][0] = FU(fa.x); Ah[mt][1] = FU(fb.x);
            Ah[mt][2] = FU(fa.y); Ah[mt][3] = FU(fb.y);
            Al[mt][0] = FU(fa.z); Al[mt][1] = FU(fb.z);
            Al[mt][2] = FU(fa.w); Al[mt][3] = FU(fb.w);
        }
        uint32_t Bh[4][2], Bl[4][2];
        #pragma unroll
        for (int nt = 0; nt < 4; nt++) {
            float4 f = BS_[lq * 130 + warp_n + nt * 8 + g];
            Bh[nt][0] = FU(f.x); Bh[nt][1] = FU(f.y);
            Bl[nt][0] = FU(f.z); Bl[nt][1] = FU(f.w);
        }
        #pragma unroll
        for (int mt = 0; mt < 4; mt++)
            #pragma unroll
            for (int nt = 0; nt < 4; nt++) {
                mma_f16(acc[mt][nt], Ah[mt][0], Ah[mt][1], Ah[mt][2], Ah[mt][3],
                        Bl[nt][0], Bl[nt][1]);
                mma_f16(acc[mt][nt], Al[mt][0], Al[mt][1], Al[mt][2], Al[mt][3],
                        Bh[nt][0], Bh[nt][1]);
                mma_f16(acc[mt][nt], Ah[mt][0], Ah[mt][1], Ah[mt][2], Ah[mt][3],
                        Bh[nt][0], Bh[nt][1]);
            }
    }

    const float s = 1.f / 256.f;
    #pragma unroll
    for (int mt = 0; mt < 4; mt++) {
        const int r0 = m0 + warp_m + mt * 16 + g;
        #pragma unroll
        for (int nt = 0; nt < 4; nt++) {
            const int col = n0 + warp_n + nt * 8 + lq * 2;
            const float2 b2 = *(const float2*)(bias + col);
            float2 o;
            o.x = acc[mt][nt][0] * s + b2.x;
            o.y = acc[mt][nt][1] * s + b2.y;
            *(float2*)(C + (size_t)r0 * N + col) = o;
            o.x = acc[mt][nt][2] * s + b2.x;
            o.y = acc[mt][nt][3] * s + b2.y;
            *(float2*)(C + (size_t)(r0 + 8) * N + col) = o;
        }
    }
}

// ---------------------------------------------------------------------------
// LayerNorm over last dim (512), in place. One block (256 threads) per row.
// ---------------------------------------------------------------------------
__global__ __launch_bounds__(256) void ln512(
    float* __restrict__ x,
    const float* __restrict__ g,
    const float* __restrict__ b)
{
    const int row = blockIdx.x;
    float* xr = x + (size_t)row * Ll;
    const int tid = threadIdx.x;

    float v0 = xr[tid];
    float v1 = xr[tid + 256];
    float s  = v0 + v1;
    float sq = v0 * v0 + v1 * v1;

    #pragma unroll
    for (int o = 16; o > 0; o >>= 1) {
        s  += __shfl_xor_sync(0xffffffffu, s,  o);
        sq += __shfl_xor_sync(0xffffffffu, sq, o);
    }
    __shared__ float ss[8], ssq[8];
    __shared__ float mean_sh, inv_sh;
    const int w = tid >> 5;
    if ((tid & 31) == 0) { ss[w] = s; ssq[w] = sq; }
    __syncthreads();
    if (tid == 0) {
        float S = 0.f, SQ = 0.f;
        #pragma unroll
        for (int i = 0; i < 8; i++) { S += ss[i]; SQ += ssq[i]; }
        float m = S * (1.f / Ll);
        float var = SQ * (1.f / Ll) - m * m;
        mean_sh = m;
        inv_sh = rsqrtf(var + 1e-5f);
    }
    __syncthreads();
    const float m = mean_sh, inv = inv_sh;
    xr[tid]       = (v0 - m) * inv * g[tid]       + b[tid];
    xr[tid + 256] = (v1 - m) * inv * g[tid + 256] + b[tid + 256];
}

// ---------------------------------------------------------------------------
// Flash attention on pre-packed K/V. CTA: 128 queries (8 warps x m16), key
// tiles of 64, HD=128. 3-stage cp.async pipeline, one syncthreads per tile.
// ---------------------------------------------------------------------------
#define STG_F  12672                 // floats per stage: K 8448 + V 4224
#define KS_F(s) ((s) * STG_F)
#define VS_F(s) ((s) * STG_F + 8448)
#define P_F    38016
#define MASK_B 172544                // bytes
#define ATT_SMEM 172736

__global__ __launch_bounds__(256, 1) void attn_mma(
    const float* __restrict__ q,
    const float4* __restrict__ kpk,
    const float2* __restrict__ vpk,
    const unsigned char* __restrict__ mask,
    float* __restrict__ out)
{
    extern __shared__ float sm[];
    unsigned char* smb = (unsigned char*)sm;

    const int bh = blockIdx.y;
    const int b = bh >> 4, h = bh & 15;
    const int qb = gridDim.x - 1 - blockIdx.x;   // heavy blocks first
    const int q0 = qb * 128;
    const int ktmax = 2 * qb + 1;

    const int tid = threadIdx.x;
    const int wid = tid >> 5, lid = tid & 31;
    const int g = lid >> 2, lq = lid & 3;
    const int warp_m = wid * 16;

    const float* Qp = q + (size_t)b * Sq * Dm + (size_t)h * HDm;
    const unsigned char* mp = mask + (size_t)b * Sq;

    const uint32_t smu = smem_u32(sm);

    // ---- stage Q raw (overlaps stage buffers; done before any load_kv) ----
    #pragma unroll
    for (int t = 0; t < 16; t++) {
        int idx = tid + t * 256;
        int row = idx >> 5, c4 = (idx & 31) << 2;
        cp16(smu + (row * 132 + c4) * 4, Qp + (size_t)(q0 + row) * Dm + c4);
    }
    asm volatile("cp.async.commit_group;" ::: "memory");
    asm volatile("cp.async.wait_group 0;" ::: "memory");
    __syncthreads();

    uint32_t Qh[8][4], Ql[8][4];
    #pragma unroll
    for (int c = 0; c < 8; c++)
        #pragma unroll
        for (int e = 0; e < 4; e++) {
            int row = warp_m + g + (e & 1) * 8;
            int col = c * 16 + 2 * lq + (e >> 1) * 8;
            float a0 = sm[row * 132 + col];
            float a1 = sm[row * 132 + col + 1];
            __half h0 = __float2half_rn(a0), h1 = __float2half_rn(a1);
            __half2 hp = __halves2half2(h0, h1);
            Qh[c][e] = *(uint32_t*)&hp;
            Ql[c][e] = FU(h2pack(a0 - __half2float(h0), a1 - __half2float(h1)));
        }
    __syncthreads();

    auto load_kv = [&](int kt, int s) {
        const float4* kg = kpk + (size_t)(bh * 32 + kt) * 2048;
        const float2* vg = vpk + (size_t)(bh * 32 + kt) * 2048;
        #pragma unroll
        for (int t = 0; t < 8; t++) {
            int idx = tid + t * 256;
            int r = idx >> 6, n = idx & 63;
            cp16(smu + KS_F(s) * 4 + (r * 66 + n) * 16, kg + r * 64 + n);
        }
        #pragma unroll
        for (int t = 0; t < 4; t++) {
            int idx = tid + t * 256;
            int r = idx >> 6, dd = idx & 63;
            cp16(smu + VS_F(s) * 4 + (r * 132 + 2 * dd) * 8, vg + r * 128 + 2 * dd);
        }
        if (tid < 4)
            cp16(smu + MASK_B + s * 64 + tid * 16, mp + kt * 64 + tid * 16);
        asm volatile("cp.async.commit_group;" ::: "memory");
    };

    load_kv(0, 0);
    load_kv(1, 1);

    const int row0 = q0 + warp_m + g;
    const int row1 = row0 + 8;
    float m_i0 = -CUDART_INF_F, m_i1 = -CUDART_INF_F;
    float l0 = 0.f, l1 = 0.f;
    float acc[16][4];
    #pragma unroll
    for (int nt = 0; nt < 16; nt++)
        #pragma unroll
        for (int e = 0; e < 4; e++) acc[nt][e] = 0.f;

    const float scale = 0.08838834764831845f;    // 1/sqrt(128)
    float2* pf2 = (float2*)(sm + P_F);

    for (int kt = 0; kt <= ktmax; ++kt) {
        const int st = kt % 3;
        if (kt < ktmax) { asm volatile("cp.async.wait_group 1;" ::: "memory"); }
        else            { asm volatile("cp.async.wait_group 0;" ::: "memory"); }
        __syncthreads();
        if (kt + 2 <= ktmax) load_kv(kt + 2, (kt + 2) % 3);

        const float4* kf4 = (const float4*)(sm + KS_F(st));
        const float2* vf2 = (const float2*)(sm + VS_F(st));
        const unsigned char* mk = smb + MASK_B + st * 64;

        // ---- scores: S = Q @ K^T  (3-term fp16) ----
        float sc[8][4];
        #pragma unroll
        for (int nt = 0; nt < 8; nt++)
            #pragma unroll
            for (int e = 0; e < 4; e++) sc[nt][e] = 0.f;

        #pragma unroll 4
        for (int c = 0; c < 8; c++) {
            const float4* kp_ = kf4 + (c * 4 + lq) * 66;
            #pragma unroll
            for (int nt = 0; nt < 8; nt++) {
                float4 kk = kp_[nt * 8 + g];
                mma_f16(sc[nt], Qh[c][0], Qh[c][1], Qh[c][2], Qh[c][3],
                        FU(kk.z), FU(kk.w));
                mma_f16(sc[nt], Ql[c][0], Ql[c][1], Ql[c][2], Ql[c][3],
                        FU(kk.x), FU(kk.y));
                mma_f16(sc[nt], Qh[c][0], Qh[c][1], Qh[c][2], Qh[c][3],
                        FU(kk.x), FU(kk.y));
            }
        }

        // ---- mask + scale + row max ----
        const bool diag = (kt >= 2 * qb);
        float m0 = -CUDART_INF_F, m1 = -CUDART_INF_F;
        #pragma unroll
        for (int nt = 0; nt < 8; nt++) {
            const int cl = nt * 8 + 2 * lq;
            const int cg = kt * 64 + cl;
            const bool pk0 = mk[cl] != 0, pk1 = mk[cl + 1] != 0;
            float v0 = (pk0 || (diag && cg     > row0)) ? -CUDART_INF_F : sc[nt][0] * scale;
            float v1 = (pk1 || (diag && cg + 1 > row0)) ? -CUDART_INF_F : sc[nt][1] * scale;
            float v2 = (pk0 || (diag && cg     > row1)) ? -CUDART_INF_F : sc[nt][2] * scale;
            float v3 = (pk1 || (diag && cg + 1 > row1)) ? -CUDART_INF_F : sc[nt][3] * scale;
            sc[nt][0] = v0; sc[nt][1] = v1; sc[nt][2] = v2; sc[nt][3] = v3;
            m0 = fmaxf(m0, fmaxf(v0, v1));
            m1 = fmaxf(m1, fmaxf(v2, v3));
        }
        m0 = fmaxf(m0, __shfl_xor_sync(0xffffffffu, m0, 1));
        m0 = fmaxf(m0, __shfl_xor_sync(0xffffffffu, m0, 2));
        m1 = fmaxf(m1, __shfl_xor_sync(0xffffffffu, m1, 1));
        m1 = fmaxf(m1, __shfl_xor_sync(0xffffffffu, m1, 2));

        const float mn0 = fmaxf(m_i0, m0), mn1 = fmaxf(m_i1, m1);
        const float corr0 = (mn0 == -CUDART_INF_F) ? 1.f : __expf(m_i0 - mn0);
        const float corr1 = (mn1 == -CUDART_INF_F) ? 1.f : __expf(m_i1 - mn1);
        const float base0 = (mn0 == -CUDART_INF_F) ? 0.f : mn0;
        const float base1 = (mn1 == -CUDART_INF_F) ? 0.f : mn1;

        float psum0 = 0.f, psum1 = 0.f;
        uint32_t ptop_prev = 0, pbot_prev = 0;
        __syncwarp();
        #pragma unroll
        for (int nt = 0; nt < 8; nt++) {
            float p0 = (sc[nt][0] == -CUDART_INF_F) ? 0.f : __expf(sc[nt][0] - base0);
            float p1 = (sc[nt][1] == -CUDART_INF_F) ? 0.f : __expf(sc[nt][1] - base0);
            float p2 = (sc[nt][2] == -CUDART_INF_F) ? 0.f : __expf(sc[nt][2] - base1);
            float p3 = (sc[nt][3] == -CUDART_INF_F) ? 0.f : __expf(sc[nt][3] - base1);
            psum0 += p0 + p1;
            psum1 += p2 + p3;
            uint32_t top = FU(h2pack(p0, p1));
            uint32_t bot = FU(h2pack(p2, p3));
            if (nt & 1) {
                const int c = nt >> 1;
                pf2[(warp_m + g) * 20 + c * 4 + lq] =
                    make_float2(__uint_as_float(ptop_prev), __uint_as_float(top));
                pf2[(warp_m + g + 8) * 20 + c * 4 + lq] =
                    make_float2(__uint_as_float(pbot_prev), __uint_as_float(bot));
            } else { ptop_prev = top; pbot_prev = bot; }
        }
        psum0 += __shfl_xor_sync(0xffffffffu, psum0, 1);
        psum0 += __shfl_xor_sync(0xffffffffu, psum0, 2);
        psum1 += __shfl_xor_sync(0xffffffffu, psum1, 1);
        psum1 += __shfl_xor_sync(0xffffffffu, psum1, 2);
        l0 = l0 * corr0 + psum0;
        l1 = l1 * corr1 + psum1;
        m_i0 = mn0; m_i1 = mn1;

        #pragma unroll
        for (int nt = 0; nt < 16; nt++) {
            acc[nt][0] *= corr0; acc[nt][1] *= corr0;
            acc[nt][2] *= corr1; acc[nt][3] *= corr1;
        }
        __syncwarp();

        // ---- O += P @ V  (1x fp16, packed) ----
        #pragma unroll
        for (int c = 0; c < 4; c++) {
            float2 pa = pf2[(warp_m + g) * 20 + c * 4 + lq];
            float2 pb = pf2[(warp_m + g + 8) * 20 + c * 4 + lq];
            uint32_t A0 = FU(pa.x), A1 = FU(pb.x), A2 = FU(pa.y), A3 = FU(pb.y);
            const float2* vp = vf2 + (c * 4 + lq) * 132;
            #pragma unroll
            for (int nt = 0; nt < 16; nt++) {
                float2 vv = vp[nt * 8 + g];
                mma_f16(acc[nt], A0, A1, A2, A3, FU(vv.x), FU(vv.y));
            }
        }
    }

    // ---- epilogue ----
    const float inv0 = (l0 > 0.f) ? (1.f / l0) : 0.f;
    const float inv1 = (l1 > 0.f) ? (1.f / l1) : 0.f;
    float* o0 = out + (size_t)(b * Sq + row0) * Dm + (size_t)h * HDm;
    float* o1 = out + (size_t)(b * Sq + row1) * Dm + (size_t)h * HDm;
    #pragma unroll
    for (int nt = 0; nt < 16; nt++) {
        const int cl = nt * 8 + 2 * lq;
        *(float2*)(o0 + cl) = make_float2(acc[nt][0] * inv0, acc[nt][1] * inv0);
        *(float2*)(o1 + cl) = make_float2(acc[nt][2] * inv1, acc[nt][3] * inv1);
    }
}

// ---------------------------------------------------------------------------
// Launch
// ---------------------------------------------------------------------------
extern "C" void kernel_launch(void* const* d_in, const int* in_sizes, int n_in,
                              void* d_out, int out_size)
{
    const float*         x        = (const float*)d_in[0];
    const unsigned char* mask     = (const unsigned char*)d_in[1];
    const float*         wq_down  = (const float*)d_in[2];
    const float*         bq_down  = (const float*)d_in[3];
    const float*         gq_ln    = (const float*)d_in[4];
    const float*         bq_ln    = (const float*)d_in[5];
    const float*         wq_up    = (const float*)d_in[6];
    const float*         bq_up    = (const float*)d_in[7];
    const float*         wkv_down = (const float*)d_in[8];
    const float*         bkv_down = (const float*)d_in[9];
    const float*         gkv_ln   = (const float*)d_in[10];
    const float*         bkv_ln   = (const float*)d_in[11];
    const float*         wkv_up   = (const float*)d_in[12];
    const float*         bkv_up   = (const float*)d_in[13];
    const float*         w_out    = (const float*)d_in[14];
    const float*         b_out    = (const float*)d_in[15];
    float* out = (float*)d_out;

    float *qlat, *qb, *kvlat, *kvb, *attnb;
    float4 *wpk, *apk, *lpk, *kpk;
    float2 *vpk;
    cudaGetSymbolAddress((void**)&qlat,  g_qlat);
    cudaGetSymbolAddress((void**)&qb,    g_q);
    cudaGetSymbolAddress((void**)&kvlat, g_kvlat);
    cudaGetSymbolAddress((void**)&kvb,   g_kv);
    cudaGetSymbolAddress((void**)&attnb, g_attn);
    cudaGetSymbolAddress((void**)&wpk,   g_wpk);
    cudaGetSymbolAddress((void**)&apk,   g_apk);
    cudaGetSymbolAddress((void**)&lpk,   g_lpk);
    cudaGetSymbolAddress((void**)&kpk,   g_kpk);
    cudaGetSymbolAddress((void**)&vpk,   g_vpk);

    cudaFuncSetAttribute(attn_mma,
                         cudaFuncAttributeMaxDynamicSharedMemorySize, ATT_SMEM);
    cudaFuncSetAttribute(gemm_hp,
                         cudaFuncAttributeMaxDynamicSharedMemorySize, GEMM_SMEM);

    // ---- Q/KV down-projections ----
    {
        int tot = Mrows * Dm / 4;
        pack_act<<<tot / 256, 256>>>(x, apk, Dm, tot);
    }
    {
        int tot = (Dm / 16) * 4 * Ll;
        pack_w<<<tot / 256, 256>>>(wq_down, wpk, Ll, tot);
        gemm_hp<<<dim3(Ll / 128, Mrows / 128), 256, GEMM_SMEM>>>(
            Mrows, Ll, Dm, apk, wpk, bq_down, qlat);
        pack_w<<<tot / 256, 256>>>(wkv_down, wpk, Ll, tot);
        gemm_hp<<<dim3(Ll / 128, Mrows / 128), 256, GEMM_SMEM>>>(
            Mrows, Ll, Dm, apk, wpk, bkv_down, kvlat);
    }
    ln512<<<Mrows, 256>>>(qlat, gq_ln, bq_ln);
    ln512<<<Mrows, 256>>>(kvlat, gkv_ln, bkv_ln);

    // ---- up-projections ----
    {
        int tota = Mrows * Ll / 4;
        int totw = (Ll / 16) * 4 * Dm;
        pack_act<<<tota / 256, 256>>>(qlat, lpk, Ll, tota);
        pack_w<<<totw / 256, 256>>>(wq_up, wpk, Dm, totw);
        gemm_hp<<<dim3(Dm / 128, Mrows / 128), 256, GEMM_SMEM>>>(
            Mrows, Dm, Ll, lpk, wpk, bq_up, qb);
        pack_act<<<tota / 256, 256>>>(kvlat, lpk, Ll, tota);
        int totw2 = (Ll / 16) * 4 * 2 * Dm;
        pack_w<<<totw2 / 256, 256>>>(wkv_up, wpk, 2 * Dm, totw2);
        gemm_hp<<<dim3(2 * Dm / 128, Mrows / 128), 256, GEMM_SMEM>>>(
            Mrows, 2 * Dm, Ll, lpk, wpk, bkv_up, kvb);
    }

    // ---- attention ----
    pack_kv<<<dim3(Sq / 64, Bsz * Hh), 256>>>(kvb, kpk, vpk);
    attn_mma<<<dim3(Sq / 128, Bsz * Hh), 256, ATT_SMEM>>>(qb, kpk, vpk, mask, attnb);

    // ---- output projection ----
    {
        int tota = Mrows * Dm / 4;
        int totw = (Dm / 16) * 4 * Dm;
        pack_act<<<tota / 256, 256>>>(attnb, apk, Dm, tota);
        pack_w<<<totw / 256, 256>>>(w_out, wpk, Dm, totw);
        gemm_hp<<<dim3(Dm / 128, Mrows / 128), 256, GEMM_SMEM>>>(
            Mrows, Dm, Dm, apk, wpk, b_out, out);
    }
}

// round 11
// speedup vs baseline: 2.3280x; 1.0160x over previous
#include <cuda_runtime.h>
#include <cuda_fp16.h>
#include <math_constants.h>
#include <cstdint>

// Problem constants
#define Bsz 2
#define Sq  2048
#define Dm  2048
#define Hh  16
#define Ll  512
#define HDm 128
#define Mrows (Bsz*Sq)      // 4096

// ---------------------------------------------------------------------------
// Scratch (static device globals — no runtime allocation allowed)
// ---------------------------------------------------------------------------
__device__ float  g_qlat [(size_t)Mrows * Ll];
__device__ float  g_q    [(size_t)Mrows * Dm];
__device__ float  g_kvlat[(size_t)Mrows * Ll];
__device__ float  g_kv   [(size_t)Mrows * 2 * Dm];
__device__ float4 g_wpk  [(size_t)Dm * Dm / 4];      // packed weights (reused)
__device__ float4 g_apk  [(size_t)Mrows * Dm / 4];   // packed acts (x, attn out)
__device__ float4 g_lpk  [(size_t)Mrows * Ll / 4];   // packed latents (reused)
__device__ float4 g_kpk  [(size_t)Mrows * Dm / 4];   // packed K fragments
__device__ float2 g_vpk  [(size_t)Mrows * Dm / 4];   // packed V half2 pairs

// ---------------------------------------------------------------------------
// Helpers
// ---------------------------------------------------------------------------
__device__ __forceinline__ uint32_t smem_u32(const void* p) {
    uint32_t a;
    asm("{ .reg .u64 t; cvta.to.shared.u64 t, %1; cvt.u32.u64 %0, t; }"
        : "=r"(a) : "l"(p));
    return a;
}
__device__ __forceinline__ void cp16(uint32_t dst, const void* src) {
    asm volatile("cp.async.cg.shared.global [%0], [%1], 16;"
                 :: "r"(dst), "l"(src) : "memory");
}
__device__ __forceinline__ float h2pack(float a, float b) {
    __half2 h = __halves2half2(__float2half_rn(a), __float2half_rn(b));
    return __uint_as_float(*(uint32_t*)&h);
}
__device__ __forceinline__ float4 pack_hl4(float a0, float a1, float a2, float a3) {
    __half h0 = __float2half_rn(a0), h1 = __float2half_rn(a1);
    __half h2 = __float2half_rn(a2), h3 = __float2half_rn(a3);
    float4 r;
    __half2 p;
    p = __halves2half2(h0, h1); r.x = __uint_as_float(*(uint32_t*)&p);
    p = __halves2half2(h2, h3); r.y = __uint_as_float(*(uint32_t*)&p);
    r.z = h2pack(a0 - __half2float(h0), a1 - __half2float(h1));
    r.w = h2pack(a2 - __half2float(h2), a3 - __half2float(h3));
    return r;
}
__device__ __forceinline__ void mma_f16(
    float c[4], uint32_t a0, uint32_t a1, uint32_t a2, uint32_t a3,
    uint32_t b0, uint32_t b1)
{
    asm volatile(
        "mma.sync.aligned.m16n8k16.row.col.f32.f16.f16.f32 "
        "{%0,%1,%2,%3}, {%4,%5,%6,%7}, {%8,%9}, {%0,%1,%2,%3};"
        : "+f"(c[0]), "+f"(c[1]), "+f"(c[2]), "+f"(c[3])
        : "r"(a0), "r"(a1), "r"(a2), "r"(a3), "r"(b0), "r"(b1));
}
#define FU(x) __float_as_uint(x)

// ---------------------------------------------------------------------------
// Pack kernels — one-time fp32 -> packed fp16 hi/lo fragment layouts
// ---------------------------------------------------------------------------
__global__ __launch_bounds__(256) void pack_act(
    const float* __restrict__ A, float4* __restrict__ out, int K, int total)
{
    int idx = blockIdx.x * 256 + threadIdx.x;
    if (idx >= total) return;
    int lq = idx & 3, rest = idx >> 2;
    int jc = rest % (K >> 4), m = rest / (K >> 4);
    const float* base = A + (size_t)m * K + 16 * jc + 2 * lq;
    float2 a = *(const float2*)base;
    float2 b = *(const float2*)(base + 8);
    out[idx] = pack_hl4(a.x, a.y, b.x, b.y);
}
__global__ __launch_bounds__(256) void pack_w(
    const float* __restrict__ W, float4* __restrict__ out, int N, int total)
{
    int idx = blockIdx.x * 256 + threadIdx.x;
    if (idx >= total) return;
    int n = idx % N, g2 = idx / N;
    int lq = g2 & 3, jc = g2 >> 2;
    size_t k = 16 * jc + 2 * lq;
    out[idx] = pack_hl4(W[k * N + n] * 256.f, W[(k + 1) * N + n] * 256.f,
                        W[(k + 8) * N + n] * 256.f, W[(k + 9) * N + n] * 256.f);
}
// KV pack: one block per (kt, bh) tile.
__global__ __launch_bounds__(256) void pack_kv(
    const float* __restrict__ kv, float4* __restrict__ kpk, float2* __restrict__ vpk)
{
    __shared__ float Kr[64 * 132];
    const int kt = blockIdx.x, bh = blockIdx.y;
    const int b = bh >> 4, h = bh & 15;
    const float* Kp = kv + (size_t)b * Sq * 2 * Dm + (size_t)h * HDm
                         + (size_t)kt * 64 * 2 * Dm;
    const float* Vp = Kp + Dm;
    const uint32_t smu = smem_u32(Kr);
    const int tid = threadIdx.x;

    #pragma unroll
    for (int t = 0; t < 8; t++) {
        int idx = tid + t * 256;
        int row = idx >> 5, c4 = (idx & 31) * 4;
        cp16(smu + (row * 132 + c4) * 4, Kp + (size_t)row * 2 * Dm + c4);
    }
    asm volatile("cp.async.commit_group;" ::: "memory");
    asm volatile("cp.async.wait_group 0;" ::: "memory");
    __syncthreads();

    const size_t obase = (size_t)(bh * 32 + kt) * 2048;
    #pragma unroll
    for (int t = 0; t < 8; t++) {
        int idx = tid + t * 256;
        int n = idx & 63, grp = idx >> 6;
        int c = grp >> 2, lqq = grp & 3;
        const float* kr = Kr + n * 132 + c * 16 + 2 * lqq;
        kpk[obase + grp * 64 + n] = pack_hl4(kr[0], kr[1], kr[8], kr[9]);
    }
    #pragma unroll
    for (int t = 0; t < 8; t++) {
        int idx = tid + t * 256;
        int d = idx & 127, grp = idx >> 7;
        int c = grp >> 2, lqq = grp & 3;
        const float* vr = Vp + (size_t)(c * 16 + 2 * lqq) * 2 * Dm + d;
        vpk[obase + grp * 128 + d] =
            make_float2(h2pack(vr[0], vr[2 * Dm]),
                        h2pack(vr[8 * 2 * Dm], vr[9 * 2 * Dm]));
    }
}

// ---------------------------------------------------------------------------
// fp16 3-term GEMM on pre-packed operands. CTA 128x128, BK=16, 256 threads,
// 3-stage cp.async pipeline, one syncthreads per chunk. 2 CTAs/SM.
// ---------------------------------------------------------------------------
#define GSTG 1032            // float4 per stage: 512 A + 520 B (stride 130)
#define GEMM_SMEM (3 * GSTG * 16)

__global__ __launch_bounds__(256, 2) void gemm_hp(
    int M, int N, int K,
    const float4* __restrict__ Apk,
    const float4* __restrict__ Bpk,
    const float* __restrict__ bias,
    float* __restrict__ C)
{
    extern __shared__ float4 gsm[];
    const uint32_t smu = smem_u32(gsm);
    const int tid = threadIdx.x;
    const int wid = tid >> 5, lid = tid & 31;
    const int g = lid >> 2, lq = lid & 3;
    const int m0 = blockIdx.y * 128, n0 = blockIdx.x * 128;
    const int warp_m = (wid & 1) * 64;
    const int warp_n = (wid >> 1) * 32;
    const int nc = K >> 4, K16 = K >> 4;

    float acc[4][4][4];
    #pragma unroll
    for (int mt = 0; mt < 4; mt++)
        #pragma unroll
        for (int nt = 0; nt < 4; nt++)
            #pragma unroll
            for (int e = 0; e < 4; e++) acc[mt][nt][e] = 0.f;

    auto load_tile = [&](int c, int s) {
        const uint32_t sb = smu + s * (GSTG * 16);
        #pragma unroll
        for (int t = 0; t < 2; t++) {
            int idx = tid + t * 256;
            int m = idx >> 2, j = idx & 3;
            cp16(sb + ((m * 4 + j) << 4),
                 Apk + ((size_t)(m0 + m) * K16 + c) * 4 + j);
        }
        #pragma unroll
        for (int t = 0; t < 2; t++) {
            int idx = tid + t * 256;
            int j = idx >> 7, n = idx & 127;
            cp16(sb + ((512 + j * 130 + n) << 4),
                 Bpk + (size_t)(c * 4 + j) * N + n0 + n);
        }
        asm volatile("cp.async.commit_group;" ::: "memory");
    };

    load_tile(0, 0);
    load_tile(1, 1);

    for (int c = 0; c < nc; ++c) {
        if (c + 1 < nc) { asm volatile("cp.async.wait_group 1;" ::: "memory"); }
        else            { asm volatile("cp.async.wait_group 0;" ::: "memory"); }
        __syncthreads();
        if (c + 2 < nc) load_tile(c + 2, (c + 2) % 3);

        const float4* AS_ = gsm + (c % 3) * GSTG;
        const float4* BS_ = AS_ + 512;

        uint32_t Ah[4][4], Al[4][4];
        #pragma unroll
        for (int mt = 0; mt < 4; mt++) {
            float4 fa = AS_[(warp_m + mt * 16 + g) * 4 + lq];
            float4 fb = AS_[(warp_m + mt * 16 + g + 8) * 4 + lq];
            Ah[mt][0] = FU(fa.x); Ah[mt][1] = FU(fb.x);
            Ah[mt][2] = FU(fa.y); Ah[mt][3] = FU(fb.y);
            Al[mt][0] = FU(fa.z); Al[mt][1] = FU(fb.z);
            Al[mt][2] = FU(fa.w); Al[mt][3] = FU(fb.w);
        }
        uint32_t Bh[4][2], Bl[4][2];
        #pragma unroll
        for (int nt = 0; nt < 4; nt++) {
            float4 f = BS_[lq * 130 + warp_n + nt * 8 + g];
            Bh[nt][0] = FU(f.x); Bh[nt][1] = FU(f.y);
            Bl[nt][0] = FU(f.z); Bl[nt][1] = FU(f.w);
        }
        #pragma unroll
        for (int mt = 0; mt < 4; mt++)
            #pragma unroll
            for (int nt = 0; nt < 4; nt++) {
                mma_f16(acc[mt][nt], Ah[mt][0], Ah[mt][1], Ah[mt][2], Ah[mt][3],
                        Bl[nt][0], Bl[nt][1]);
                mma_f16(acc[mt][nt], Al[mt][0], Al[mt][1], Al[mt][2], Al[mt][3],
                        Bh[nt][0], Bh[nt][1]);
                mma_f16(acc[mt][nt], Ah[mt][0], Ah[mt][1], Ah[mt][2], Ah[mt][3],
                        Bh[nt][0], Bh[nt][1]);
            }
    }

    const float s = 1.f / 256.f;
    #pragma unroll
    for (int mt = 0; mt < 4; mt++) {
        const int r0 = m0 + warp_m + mt * 16 + g;
        #pragma unroll
        for (int nt = 0; nt < 4; nt++) {
            const int col = n0 + warp_n + nt * 8 + lq * 2;
            const float2 b2 = *(const float2*)(bias + col);
            float2 o;
            o.x = acc[mt][nt][0] * s + b2.x;
            o.y = acc[mt][nt][1] * s + b2.y;
            *(float2*)(C + (size_t)r0 * N + col) = o;
            o.x = acc[mt][nt][2] * s + b2.x;
            o.y = acc[mt][nt][3] * s + b2.y;
            *(float2*)(C + (size_t)(r0 + 8) * N + col) = o;
        }
    }
}

// ---------------------------------------------------------------------------
// LayerNorm over last dim (512), emitting packed fp16 hi/lo fragments
// directly (same layout as pack_act with K=512). One block per row.
// ---------------------------------------------------------------------------
__global__ __launch_bounds__(256) void ln512_pack(
    const float* __restrict__ x,
    const float* __restrict__ g,
    const float* __restrict__ b,
    float4* __restrict__ out)
{
    __shared__ float row_sh[512];
    const int row = blockIdx.x;
    const float* xr = x + (size_t)row * Ll;
    const int tid = threadIdx.x;

    float v0 = xr[tid];
    float v1 = xr[tid + 256];
    float s  = v0 + v1;
    float sq = v0 * v0 + v1 * v1;

    #pragma unroll
    for (int o = 16; o > 0; o >>= 1) {
        s  += __shfl_xor_sync(0xffffffffu, s,  o);
        sq += __shfl_xor_sync(0xffffffffu, sq, o);
    }
    __shared__ float ss[8], ssq[8];
    __shared__ float mean_sh, inv_sh;
    const int w = tid >> 5;
    if ((tid & 31) == 0) { ss[w] = s; ssq[w] = sq; }
    __syncthreads();
    if (tid == 0) {
        float S = 0.f, SQ = 0.f;
        #pragma unroll
        for (int i = 0; i < 8; i++) { S += ss[i]; SQ += ssq[i]; }
        float m = S * (1.f / Ll);
        float var = SQ * (1.f / Ll) - m * m;
        mean_sh = m;
        inv_sh = rsqrtf(var + 1e-5f);
    }
    __syncthreads();
    const float m = mean_sh, inv = inv_sh;
    row_sh[tid]       = (v0 - m) * inv * g[tid]       + b[tid];
    row_sh[tid + 256] = (v1 - m) * inv * g[tid + 256] + b[tid + 256];
    __syncthreads();
    if (tid < 128) {
        int jc = tid >> 2, lq = tid & 3;
        const float* p = row_sh + 16 * jc + 2 * lq;
        out[(size_t)row * 128 + tid] = pack_hl4(p[0], p[1], p[8], p[9]);
    }
}

// ---------------------------------------------------------------------------
// Flash attention on pre-packed K/V; output written DIRECTLY as packed
// fragments (apk, pack_act layout for K=2048: 512 float4 per row).
// CTA: 128 queries (8 warps x m16).
// ---------------------------------------------------------------------------
#define STG_F  12672                 // floats per stage: K 8448 + V 4224
#define KS_F(s) ((s) * STG_F)
#define VS_F(s) ((s) * STG_F + 8448)
#define P_F    38016
#define MASK_B 172544                // bytes
#define ATT_SMEM 172736

__global__ __launch_bounds__(256, 1) void attn_mma(
    const float* __restrict__ q,
    const float4* __restrict__ kpk,
    const float2* __restrict__ vpk,
    const unsigned char* __restrict__ mask,
    float4* __restrict__ apk)
{
    extern __shared__ float sm[];
    unsigned char* smb = (unsigned char*)sm;

    const int bh = blockIdx.y;
    const int b = bh >> 4, h = bh & 15;
    const int qb = gridDim.x - 1 - blockIdx.x;   // heavy blocks first
    const int q0 = qb * 128;
    const int ktmax = 2 * qb + 1;

    const int tid = threadIdx.x;
    const int wid = tid >> 5, lid = tid & 31;
    const int g = lid >> 2, lq = lid & 3;
    const int warp_m = wid * 16;

    const float* Qp = q + (size_t)b * Sq * Dm + (size_t)h * HDm;
    const unsigned char* mp = mask + (size_t)b * Sq;

    const uint32_t smu = smem_u32(sm);

    // ---- stage Q raw (overlaps stage buffers; done before any load_kv) ----
    #pragma unroll
    for (int t = 0; t < 16; t++) {
        int idx = tid + t * 256;
        int row = idx >> 5, c4 = (idx & 31) << 2;
        cp16(smu + (row * 132 + c4) * 4, Qp + (size_t)(q0 + row) * Dm + c4);
    }
    asm volatile("cp.async.commit_group;" ::: "memory");
    asm volatile("cp.async.wait_group 0;" ::: "memory");
    __syncthreads();

    uint32_t Qh[8][4], Ql[8][4];
    #pragma unroll
    for (int c = 0; c < 8; c++)
        #pragma unroll
        for (int e = 0; e < 4; e++) {
            int row = warp_m + g + (e & 1) * 8;
            int col = c * 16 + 2 * lq + (e >> 1) * 8;
            float a0 = sm[row * 132 + col];
            float a1 = sm[row * 132 + col + 1];
            __half h0 = __float2half_rn(a0), h1 = __float2half_rn(a1);
            __half2 hp = __halves2half2(h0, h1);
            Qh[c][e] = *(uint32_t*)&hp;
            Ql[c][e] = FU(h2pack(a0 - __half2float(h0), a1 - __half2float(h1)));
        }
    __syncthreads();

    auto load_kv = [&](int kt, int s) {
        const float4* kg = kpk + (size_t)(bh * 32 + kt) * 2048;
        const float2* vg = vpk + (size_t)(bh * 32 + kt) * 2048;
        #pragma unroll
        for (int t = 0; t < 8; t++) {
            int idx = tid + t * 256;
            int r = idx >> 6, n = idx & 63;
            cp16(smu + KS_F(s) * 4 + (r * 66 + n) * 16, kg + r * 64 + n);
        }
        #pragma unroll
        for (int t = 0; t < 4; t++) {
            int idx = tid + t * 256;
            int r = idx >> 6, dd = idx & 63;
            cp16(smu + VS_F(s) * 4 + (r * 132 + 2 * dd) * 8, vg + r * 128 + 2 * dd);
        }
        if (tid < 4)
            cp16(smu + MASK_B + s * 64 + tid * 16, mp + kt * 64 + tid * 16);
        asm volatile("cp.async.commit_group;" ::: "memory");
    };

    load_kv(0, 0);
    load_kv(1, 1);

    const int row0 = q0 + warp_m + g;
    const int row1 = row0 + 8;
    float m_i0 = -CUDART_INF_F, m_i1 = -CUDART_INF_F;
    float l0 = 0.f, l1 = 0.f;
    float acc[16][4];
    #pragma unroll
    for (int nt = 0; nt < 16; nt++)
        #pragma unroll
        for (int e = 0; e < 4; e++) acc[nt][e] = 0.f;

    const float scale = 0.08838834764831845f;    // 1/sqrt(128)
    float2* pf2 = (float2*)(sm + P_F);

    for (int kt = 0; kt <= ktmax; ++kt) {
        const int st = kt % 3;
        if (kt < ktmax) { asm volatile("cp.async.wait_group 1;" ::: "memory"); }
        else            { asm volatile("cp.async.wait_group 0;" ::: "memory"); }
        __syncthreads();
        if (kt + 2 <= ktmax) load_kv(kt + 2, (kt + 2) % 3);

        const float4* kf4 = (const float4*)(sm + KS_F(st));
        const float2* vf2 = (const float2*)(sm + VS_F(st));
        const unsigned char* mk = smb + MASK_B + st * 64;

        // ---- scores: S = Q @ K^T  (3-term fp16) ----
        float sc[8][4];
        #pragma unroll
        for (int nt = 0; nt < 8; nt++)
            #pragma unroll
            for (int e = 0; e < 4; e++) sc[nt][e] = 0.f;

        #pragma unroll 4
        for (int c = 0; c < 8; c++) {
            const float4* kp_ = kf4 + (c * 4 + lq) * 66;
            #pragma unroll
            for (int nt = 0; nt < 8; nt++) {
                float4 kk = kp_[nt * 8 + g];
                mma_f16(sc[nt], Qh[c][0], Qh[c][1], Qh[c][2], Qh[c][3],
                        FU(kk.z), FU(kk.w));
                mma_f16(sc[nt], Ql[c][0], Ql[c][1], Ql[c][2], Ql[c][3],
                        FU(kk.x), FU(kk.y));
                mma_f16(sc[nt], Qh[c][0], Qh[c][1], Qh[c][2], Qh[c][3],
                        FU(kk.x), FU(kk.y));
            }
        }

        // ---- mask + scale + row max ----
        const bool diag = (kt >= 2 * qb);
        float m0 = -CUDART_INF_F, m1 = -CUDART_INF_F;
        #pragma unroll
        for (int nt = 0; nt < 8; nt++) {
            const int cl = nt * 8 + 2 * lq;
            const int cg = kt * 64 + cl;
            const bool pk0 = mk[cl] != 0, pk1 = mk[cl + 1] != 0;
            float v0 = (pk0 || (diag && cg     > row0)) ? -CUDART_INF_F : sc[nt][0] * scale;
            float v1 = (pk1 || (diag && cg + 1 > row0)) ? -CUDART_INF_F : sc[nt][1] * scale;
            float v2 = (pk0 || (diag && cg     > row1)) ? -CUDART_INF_F : sc[nt][2] * scale;
            float v3 = (pk1 || (diag && cg + 1 > row1)) ? -CUDART_INF_F : sc[nt][3] * scale;
            sc[nt][0] = v0; sc[nt][1] = v1; sc[nt][2] = v2; sc[nt][3] = v3;
            m0 = fmaxf(m0, fmaxf(v0, v1));
            m1 = fmaxf(m1, fmaxf(v2, v3));
        }
        m0 = fmaxf(m0, __shfl_xor_sync(0xffffffffu, m0, 1));
        m0 = fmaxf(m0, __shfl_xor_sync(0xffffffffu, m0, 2));
        m1 = fmaxf(m1, __shfl_xor_sync(0xffffffffu, m1, 1));
        m1 = fmaxf(m1, __shfl_xor_sync(0xffffffffu, m1, 2));

        const float mn0 = fmaxf(m_i0, m0), mn1 = fmaxf(m_i1, m1);
        const float corr0 = (mn0 == -CUDART_INF_F) ? 1.f : __expf(m_i0 - mn0);
        const float corr1 = (mn1 == -CUDART_INF_F) ? 1.f : __expf(m_i1 - mn1);
        const float base0 = (mn0 == -CUDART_INF_F) ? 0.f : mn0;
        const float base1 = (mn1 == -CUDART_INF_F) ? 0.f : mn1;

        float psum0 = 0.f, psum1 = 0.f;
        uint32_t ptop_prev = 0, pbot_prev = 0;
        __syncwarp();
        #pragma unroll
        for (int nt = 0; nt < 8; nt++) {
            float p0 = (sc[nt][0] == -CUDART_INF_F) ? 0.f : __expf(sc[nt][0] - base0);
            float p1 = (sc[nt][1] == -CUDART_INF_F) ? 0.f : __expf(sc[nt][1] - base0);
            float p2 = (sc[nt][2] == -CUDART_INF_F) ? 0.f : __expf(sc[nt][2] - base1);
            float p3 = (sc[nt][3] == -CUDART_INF_F) ? 0.f : __expf(sc[nt][3] - base1);
            psum0 += p0 + p1;
            psum1 += p2 + p3;
            uint32_t top = FU(h2pack(p0, p1));
            uint32_t bot = FU(h2pack(p2, p3));
            if (nt & 1) {
                const int c = nt >> 1;
                pf2[(warp_m + g) * 20 + c * 4 + lq] =
                    make_float2(__uint_as_float(ptop_prev), __uint_as_float(top));
                pf2[(warp_m + g + 8) * 20 + c * 4 + lq] =
                    make_float2(__uint_as_float(pbot_prev), __uint_as_float(bot));
            } else { ptop_prev = top; pbot_prev = bot; }
        }
        psum0 += __shfl_xor_sync(0xffffffffu, psum0, 1);
        psum0 += __shfl_xor_sync(0xffffffffu, psum0, 2);
        psum1 += __shfl_xor_sync(0xffffffffu, psum1, 1);
        psum1 += __shfl_xor_sync(0xffffffffu, psum1, 2);
        l0 = l0 * corr0 + psum0;
        l1 = l1 * corr1 + psum1;
        m_i0 = mn0; m_i1 = mn1;

        #pragma unroll
        for (int nt = 0; nt < 16; nt++) {
            acc[nt][0] *= corr0; acc[nt][1] *= corr0;
            acc[nt][2] *= corr1; acc[nt][3] *= corr1;
        }
        __syncwarp();

        // ---- O += P @ V  (1x fp16, packed) ----
        #pragma unroll
        for (int c = 0; c < 4; c++) {
            float2 pa = pf2[(warp_m + g) * 20 + c * 4 + lq];
            float2 pb = pf2[(warp_m + g + 8) * 20 + c * 4 + lq];
            uint32_t A0 = FU(pa.x), A1 = FU(pb.x), A2 = FU(pa.y), A3 = FU(pb.y);
            const float2* vp = vf2 + (c * 4 + lq) * 132;
            #pragma unroll
            for (int nt = 0; nt < 16; nt++) {
                float2 vv = vp[nt * 8 + g];
                mma_f16(acc[nt], A0, A1, A2, A3, FU(vv.x), FU(vv.y));
            }
        }
    }

    // ---- epilogue: write packed fragments directly (pack_act K=2048 layout:
    //      row stride 512 float4; fragment (h*8+c, lq) at row*512 + (h*8+c)*4+lq)
    const float inv0 = (l0 > 0.f) ? (1.f / l0) : 0.f;
    const float inv1 = (l1 > 0.f) ? (1.f / l1) : 0.f;
    const size_t fb0 = (size_t)(b * Sq + row0) * 512 + (h * 8) * 4 + lq;
    const size_t fb1 = (size_t)(b * Sq + row1) * 512 + (h * 8) * 4 + lq;
    #pragma unroll
    for (int c = 0; c < 8; c++) {
        apk[fb0 + c * 4] = pack_hl4(acc[2*c][0] * inv0, acc[2*c][1] * inv0,
                                    acc[2*c+1][0] * inv0, acc[2*c+1][1] * inv0);
        apk[fb1 + c * 4] = pack_hl4(acc[2*c][2] * inv1, acc[2*c][3] * inv1,
                                    acc[2*c+1][2] * inv1, acc[2*c+1][3] * inv1);
    }
}

// ---------------------------------------------------------------------------
// Launch
// ---------------------------------------------------------------------------
extern "C" void kernel_launch(void* const* d_in, const int* in_sizes, int n_in,
                              void* d_out, int out_size)
{
    const float*         x        = (const float*)d_in[0];
    const unsigned char* mask     = (const unsigned char*)d_in[1];
    const float*         wq_down  = (const float*)d_in[2];
    const float*         bq_down  = (const float*)d_in[3];
    const float*         gq_ln    = (const float*)d_in[4];
    const float*         bq_ln    = (const float*)d_in[5];
    const float*         wq_up    = (const float*)d_in[6];
    const float*         bq_up    = (const float*)d_in[7];
    const float*         wkv_down = (const float*)d_in[8];
    const float*         bkv_down = (const float*)d_in[9];
    const float*         gkv_ln   = (const float*)d_in[10];
    const float*         bkv_ln   = (const float*)d_in[11];
    const float*         wkv_up   = (const float*)d_in[12];
    const float*         bkv_up   = (const float*)d_in[13];
    const float*         w_out    = (const float*)d_in[14];
    const float*         b_out    = (const float*)d_in[15];
    float* out = (float*)d_out;

    float *qlat, *qb, *kvlat, *kvb;
    float4 *wpk, *apk, *lpk, *kpk;
    float2 *vpk;
    cudaGetSymbolAddress((void**)&qlat,  g_qlat);
    cudaGetSymbolAddress((void**)&qb,    g_q);
    cudaGetSymbolAddress((void**)&kvlat, g_kvlat);
    cudaGetSymbolAddress((void**)&kvb,   g_kv);
    cudaGetSymbolAddress((void**)&wpk,   g_wpk);
    cudaGetSymbolAddress((void**)&apk,   g_apk);
    cudaGetSymbolAddress((void**)&lpk,   g_lpk);
    cudaGetSymbolAddress((void**)&kpk,   g_kpk);
    cudaGetSymbolAddress((void**)&vpk,   g_vpk);

    cudaFuncSetAttribute(attn_mma,
                         cudaFuncAttributeMaxDynamicSharedMemorySize, ATT_SMEM);
    cudaFuncSetAttribute(gemm_hp,
                         cudaFuncAttributeMaxDynamicSharedMemorySize, GEMM_SMEM);

    // ---- Q/KV down-projections ----
    {
        int tot = Mrows * Dm / 4;
        pack_act<<<tot / 256, 256>>>(x, apk, Dm, tot);
    }
    {
        int tot = (Dm / 16) * 4 * Ll;
        pack_w<<<tot / 256, 256>>>(wq_down, wpk, Ll, tot);
        gemm_hp<<<dim3(Ll / 128, Mrows / 128), 256, GEMM_SMEM>>>(
            Mrows, Ll, Dm, apk, wpk, bq_down, qlat);
        pack_w<<<tot / 256, 256>>>(wkv_down, wpk, Ll, tot);
        gemm_hp<<<dim3(Ll / 128, Mrows / 128), 256, GEMM_SMEM>>>(
            Mrows, Ll, Dm, apk, wpk, bkv_down, kvlat);
    }

    // ---- up-projections (LN fused with act packing) ----
    {
        int totw = (Ll / 16) * 4 * Dm;
        ln512_pack<<<Mrows, 256>>>(qlat, gq_ln, bq_ln, lpk);
        pack_w<<<totw / 256, 256>>>(wq_up, wpk, Dm, totw);
        gemm_hp<<<dim3(Dm / 128, Mrows / 128), 256, GEMM_SMEM>>>(
            Mrows, Dm, Ll, lpk, wpk, bq_up, qb);
        ln512_pack<<<Mrows, 256>>>(kvlat, gkv_ln, bkv_ln, lpk);
        int totw2 = (Ll / 16) * 4 * 2 * Dm;
        pack_w<<<totw2 / 256, 256>>>(wkv_up, wpk, 2 * Dm, totw2);
        gemm_hp<<<dim3(2 * Dm / 128, Mrows / 128), 256, GEMM_SMEM>>>(
            Mrows, 2 * Dm, Ll, lpk, wpk, bkv_up, kvb);
    }

    // ---- attention (emits packed out-proj operand directly) ----
    pack_kv<<<dim3(Sq / 64, Bsz * Hh), 256>>>(kvb, kpk, vpk);
    attn_mma<<<dim3(Sq / 128, Bsz * Hh), 256, ATT_SMEM>>>(qb, kpk, vpk, mask, apk);

    // ---- output projection ----
    {
        int totw = (Dm / 16) * 4 * Dm;
        pack_w<<<totw / 256, 256>>>(w_out, wpk, Dm, totw);
        gemm_hp<<<dim3(Dm / 128, Mrows / 128), 256, GEMM_SMEM>>>(
            Mrows, Dm, Dm, apk, wpk, b_out, out);
    }
}

// round 12
// speedup vs baseline: 2.5221x; 1.0834x over previous
#include <cuda_runtime.h>
#include <cuda_fp16.h>
#include <math_constants.h>
#include <cstdint>

// Problem constants
#define Bsz 2
#define Sq  2048
#define Dm  2048
#define Hh  16
#define Ll  512
#define HDm 128
#define Mrows (Bsz*Sq)      // 4096

// ---------------------------------------------------------------------------
// Scratch (static device globals — no runtime allocation allowed)
// ---------------------------------------------------------------------------
__device__ float  g_qlat [(size_t)Mrows * Ll];
__device__ float  g_q    [(size_t)Mrows * Dm];
__device__ float  g_kvlat[(size_t)Mrows * Ll];
__device__ float  g_kv   [(size_t)Mrows * 2 * Dm];
__device__ float4 g_apk  [(size_t)Mrows * Dm / 4];    // packed acts (x, attn out)
__device__ float4 g_lpkq [(size_t)Mrows * Ll / 4];    // packed latent (q path)
__device__ float4 g_lpkkv[(size_t)Mrows * Ll / 4];    // packed latent (kv path)
__device__ float4 g_kpk  [(size_t)Mrows * Dm / 4];    // packed K fragments
__device__ float2 g_vpk  [(size_t)Mrows * Dm / 4];    // packed V half2 pairs
// per-weight packed buffers (enable stream-parallel packing)
__device__ float4 g_wqd_pk [(size_t)Dm * Ll / 4];
__device__ float4 g_wkvd_pk[(size_t)Dm * Ll / 4];
__device__ float4 g_wqu_pk [(size_t)Ll * Dm / 4];
__device__ float4 g_wkvu_pk[(size_t)Ll * 2 * Dm / 4];
__device__ float4 g_wout_pk[(size_t)Dm * Dm / 4];

// ---------------------------------------------------------------------------
// Helpers
// ---------------------------------------------------------------------------
__device__ __forceinline__ uint32_t smem_u32(const void* p) {
    uint32_t a;
    asm("{ .reg .u64 t; cvta.to.shared.u64 t, %1; cvt.u32.u64 %0, t; }"
        : "=r"(a) : "l"(p));
    return a;
}
__device__ __forceinline__ void cp16(uint32_t dst, const void* src) {
    asm volatile("cp.async.cg.shared.global [%0], [%1], 16;"
                 :: "r"(dst), "l"(src) : "memory");
}
__device__ __forceinline__ float h2pack(float a, float b) {
    __half2 h = __halves2half2(__float2half_rn(a), __float2half_rn(b));
    return __uint_as_float(*(uint32_t*)&h);
}
__device__ __forceinline__ float4 pack_hl4(float a0, float a1, float a2, float a3) {
    __half h0 = __float2half_rn(a0), h1 = __float2half_rn(a1);
    __half h2 = __float2half_rn(a2), h3 = __float2half_rn(a3);
    float4 r;
    __half2 p;
    p = __halves2half2(h0, h1); r.x = __uint_as_float(*(uint32_t*)&p);
    p = __halves2half2(h2, h3); r.y = __uint_as_float(*(uint32_t*)&p);
    r.z = h2pack(a0 - __half2float(h0), a1 - __half2float(h1));
    r.w = h2pack(a2 - __half2float(h2), a3 - __half2float(h3));
    return r;
}
__device__ __forceinline__ void mma_f16(
    float c[4], uint32_t a0, uint32_t a1, uint32_t a2, uint32_t a3,
    uint32_t b0, uint32_t b1)
{
    asm volatile(
        "mma.sync.aligned.m16n8k16.row.col.f32.f16.f16.f32 "
        "{%0,%1,%2,%3}, {%4,%5,%6,%7}, {%8,%9}, {%0,%1,%2,%3};"
        : "+f"(c[0]), "+f"(c[1]), "+f"(c[2]), "+f"(c[3])
        : "r"(a0), "r"(a1), "r"(a2), "r"(a3), "r"(b0), "r"(b1));
}
#define FU(x) __float_as_uint(x)

// ---------------------------------------------------------------------------
// Pack kernels
// ---------------------------------------------------------------------------
__global__ __launch_bounds__(256) void pack_act(
    const float* __restrict__ A, float4* __restrict__ out, int K, int total)
{
    int idx = blockIdx.x * 256 + threadIdx.x;
    if (idx >= total) return;
    int lq = idx & 3, rest = idx >> 2;
    int jc = rest % (K >> 4), m = rest / (K >> 4);
    const float* base = A + (size_t)m * K + 16 * jc + 2 * lq;
    float2 a = *(const float2*)base;
    float2 b = *(const float2*)(base + 8);
    out[idx] = pack_hl4(a.x, a.y, b.x, b.y);
}
__global__ __launch_bounds__(256) void pack_w(
    const float* __restrict__ W, float4* __restrict__ out, int N, int total)
{
    int idx = blockIdx.x * 256 + threadIdx.x;
    if (idx >= total) return;
    int n = idx % N, g2 = idx / N;
    int lq = g2 & 3, jc = g2 >> 2;
    size_t k = 16 * jc + 2 * lq;
    out[idx] = pack_hl4(W[k * N + n] * 256.f, W[(k + 1) * N + n] * 256.f,
                        W[(k + 8) * N + n] * 256.f, W[(k + 9) * N + n] * 256.f);
}
// KV pack: one block per (kt, bh) tile.
__global__ __launch_bounds__(256) void pack_kv(
    const float* __restrict__ kv, float4* __restrict__ kpk, float2* __restrict__ vpk)
{
    __shared__ float Kr[64 * 132];
    const int kt = blockIdx.x, bh = blockIdx.y;
    const int b = bh >> 4, h = bh & 15;
    const float* Kp = kv + (size_t)b * Sq * 2 * Dm + (size_t)h * HDm
                         + (size_t)kt * 64 * 2 * Dm;
    const float* Vp = Kp + Dm;
    const uint32_t smu = smem_u32(Kr);
    const int tid = threadIdx.x;

    #pragma unroll
    for (int t = 0; t < 8; t++) {
        int idx = tid + t * 256;
        int row = idx >> 5, c4 = (idx & 31) * 4;
        cp16(smu + (row * 132 + c4) * 4, Kp + (size_t)row * 2 * Dm + c4);
    }
    asm volatile("cp.async.commit_group;" ::: "memory");
    asm volatile("cp.async.wait_group 0;" ::: "memory");
    __syncthreads();

    const size_t obase = (size_t)(bh * 32 + kt) * 2048;
    #pragma unroll
    for (int t = 0; t < 8; t++) {
        int idx = tid + t * 256;
        int n = idx & 63, grp = idx >> 6;
        int c = grp >> 2, lqq = grp & 3;
        const float* kr = Kr + n * 132 + c * 16 + 2 * lqq;
        kpk[obase + grp * 64 + n] = pack_hl4(kr[0], kr[1], kr[8], kr[9]);
    }
    #pragma unroll
    for (int t = 0; t < 8; t++) {
        int idx = tid + t * 256;
        int d = idx & 127, grp = idx >> 7;
        int c = grp >> 2, lqq = grp & 3;
        const float* vr = Vp + (size_t)(c * 16 + 2 * lqq) * 2 * Dm + d;
        vpk[obase + grp * 128 + d] =
            make_float2(h2pack(vr[0], vr[2 * Dm]),
                        h2pack(vr[8 * 2 * Dm], vr[9 * 2 * Dm]));
    }
}

// ---------------------------------------------------------------------------
// fp16 3-term GEMM on pre-packed operands. CTA 128x128, BK=16, 256 threads,
// 3-stage cp.async pipeline, one syncthreads per chunk. 2 CTAs/SM.
// ---------------------------------------------------------------------------
#define GSTG 1032            // float4 per stage: 512 A + 520 B (stride 130)
#define GEMM_SMEM (3 * GSTG * 16)

__global__ __launch_bounds__(256, 2) void gemm_hp(
    int M, int N, int K,
    const float4* __restrict__ Apk,
    const float4* __restrict__ Bpk,
    const float* __restrict__ bias,
    float* __restrict__ C)
{
    extern __shared__ float4 gsm[];
    const uint32_t smu = smem_u32(gsm);
    const int tid = threadIdx.x;
    const int wid = tid >> 5, lid = tid & 31;
    const int g = lid >> 2, lq = lid & 3;
    const int m0 = blockIdx.y * 128, n0 = blockIdx.x * 128;
    const int warp_m = (wid & 1) * 64;
    const int warp_n = (wid >> 1) * 32;
    const int nc = K >> 4, K16 = K >> 4;

    float acc[4][4][4];
    #pragma unroll
    for (int mt = 0; mt < 4; mt++)
        #pragma unroll
        for (int nt = 0; nt < 4; nt++)
            #pragma unroll
            for (int e = 0; e < 4; e++) acc[mt][nt][e] = 0.f;

    auto load_tile = [&](int c, int s) {
        const uint32_t sb = smu + s * (GSTG * 16);
        #pragma unroll
        for (int t = 0; t < 2; t++) {
            int idx = tid + t * 256;
            int m = idx >> 2, j = idx & 3;
            cp16(sb + ((m * 4 + j) << 4),
                 Apk + ((size_t)(m0 + m) * K16 + c) * 4 + j);
        }
        #pragma unroll
        for (int t = 0; t < 2; t++) {
            int idx = tid + t * 256;
            int j = idx >> 7, n = idx & 127;
            cp16(sb + ((512 + j * 130 + n) << 4),
                 Bpk + (size_t)(c * 4 + j) * N + n0 + n);
        }
        asm volatile("cp.async.commit_group;" ::: "memory");
    };

    load_tile(0, 0);
    load_tile(1, 1);

    for (int c = 0; c < nc; ++c) {
        if (c + 1 < nc) { asm volatile("cp.async.wait_group 1;" ::: "memory"); }
        else            { asm volatile("cp.async.wait_group 0;" ::: "memory"); }
        __syncthreads();
        if (c + 2 < nc) load_tile(c + 2, (c + 2) % 3);

        const float4* AS_ = gsm + (c % 3) * GSTG;
        const float4* BS_ = AS_ + 512;

        uint32_t Ah[4][4], Al[4][4];
        #pragma unroll
        for (int mt = 0; mt < 4; mt++) {
            float4 fa = AS_[(warp_m + mt * 16 + g) * 4 + lq];
            float4 fb = AS_[(warp_m + mt * 16 + g + 8) * 4 + lq];
            Ah[mt][0] = FU(fa.x); Ah[mt][1] = FU(fb.x);
            Ah[mt][2] = FU(fa.y); Ah[mt][3] = FU(fb.y);
            Al[mt][0] = FU(fa.z); Al[mt][1] = FU(fb.z);
            Al[mt][2] = FU(fa.w); Al[mt][3] = FU(fb.w);
        }
        uint32_t Bh[4][2], Bl[4][2];
        #pragma unroll
        for (int nt = 0; nt < 4; nt++) {
            float4 f = BS_[lq * 130 + warp_n + nt * 8 + g];
            Bh[nt][0] = FU(f.x); Bh[nt][1] = FU(f.y);
            Bl[nt][0] = FU(f.z); Bl[nt][1] = FU(f.w);
        }
        #pragma unroll
        for (int mt = 0; mt < 4; mt++)
            #pragma unroll
            for (int nt = 0; nt < 4; nt++) {
                mma_f16(acc[mt][nt], Ah[mt][0], Ah[mt][1], Ah[mt][2], Ah[mt][3],
                        Bl[nt][0], Bl[nt][1]);
                mma_f16(acc[mt][nt], Al[mt][0], Al[mt][1], Al[mt][2], Al[mt][3],
                        Bh[nt][0], Bh[nt][1]);
                mma_f16(acc[mt][nt], Ah[mt][0], Ah[mt][1], Ah[mt][2], Ah[mt][3],
                        Bh[nt][0], Bh[nt][1]);
            }
    }

    const float s = 1.f / 256.f;
    #pragma unroll
    for (int mt = 0; mt < 4; mt++) {
        const int r0 = m0 + warp_m + mt * 16 + g;
        #pragma unroll
        for (int nt = 0; nt < 4; nt++) {
            const int col = n0 + warp_n + nt * 8 + lq * 2;
            const float2 b2 = *(const float2*)(bias + col);
            float2 o;
            o.x = acc[mt][nt][0] * s + b2.x;
            o.y = acc[mt][nt][1] * s + b2.y;
            *(float2*)(C + (size_t)r0 * N + col) = o;
            o.x = acc[mt][nt][2] * s + b2.x;
            o.y = acc[mt][nt][3] * s + b2.y;
            *(float2*)(C + (size_t)(r0 + 8) * N + col) = o;
        }
    }
}

// ---------------------------------------------------------------------------
// LayerNorm over last dim (512), emitting packed fp16 hi/lo fragments.
// ---------------------------------------------------------------------------
__global__ __launch_bounds__(256) void ln512_pack(
    const float* __restrict__ x,
    const float* __restrict__ g,
    const float* __restrict__ b,
    float4* __restrict__ out)
{
    __shared__ float row_sh[512];
    const int row = blockIdx.x;
    const float* xr = x + (size_t)row * Ll;
    const int tid = threadIdx.x;

    float v0 = xr[tid];
    float v1 = xr[tid + 256];
    float s  = v0 + v1;
    float sq = v0 * v0 + v1 * v1;

    #pragma unroll
    for (int o = 16; o > 0; o >>= 1) {
        s  += __shfl_xor_sync(0xffffffffu, s,  o);
        sq += __shfl_xor_sync(0xffffffffu, sq, o);
    }
    __shared__ float ss[8], ssq[8];
    __shared__ float mean_sh, inv_sh;
    const int w = tid >> 5;
    if ((tid & 31) == 0) { ss[w] = s; ssq[w] = sq; }
    __syncthreads();
    if (tid == 0) {
        float S = 0.f, SQ = 0.f;
        #pragma unroll
        for (int i = 0; i < 8; i++) { S += ss[i]; SQ += ssq[i]; }
        float m = S * (1.f / Ll);
        float var = SQ * (1.f / Ll) - m * m;
        mean_sh = m;
        inv_sh = rsqrtf(var + 1e-5f);
    }
    __syncthreads();
    const float m = mean_sh, inv = inv_sh;
    row_sh[tid]       = (v0 - m) * inv * g[tid]       + b[tid];
    row_sh[tid + 256] = (v1 - m) * inv * g[tid + 256] + b[tid + 256];
    __syncthreads();
    if (tid < 128) {
        int jc = tid >> 2, lq = tid & 3;
        const float* p = row_sh + 16 * jc + 2 * lq;
        out[(size_t)row * 128 + tid] = pack_hl4(p[0], p[1], p[8], p[9]);
    }
}

// ---------------------------------------------------------------------------
// Flash attention on pre-packed K/V; output written as packed apk fragments
// (pack_act K=2048 layout: row stride 512 float4).
// ---------------------------------------------------------------------------
#define STG_F  12672                 // floats per stage: K 8448 + V 4224
#define KS_F(s) ((s) * STG_F)
#define VS_F(s) ((s) * STG_F + 8448)
#define P_F    38016
#define MASK_B 172544                // bytes
#define ATT_SMEM 172736

__global__ __launch_bounds__(256, 1) void attn_mma(
    const float* __restrict__ q,
    const float4* __restrict__ kpk,
    const float2* __restrict__ vpk,
    const unsigned char* __restrict__ mask,
    float4* __restrict__ apk)
{
    extern __shared__ float sm[];
    unsigned char* smb = (unsigned char*)sm;

    const int bh = blockIdx.y;
    const int b = bh >> 4, h = bh & 15;
    const int qb = gridDim.x - 1 - blockIdx.x;   // heavy blocks first
    const int q0 = qb * 128;
    const int ktmax = 2 * qb + 1;

    const int tid = threadIdx.x;
    const int wid = tid >> 5, lid = tid & 31;
    const int g = lid >> 2, lq = lid & 3;
    const int warp_m = wid * 16;

    const float* Qp = q + (size_t)b * Sq * Dm + (size_t)h * HDm;
    const unsigned char* mp = mask + (size_t)b * Sq;

    const uint32_t smu = smem_u32(sm);

    // ---- stage Q raw (overlaps stage buffers; done before any load_kv) ----
    #pragma unroll
    for (int t = 0; t < 16; t++) {
        int idx = tid + t * 256;
        int row = idx >> 5, c4 = (idx & 31) << 2;
        cp16(smu + (row * 132 + c4) * 4, Qp + (size_t)(q0 + row) * Dm + c4);
    }
    asm volatile("cp.async.commit_group;" ::: "memory");
    asm volatile("cp.async.wait_group 0;" ::: "memory");
    __syncthreads();

    uint32_t Qh[8][4], Ql[8][4];
    #pragma unroll
    for (int c = 0; c < 8; c++)
        #pragma unroll
        for (int e = 0; e < 4; e++) {
            int row = warp_m + g + (e & 1) * 8;
            int col = c * 16 + 2 * lq + (e >> 1) * 8;
            float a0 = sm[row * 132 + col];
            float a1 = sm[row * 132 + col + 1];
            __half h0 = __float2half_rn(a0), h1 = __float2half_rn(a1);
            __half2 hp = __halves2half2(h0, h1);
            Qh[c][e] = *(uint32_t*)&hp;
            Ql[c][e] = FU(h2pack(a0 - __half2float(h0), a1 - __half2float(h1)));
        }
    __syncthreads();

    auto load_kv = [&](int kt, int s) {
        const float4* kg = kpk + (size_t)(bh * 32 + kt) * 2048;
        const float2* vg = vpk + (size_t)(bh * 32 + kt) * 2048;
        #pragma unroll
        for (int t = 0; t < 8; t++) {
            int idx = tid + t * 256;
            int r = idx >> 6, n = idx & 63;
            cp16(smu + KS_F(s) * 4 + (r * 66 + n) * 16, kg + r * 64 + n);
        }
        #pragma unroll
        for (int t = 0; t < 4; t++) {
            int idx = tid + t * 256;
            int r = idx >> 6, dd = idx & 63;
            cp16(smu + VS_F(s) * 4 + (r * 132 + 2 * dd) * 8, vg + r * 128 + 2 * dd);
        }
        if (tid < 4)
            cp16(smu + MASK_B + s * 64 + tid * 16, mp + kt * 64 + tid * 16);
        asm volatile("cp.async.commit_group;" ::: "memory");
    };

    load_kv(0, 0);
    load_kv(1, 1);

    const int row0 = q0 + warp_m + g;
    const int row1 = row0 + 8;
    float m_i0 = -CUDART_INF_F, m_i1 = -CUDART_INF_F;
    float l0 = 0.f, l1 = 0.f;
    float acc[16][4];
    #pragma unroll
    for (int nt = 0; nt < 16; nt++)
        #pragma unroll
        for (int e = 0; e < 4; e++) acc[nt][e] = 0.f;

    const float scale = 0.08838834764831845f;    // 1/sqrt(128)
    float2* pf2 = (float2*)(sm + P_F);

    for (int kt = 0; kt <= ktmax; ++kt) {
        const int st = kt % 3;
        if (kt < ktmax) { asm volatile("cp.async.wait_group 1;" ::: "memory"); }
        else            { asm volatile("cp.async.wait_group 0;" ::: "memory"); }
        __syncthreads();
        if (kt + 2 <= ktmax) load_kv(kt + 2, (kt + 2) % 3);

        const float4* kf4 = (const float4*)(sm + KS_F(st));
        const float2* vf2 = (const float2*)(sm + VS_F(st));
        const unsigned char* mk = smb + MASK_B + st * 64;

        // ---- scores: S = Q @ K^T  (3-term fp16) ----
        float sc[8][4];
        #pragma unroll
        for (int nt = 0; nt < 8; nt++)
            #pragma unroll
            for (int e = 0; e < 4; e++) sc[nt][e] = 0.f;

        #pragma unroll 4
        for (int c = 0; c < 8; c++) {
            const float4* kp_ = kf4 + (c * 4 + lq) * 66;
            #pragma unroll
            for (int nt = 0; nt < 8; nt++) {
                float4 kk = kp_[nt * 8 + g];
                mma_f16(sc[nt], Qh[c][0], Qh[c][1], Qh[c][2], Qh[c][3],
                        FU(kk.z), FU(kk.w));
                mma_f16(sc[nt], Ql[c][0], Ql[c][1], Ql[c][2], Ql[c][3],
                        FU(kk.x), FU(kk.y));
                mma_f16(sc[nt], Qh[c][0], Qh[c][1], Qh[c][2], Qh[c][3],
                        FU(kk.x), FU(kk.y));
            }
        }

        // ---- mask + scale + row max ----
        const bool diag = (kt >= 2 * qb);
        float m0 = -CUDART_INF_F, m1 = -CUDART_INF_F;
        #pragma unroll
        for (int nt = 0; nt < 8; nt++) {
            const int cl = nt * 8 + 2 * lq;
            const int cg = kt * 64 + cl;
            const bool pk0 = mk[cl] != 0, pk1 = mk[cl + 1] != 0;
            float v0 = (pk0 || (diag && cg     > row0)) ? -CUDART_INF_F : sc[nt][0] * scale;
            float v1 = (pk1 || (diag && cg + 1 > row0)) ? -CUDART_INF_F : sc[nt][1] * scale;
            float v2 = (pk0 || (diag && cg     > row1)) ? -CUDART_INF_F : sc[nt][2] * scale;
            float v3 = (pk1 || (diag && cg + 1 > row1)) ? -CUDART_INF_F : sc[nt][3] * scale;
            sc[nt][0] = v0; sc[nt][1] = v1; sc[nt][2] = v2; sc[nt][3] = v3;
            m0 = fmaxf(m0, fmaxf(v0, v1));
            m1 = fmaxf(m1, fmaxf(v2, v3));
        }
        m0 = fmaxf(m0, __shfl_xor_sync(0xffffffffu, m0, 1));
        m0 = fmaxf(m0, __shfl_xor_sync(0xffffffffu, m0, 2));
        m1 = fmaxf(m1, __shfl_xor_sync(0xffffffffu, m1, 1));
        m1 = fmaxf(m1, __shfl_xor_sync(0xffffffffu, m1, 2));

        const float mn0 = fmaxf(m_i0, m0), mn1 = fmaxf(m_i1, m1);
        const float corr0 = (mn0 == -CUDART_INF_F) ? 1.f : __expf(m_i0 - mn0);
        const float corr1 = (mn1 == -CUDART_INF_F) ? 1.f : __expf(m_i1 - mn1);
        const float base0 = (mn0 == -CUDART_INF_F) ? 0.f : mn0;
        const float base1 = (mn1 == -CUDART_INF_F) ? 0.f : mn1;

        float psum0 = 0.f, psum1 = 0.f;
        uint32_t ptop_prev = 0, pbot_prev = 0;
        __syncwarp();
        #pragma unroll
        for (int nt = 0; nt < 8; nt++) {
            float p0 = (sc[nt][0] == -CUDART_INF_F) ? 0.f : __expf(sc[nt][0] - base0);
            float p1 = (sc[nt][1] == -CUDART_INF_F) ? 0.f : __expf(sc[nt][1] - base0);
            float p2 = (sc[nt][2] == -CUDART_INF_F) ? 0.f : __expf(sc[nt][2] - base1);
            float p3 = (sc[nt][3] == -CUDART_INF_F) ? 0.f : __expf(sc[nt][3] - base1);
            psum0 += p0 + p1;
            psum1 += p2 + p3;
            uint32_t top = FU(h2pack(p0, p1));
            uint32_t bot = FU(h2pack(p2, p3));
            if (nt & 1) {
                const int c = nt >> 1;
                pf2[(warp_m + g) * 20 + c * 4 + lq] =
                    make_float2(__uint_as_float(ptop_prev), __uint_as_float(top));
                pf2[(warp_m + g + 8) * 20 + c * 4 + lq] =
                    make_float2(__uint_as_float(pbot_prev), __uint_as_float(bot));
            } else { ptop_prev = top; pbot_prev = bot; }
        }
        psum0 += __shfl_xor_sync(0xffffffffu, psum0, 1);
        psum0 += __shfl_xor_sync(0xffffffffu, psum0, 2);
        psum1 += __shfl_xor_sync(0xffffffffu, psum1, 1);
        psum1 += __shfl_xor_sync(0xffffffffu, psum1, 2);
        l0 = l0 * corr0 + psum0;
        l1 = l1 * corr1 + psum1;
        m_i0 = mn0; m_i1 = mn1;

        #pragma unroll
        for (int nt = 0; nt < 16; nt++) {
            acc[nt][0] *= corr0; acc[nt][1] *= corr0;
            acc[nt][2] *= corr1; acc[nt][3] *= corr1;
        }
        __syncwarp();

        // ---- O += P @ V  (1x fp16, packed) ----
        #pragma unroll
        for (int c = 0; c < 4; c++) {
            float2 pa = pf2[(warp_m + g) * 20 + c * 4 + lq];
            float2 pb = pf2[(warp_m + g + 8) * 20 + c * 4 + lq];
            uint32_t A0 = FU(pa.x), A1 = FU(pb.x), A2 = FU(pa.y), A3 = FU(pb.y);
            const float2* vp = vf2 + (c * 4 + lq) * 132;
            #pragma unroll
            for (int nt = 0; nt < 16; nt++) {
                float2 vv = vp[nt * 8 + g];
                mma_f16(acc[nt], A0, A1, A2, A3, FU(vv.x), FU(vv.y));
            }
        }
    }

    // ---- epilogue: packed fragments (row stride 512 float4) ----
    const float inv0 = (l0 > 0.f) ? (1.f / l0) : 0.f;
    const float inv1 = (l1 > 0.f) ? (1.f / l1) : 0.f;
    const size_t fb0 = (size_t)(b * Sq + row0) * 512 + (h * 8) * 4 + lq;
    const size_t fb1 = (size_t)(b * Sq + row1) * 512 + (h * 8) * 4 + lq;
    #pragma unroll
    for (int c = 0; c < 8; c++) {
        apk[fb0 + c * 4] = pack_hl4(acc[2*c][0] * inv0, acc[2*c][1] * inv0,
                                    acc[2*c+1][0] * inv0, acc[2*c+1][1] * inv0);
        apk[fb1 + c * 4] = pack_hl4(acc[2*c][2] * inv1, acc[2*c][3] * inv1,
                                    acc[2*c+1][2] * inv1, acc[2*c+1][3] * inv1);
    }
}

// ---------------------------------------------------------------------------
// Launch — dependency DAG across streams (graph-capture-safe event fork/join)
// ---------------------------------------------------------------------------
extern "C" void kernel_launch(void* const* d_in, const int* in_sizes, int n_in,
                              void* d_out, int out_size)
{
    const float*         x        = (const float*)d_in[0];
    const unsigned char* mask     = (const unsigned char*)d_in[1];
    const float*         wq_down  = (const float*)d_in[2];
    const float*         bq_down  = (const float*)d_in[3];
    const float*         gq_ln    = (const float*)d_in[4];
    const float*         bq_ln    = (const float*)d_in[5];
    const float*         wq_up    = (const float*)d_in[6];
    const float*         bq_up    = (const float*)d_in[7];
    const float*         wkv_down = (const float*)d_in[8];
    const float*         bkv_down = (const float*)d_in[9];
    const float*         gkv_ln   = (const float*)d_in[10];
    const float*         bkv_ln   = (const float*)d_in[11];
    const float*         wkv_up   = (const float*)d_in[12];
    const float*         bkv_up   = (const float*)d_in[13];
    const float*         w_out    = (const float*)d_in[14];
    const float*         b_out    = (const float*)d_in[15];
    float* out = (float*)d_out;

    float *qlat, *qb, *kvlat, *kvb;
    float4 *apk, *lpkq, *lpkkv, *kpk, *wqd, *wkvd, *wqu, *wkvu, *wout;
    float2 *vpk;
    cudaGetSymbolAddress((void**)&qlat,  g_qlat);
    cudaGetSymbolAddress((void**)&qb,    g_q);
    cudaGetSymbolAddress((void**)&kvlat, g_kvlat);
    cudaGetSymbolAddress((void**)&kvb,   g_kv);
    cudaGetSymbolAddress((void**)&apk,   g_apk);
    cudaGetSymbolAddress((void**)&lpkq,  g_lpkq);
    cudaGetSymbolAddress((void**)&lpkkv, g_lpkkv);
    cudaGetSymbolAddress((void**)&kpk,   g_kpk);
    cudaGetSymbolAddress((void**)&vpk,   g_vpk);
    cudaGetSymbolAddress((void**)&wqd,   g_wqd_pk);
    cudaGetSymbolAddress((void**)&wkvd,  g_wkvd_pk);
    cudaGetSymbolAddress((void**)&wqu,   g_wqu_pk);
    cudaGetSymbolAddress((void**)&wkvu,  g_wkvu_pk);
    cudaGetSymbolAddress((void**)&wout,  g_wout_pk);

    cudaFuncSetAttribute(attn_mma,
                         cudaFuncAttributeMaxDynamicSharedMemorySize, ATT_SMEM);
    cudaFuncSetAttribute(gemm_hp,
                         cudaFuncAttributeMaxDynamicSharedMemorySize, GEMM_SMEM);

    // streams / events (created once; safe — no device allocation)
    static cudaStream_t sA = nullptr, sB = nullptr, sC = nullptr;
    static cudaEvent_t eRoot, eApk, eWqU, eWkvU, eWout, eQb, eKV;
    if (!sA) {
        cudaStreamCreateWithFlags(&sA, cudaStreamNonBlocking);
        cudaStreamCreateWithFlags(&sB, cudaStreamNonBlocking);
        cudaStreamCreateWithFlags(&sC, cudaStreamNonBlocking);
        cudaEventCreateWithFlags(&eRoot, cudaEventDisableTiming);
        cudaEventCreateWithFlags(&eApk,  cudaEventDisableTiming);
        cudaEventCreateWithFlags(&eWqU,  cudaEventDisableTiming);
        cudaEventCreateWithFlags(&eWkvU, cudaEventDisableTiming);
        cudaEventCreateWithFlags(&eWout, cudaEventDisableTiming);
        cudaEventCreateWithFlags(&eQb,   cudaEventDisableTiming);
        cudaEventCreateWithFlags(&eKV,   cudaEventDisableTiming);
    }

    // fork
    cudaEventRecord(eRoot, 0);
    cudaStreamWaitEvent(sA, eRoot, 0);
    cudaStreamWaitEvent(sB, eRoot, 0);
    cudaStreamWaitEvent(sC, eRoot, 0);

    // stream 0: pack input activations
    {
        int tot = Mrows * Dm / 4;
        pack_act<<<tot / 256, 256, 0, 0>>>(x, apk, Dm, tot);
        cudaEventRecord(eApk, 0);
    }
    // sC: late weight packs (hidden under down-gemms)
    {
        int t1 = (Ll / 16) * 4 * Dm;
        pack_w<<<t1 / 256, 256, 0, sC>>>(wq_up, wqu, Dm, t1);
        cudaEventRecord(eWqU, sC);
        int t2 = (Ll / 16) * 4 * 2 * Dm;
        pack_w<<<t2 / 256, 256, 0, sC>>>(wkv_up, wkvu, 2 * Dm, t2);
        cudaEventRecord(eWkvU, sC);
        int t3 = (Dm / 16) * 4 * Dm;
        pack_w<<<t3 / 256, 256, 0, sC>>>(w_out, wout, Dm, t3);
        cudaEventRecord(eWout, sC);
    }
    const int totd = (Dm / 16) * 4 * Ll;
    // sA: Q path
    pack_w<<<totd / 256, 256, 0, sA>>>(wq_down, wqd, Ll, totd);
    cudaStreamWaitEvent(sA, eApk, 0);
    gemm_hp<<<dim3(Ll / 128, Mrows / 128), 256, GEMM_SMEM, sA>>>(
        Mrows, Ll, Dm, apk, wqd, bq_down, qlat);
    ln512_pack<<<Mrows, 256, 0, sA>>>(qlat, gq_ln, bq_ln, lpkq);
    cudaStreamWaitEvent(sA, eWqU, 0);
    gemm_hp<<<dim3(Dm / 128, Mrows / 128), 256, GEMM_SMEM, sA>>>(
        Mrows, Dm, Ll, lpkq, wqu, bq_up, qb);
    cudaEventRecord(eQb, sA);
    // sB: KV path
    pack_w<<<totd / 256, 256, 0, sB>>>(wkv_down, wkvd, Ll, totd);
    cudaStreamWaitEvent(sB, eApk, 0);
    gemm_hp<<<dim3(Ll / 128, Mrows / 128), 256, GEMM_SMEM, sB>>>(
        Mrows, Ll, Dm, apk, wkvd, bkv_down, kvlat);
    ln512_pack<<<Mrows, 256, 0, sB>>>(kvlat, gkv_ln, bkv_ln, lpkkv);
    cudaStreamWaitEvent(sB, eWkvU, 0);
    gemm_hp<<<dim3(2 * Dm / 128, Mrows / 128), 256, GEMM_SMEM, sB>>>(
        Mrows, 2 * Dm, Ll, lpkkv, wkvu, bkv_up, kvb);
    pack_kv<<<dim3(Sq / 64, Bsz * Hh), 256, 0, sB>>>(kvb, kpk, vpk);
    cudaEventRecord(eKV, sB);

    // join on stream 0: attention + output projection
    cudaStreamWaitEvent(0, eQb, 0);
    cudaStreamWaitEvent(0, eKV, 0);
    attn_mma<<<dim3(Sq / 128, Bsz * Hh), 256, ATT_SMEM, 0>>>(qb, kpk, vpk, mask, apk);
    cudaStreamWaitEvent(0, eWout, 0);
    gemm_hp<<<dim3(Dm / 128, Mrows / 128), 256, GEMM_SMEM, 0>>>(
        Mrows, Dm, Dm, apk, wout, b_out, out);
}

// round 13
// speedup vs baseline: 2.8700x; 1.1380x over previous
#include <cuda_runtime.h>
#include <cuda_fp16.h>
#include <math_constants.h>
#include <cstdint>

// Problem constants
#define Bsz 2
#define Sq  2048
#define Dm  2048
#define Hh  16
#define Ll  512
#define HDm 128
#define Mrows (Bsz*Sq)      // 4096

// ---------------------------------------------------------------------------
// Scratch (static device globals — no runtime allocation allowed)
// ---------------------------------------------------------------------------
__device__ float  g_qlat [(size_t)Mrows * Ll];
__device__ float  g_q    [(size_t)Mrows * Dm];
__device__ float  g_kvlat[(size_t)Mrows * Ll];
__device__ float  g_kv   [(size_t)Mrows * 2 * Dm];
__device__ float4 g_apk  [(size_t)Mrows * Dm / 4];    // packed acts (x, attn out)
__device__ float4 g_lpkq [(size_t)Mrows * Ll / 4];    // packed latent (q path)
__device__ float4 g_lpkkv[(size_t)Mrows * Ll / 4];    // packed latent (kv path)
__device__ float4 g_kpk  [(size_t)Mrows * Dm / 4];    // packed K fragments
__device__ float2 g_vpk  [(size_t)Mrows * Dm / 4];    // packed V half2 pairs
// per-weight packed buffers (enable stream-parallel packing)
__device__ float4 g_wqd_pk [(size_t)Dm * Ll / 4];
__device__ float4 g_wkvd_pk[(size_t)Dm * Ll / 4];
__device__ float4 g_wqu_pk [(size_t)Ll * Dm / 4];
__device__ float4 g_wkvu_pk[(size_t)Ll * 2 * Dm / 4];
__device__ float4 g_wout_pk[(size_t)Dm * Dm / 4];

// ---------------------------------------------------------------------------
// Helpers
// ---------------------------------------------------------------------------
__device__ __forceinline__ uint32_t smem_u32(const void* p) {
    uint32_t a;
    asm("{ .reg .u64 t; cvta.to.shared.u64 t, %1; cvt.u32.u64 %0, t; }"
        : "=r"(a) : "l"(p));
    return a;
}
__device__ __forceinline__ void cp16(uint32_t dst, const void* src) {
    asm volatile("cp.async.cg.shared.global [%0], [%1], 16;"
                 :: "r"(dst), "l"(src) : "memory");
}
__device__ __forceinline__ float fast_exp2(float x) {
    float r;
    asm("ex2.approx.f32 %0, %1;" : "=f"(r) : "f"(x));
    return r;
}
__device__ __forceinline__ float h2pack(float a, float b) {
    __half2 h = __halves2half2(__float2half_rn(a), __float2half_rn(b));
    return __uint_as_float(*(uint32_t*)&h);
}
__device__ __forceinline__ float4 pack_hl4(float a0, float a1, float a2, float a3) {
    __half h0 = __float2half_rn(a0), h1 = __float2half_rn(a1);
    __half h2 = __float2half_rn(a2), h3 = __float2half_rn(a3);
    float4 r;
    __half2 p;
    p = __halves2half2(h0, h1); r.x = __uint_as_float(*(uint32_t*)&p);
    p = __halves2half2(h2, h3); r.y = __uint_as_float(*(uint32_t*)&p);
    r.z = h2pack(a0 - __half2float(h0), a1 - __half2float(h1));
    r.w = h2pack(a2 - __half2float(h2), a3 - __half2float(h3));
    return r;
}
__device__ __forceinline__ void mma_f16(
    float c[4], uint32_t a0, uint32_t a1, uint32_t a2, uint32_t a3,
    uint32_t b0, uint32_t b1)
{
    asm volatile(
        "mma.sync.aligned.m16n8k16.row.col.f32.f16.f16.f32 "
        "{%0,%1,%2,%3}, {%4,%5,%6,%7}, {%8,%9}, {%0,%1,%2,%3};"
        : "+f"(c[0]), "+f"(c[1]), "+f"(c[2]), "+f"(c[3])
        : "r"(a0), "r"(a1), "r"(a2), "r"(a3), "r"(b0), "r"(b1));
}
#define FU(x) __float_as_uint(x)

// ---------------------------------------------------------------------------
// Pack kernels
// ---------------------------------------------------------------------------
__global__ __launch_bounds__(256) void pack_act(
    const float* __restrict__ A, float4* __restrict__ out, int K, int total)
{
    int idx = blockIdx.x * 256 + threadIdx.x;
    if (idx >= total) return;
    int lq = idx & 3, rest = idx >> 2;
    int jc = rest % (K >> 4), m = rest / (K >> 4);
    const float* base = A + (size_t)m * K + 16 * jc + 2 * lq;
    float2 a = *(const float2*)base;
    float2 b = *(const float2*)(base + 8);
    out[idx] = pack_hl4(a.x, a.y, b.x, b.y);
}
__global__ __launch_bounds__(256) void pack_w(
    const float* __restrict__ W, float4* __restrict__ out, int N, int total)
{
    int idx = blockIdx.x * 256 + threadIdx.x;
    if (idx >= total) return;
    int n = idx % N, g2 = idx / N;
    int lq = g2 & 3, jc = g2 >> 2;
    size_t k = 16 * jc + 2 * lq;
    out[idx] = pack_hl4(W[k * N + n] * 256.f, W[(k + 1) * N + n] * 256.f,
                        W[(k + 8) * N + n] * 256.f, W[(k + 9) * N + n] * 256.f);
}
// KV pack: one block per (kt, bh) tile.
__global__ __launch_bounds__(256) void pack_kv(
    const float* __restrict__ kv, float4* __restrict__ kpk, float2* __restrict__ vpk)
{
    __shared__ float Kr[64 * 132];
    const int kt = blockIdx.x, bh = blockIdx.y;
    const int b = bh >> 4, h = bh & 15;
    const float* Kp = kv + (size_t)b * Sq * 2 * Dm + (size_t)h * HDm
                         + (size_t)kt * 64 * 2 * Dm;
    const float* Vp = Kp + Dm;
    const uint32_t smu = smem_u32(Kr);
    const int tid = threadIdx.x;

    #pragma unroll
    for (int t = 0; t < 8; t++) {
        int idx = tid + t * 256;
        int row = idx >> 5, c4 = (idx & 31) * 4;
        cp16(smu + (row * 132 + c4) * 4, Kp + (size_t)row * 2 * Dm + c4);
    }
    asm volatile("cp.async.commit_group;" ::: "memory");
    asm volatile("cp.async.wait_group 0;" ::: "memory");
    __syncthreads();

    const size_t obase = (size_t)(bh * 32 + kt) * 2048;
    #pragma unroll
    for (int t = 0; t < 8; t++) {
        int idx = tid + t * 256;
        int n = idx & 63, grp = idx >> 6;
        int c = grp >> 2, lqq = grp & 3;
        const float* kr = Kr + n * 132 + c * 16 + 2 * lqq;
        kpk[obase + grp * 64 + n] = pack_hl4(kr[0], kr[1], kr[8], kr[9]);
    }
    #pragma unroll
    for (int t = 0; t < 8; t++) {
        int idx = tid + t * 256;
        int d = idx & 127, grp = idx >> 7;
        int c = grp >> 2, lqq = grp & 3;
        const float* vr = Vp + (size_t)(c * 16 + 2 * lqq) * 2 * Dm + d;
        vpk[obase + grp * 128 + d] =
            make_float2(h2pack(vr[0], vr[2 * Dm]),
                        h2pack(vr[8 * 2 * Dm], vr[9 * 2 * Dm]));
    }
}

// ---------------------------------------------------------------------------
// fp16 GEMM on pre-packed operands. FULL3: 3-term Markidis (hh+lh+hl);
// else 2-term (hh+hl — A rounded to fp16, exact-split B).
// CTA 128x128, BK=16, 256 threads, 3-stage cp.async pipeline, 2 CTAs/SM.
// ---------------------------------------------------------------------------
#define GSTG 1032            // float4 per stage: 512 A + 520 B (stride 130)
#define GEMM_SMEM (3 * GSTG * 16)

template<bool FULL3>
__global__ __launch_bounds__(256, 2) void gemm_hp(
    int M, int N, int K,
    const float4* __restrict__ Apk,
    const float4* __restrict__ Bpk,
    const float* __restrict__ bias,
    float* __restrict__ C)
{
    extern __shared__ float4 gsm[];
    const uint32_t smu = smem_u32(gsm);
    const int tid = threadIdx.x;
    const int wid = tid >> 5, lid = tid & 31;
    const int g = lid >> 2, lq = lid & 3;
    const int m0 = blockIdx.y * 128, n0 = blockIdx.x * 128;
    const int warp_m = (wid & 1) * 64;
    const int warp_n = (wid >> 1) * 32;
    const int nc = K >> 4, K16 = K >> 4;

    float acc[4][4][4];
    #pragma unroll
    for (int mt = 0; mt < 4; mt++)
        #pragma unroll
        for (int nt = 0; nt < 4; nt++)
            #pragma unroll
            for (int e = 0; e < 4; e++) acc[mt][nt][e] = 0.f;

    auto load_tile = [&](int c, int s) {
        const uint32_t sb = smu + s * (GSTG * 16);
        #pragma unroll
        for (int t = 0; t < 2; t++) {
            int idx = tid + t * 256;
            int m = idx >> 2, j = idx & 3;
            cp16(sb + ((m * 4 + j) << 4),
                 Apk + ((size_t)(m0 + m) * K16 + c) * 4 + j);
        }
        #pragma unroll
        for (int t = 0; t < 2; t++) {
            int idx = tid + t * 256;
            int j = idx >> 7, n = idx & 127;
            cp16(sb + ((512 + j * 130 + n) << 4),
                 Bpk + (size_t)(c * 4 + j) * N + n0 + n);
        }
        asm volatile("cp.async.commit_group;" ::: "memory");
    };

    load_tile(0, 0);
    load_tile(1, 1);

    for (int c = 0; c < nc; ++c) {
        if (c + 1 < nc) { asm volatile("cp.async.wait_group 1;" ::: "memory"); }
        else            { asm volatile("cp.async.wait_group 0;" ::: "memory"); }
        __syncthreads();
        if (c + 2 < nc) load_tile(c + 2, (c + 2) % 3);

        const float4* AS_ = gsm + (c % 3) * GSTG;
        const float4* BS_ = AS_ + 512;

        uint32_t Ah[4][4], Al[4][4];
        #pragma unroll
        for (int mt = 0; mt < 4; mt++) {
            float4 fa = AS_[(warp_m + mt * 16 + g) * 4 + lq];
            float4 fb = AS_[(warp_m + mt * 16 + g + 8) * 4 + lq];
            Ah[mt][0] = FU(fa.x); Ah[mt][1] = FU(fb.x);
            Ah[mt][2] = FU(fa.y); Ah[mt][3] = FU(fb.y);
            if (FULL3) {
                Al[mt][0] = FU(fa.z); Al[mt][1] = FU(fb.z);
                Al[mt][2] = FU(fa.w); Al[mt][3] = FU(fb.w);
            }
        }
        uint32_t Bh[4][2], Bl[4][2];
        #pragma unroll
        for (int nt = 0; nt < 4; nt++) {
            float4 f = BS_[lq * 130 + warp_n + nt * 8 + g];
            Bh[nt][0] = FU(f.x); Bh[nt][1] = FU(f.y);
            Bl[nt][0] = FU(f.z); Bl[nt][1] = FU(f.w);
        }
        #pragma unroll
        for (int mt = 0; mt < 4; mt++)
            #pragma unroll
            for (int nt = 0; nt < 4; nt++) {
                mma_f16(acc[mt][nt], Ah[mt][0], Ah[mt][1], Ah[mt][2], Ah[mt][3],
                        Bl[nt][0], Bl[nt][1]);
                if (FULL3)
                    mma_f16(acc[mt][nt], Al[mt][0], Al[mt][1], Al[mt][2], Al[mt][3],
                            Bh[nt][0], Bh[nt][1]);
                mma_f16(acc[mt][nt], Ah[mt][0], Ah[mt][1], Ah[mt][2], Ah[mt][3],
                        Bh[nt][0], Bh[nt][1]);
            }
    }

    const float s = 1.f / 256.f;
    #pragma unroll
    for (int mt = 0; mt < 4; mt++) {
        const int r0 = m0 + warp_m + mt * 16 + g;
        #pragma unroll
        for (int nt = 0; nt < 4; nt++) {
            const int col = n0 + warp_n + nt * 8 + lq * 2;
            const float2 b2 = *(const float2*)(bias + col);
            float2 o;
            o.x = acc[mt][nt][0] * s + b2.x;
            o.y = acc[mt][nt][1] * s + b2.y;
            *(float2*)(C + (size_t)r0 * N + col) = o;
            o.x = acc[mt][nt][2] * s + b2.x;
            o.y = acc[mt][nt][3] * s + b2.y;
            *(float2*)(C + (size_t)(r0 + 8) * N + col) = o;
        }
    }
}

// ---------------------------------------------------------------------------
// LayerNorm over last dim (512), emitting packed fp16 hi/lo fragments.
// ---------------------------------------------------------------------------
__global__ __launch_bounds__(256) void ln512_pack(
    const float* __restrict__ x,
    const float* __restrict__ g,
    const float* __restrict__ b,
    float4* __restrict__ out)
{
    __shared__ float row_sh[512];
    const int row = blockIdx.x;
    const float* xr = x + (size_t)row * Ll;
    const int tid = threadIdx.x;

    float v0 = xr[tid];
    float v1 = xr[tid + 256];
    float s  = v0 + v1;
    float sq = v0 * v0 + v1 * v1;

    #pragma unroll
    for (int o = 16; o > 0; o >>= 1) {
        s  += __shfl_xor_sync(0xffffffffu, s,  o);
        sq += __shfl_xor_sync(0xffffffffu, sq, o);
    }
    __shared__ float ss[8], ssq[8];
    __shared__ float mean_sh, inv_sh;
    const int w = tid >> 5;
    if ((tid & 31) == 0) { ss[w] = s; ssq[w] = sq; }
    __syncthreads();
    if (tid == 0) {
        float S = 0.f, SQ = 0.f;
        #pragma unroll
        for (int i = 0; i < 8; i++) { S += ss[i]; SQ += ssq[i]; }
        float m = S * (1.f / Ll);
        float var = SQ * (1.f / Ll) - m * m;
        mean_sh = m;
        inv_sh = rsqrtf(var + 1e-5f);
    }
    __syncthreads();
    const float m = mean_sh, inv = inv_sh;
    row_sh[tid]       = (v0 - m) * inv * g[tid]       + b[tid];
    row_sh[tid + 256] = (v1 - m) * inv * g[tid + 256] + b[tid + 256];
    __syncthreads();
    if (tid < 128) {
        int jc = tid >> 2, lq = tid & 3;
        const float* p = row_sh + 16 * jc + 2 * lq;
        out[(size_t)row * 128 + tid] = pack_hl4(p[0], p[1], p[8], p[9]);
    }
}

// ---------------------------------------------------------------------------
// Flash attention on pre-packed K/V; output written as packed apk fragments
// (pack_act K=2048 layout: row stride 512 float4).
// Scores carried in log2 units (scale*log2e folded into Q); ex2.approx exp.
// ---------------------------------------------------------------------------
#define STG_F  12672                 // floats per stage: K 8448 + V 4224
#define KS_F(s) ((s) * STG_F)
#define VS_F(s) ((s) * STG_F + 8448)
#define P_F    38016
#define MASK_B 172544                // bytes
#define ATT_SMEM 172736

__global__ __launch_bounds__(256, 1) void attn_mma(
    const float* __restrict__ q,
    const float4* __restrict__ kpk,
    const float2* __restrict__ vpk,
    const unsigned char* __restrict__ mask,
    float4* __restrict__ apk)
{
    extern __shared__ float sm[];
    unsigned char* smb = (unsigned char*)sm;

    const int bh = blockIdx.y;
    const int b = bh >> 4, h = bh & 15;
    const int qb = gridDim.x - 1 - blockIdx.x;   // heavy blocks first
    const int q0 = qb * 128;
    const int ktmax = 2 * qb + 1;

    const int tid = threadIdx.x;
    const int wid = tid >> 5, lid = tid & 31;
    const int g = lid >> 2, lq = lid & 3;
    const int warp_m = wid * 16;

    const float* Qp = q + (size_t)b * Sq * Dm + (size_t)h * HDm;
    const unsigned char* mp = mask + (size_t)b * Sq;

    const uint32_t smu = smem_u32(sm);
    // 1/sqrt(128) * log2(e) folded into Q
    const float SCL2 = 0.08838834764831845f * 1.4426950408889634f;

    // ---- stage Q raw (overlaps stage buffers; done before any load_kv) ----
    #pragma unroll
    for (int t = 0; t < 16; t++) {
        int idx = tid + t * 256;
        int row = idx >> 5, c4 = (idx & 31) << 2;
        cp16(smu + (row * 132 + c4) * 4, Qp + (size_t)(q0 + row) * Dm + c4);
    }
    asm volatile("cp.async.commit_group;" ::: "memory");
    asm volatile("cp.async.wait_group 0;" ::: "memory");
    __syncthreads();

    uint32_t Qh[8][4], Ql[8][4];
    #pragma unroll
    for (int c = 0; c < 8; c++)
        #pragma unroll
        for (int e = 0; e < 4; e++) {
            int row = warp_m + g + (e & 1) * 8;
            int col = c * 16 + 2 * lq + (e >> 1) * 8;
            float a0 = sm[row * 132 + col] * SCL2;
            float a1 = sm[row * 132 + col + 1] * SCL2;
            __half h0 = __float2half_rn(a0), h1 = __float2half_rn(a1);
            __half2 hp = __halves2half2(h0, h1);
            Qh[c][e] = *(uint32_t*)&hp;
            Ql[c][e] = FU(h2pack(a0 - __half2float(h0), a1 - __half2float(h1)));
        }
    __syncthreads();

    auto load_kv = [&](int kt, int s) {
        const float4* kg = kpk + (size_t)(bh * 32 + kt) * 2048;
        const float2* vg = vpk + (size_t)(bh * 32 + kt) * 2048;
        #pragma unroll
        for (int t = 0; t < 8; t++) {
            int idx = tid + t * 256;
            int r = idx >> 6, n = idx & 63;
            cp16(smu + KS_F(s) * 4 + (r * 66 + n) * 16, kg + r * 64 + n);
        }
        #pragma unroll
        for (int t = 0; t < 4; t++) {
            int idx = tid + t * 256;
            int r = idx >> 6, dd = idx & 63;
            cp16(smu + VS_F(s) * 4 + (r * 132 + 2 * dd) * 8, vg + r * 128 + 2 * dd);
        }
        if (tid < 4)
            cp16(smu + MASK_B + s * 64 + tid * 16, mp + kt * 64 + tid * 16);
        asm volatile("cp.async.commit_group;" ::: "memory");
    };

    load_kv(0, 0);
    load_kv(1, 1);

    const int row0 = q0 + warp_m + g;
    const int row1 = row0 + 8;
    float m_i0 = -CUDART_INF_F, m_i1 = -CUDART_INF_F;
    float l0 = 0.f, l1 = 0.f;
    float acc[16][4];
    #pragma unroll
    for (int nt = 0; nt < 16; nt++)
        #pragma unroll
        for (int e = 0; e < 4; e++) acc[nt][e] = 0.f;

    float2* pf2 = (float2*)(sm + P_F);

    for (int kt = 0; kt <= ktmax; ++kt) {
        const int st = kt % 3;
        if (kt < ktmax) { asm volatile("cp.async.wait_group 1;" ::: "memory"); }
        else            { asm volatile("cp.async.wait_group 0;" ::: "memory"); }
        __syncthreads();
        if (kt + 2 <= ktmax) load_kv(kt + 2, (kt + 2) % 3);

        const float4* kf4 = (const float4*)(sm + KS_F(st));
        const float2* vf2 = (const float2*)(sm + VS_F(st));
        const unsigned char* mk = smb + MASK_B + st * 64;

        // ---- scores: S = Q @ K^T  (3-term fp16, log2 units) ----
        float sc[8][4];
        #pragma unroll
        for (int nt = 0; nt < 8; nt++)
            #pragma unroll
            for (int e = 0; e < 4; e++) sc[nt][e] = 0.f;

        #pragma unroll 4
        for (int c = 0; c < 8; c++) {
            const float4* kp_ = kf4 + (c * 4 + lq) * 66;
            #pragma unroll
            for (int nt = 0; nt < 8; nt++) {
                float4 kk = kp_[nt * 8 + g];
                mma_f16(sc[nt], Qh[c][0], Qh[c][1], Qh[c][2], Qh[c][3],
                        FU(kk.z), FU(kk.w));
                mma_f16(sc[nt], Ql[c][0], Ql[c][1], Ql[c][2], Ql[c][3],
                        FU(kk.x), FU(kk.y));
                mma_f16(sc[nt], Qh[c][0], Qh[c][1], Qh[c][2], Qh[c][3],
                        FU(kk.x), FU(kk.y));
            }
        }

        // ---- mask + row max (no scale mul; Q carries it) ----
        const bool diag = (kt >= 2 * qb);
        float m0 = -CUDART_INF_F, m1 = -CUDART_INF_F;
        #pragma unroll
        for (int nt = 0; nt < 8; nt++) {
            const int cl = nt * 8 + 2 * lq;
            const int cg = kt * 64 + cl;
            const bool pk0 = mk[cl] != 0, pk1 = mk[cl + 1] != 0;
            float v0 = (pk0 || (diag && cg     > row0)) ? -CUDART_INF_F : sc[nt][0];
            float v1 = (pk1 || (diag && cg + 1 > row0)) ? -CUDART_INF_F : sc[nt][1];
            float v2 = (pk0 || (diag && cg     > row1)) ? -CUDART_INF_F : sc[nt][2];
            float v3 = (pk1 || (diag && cg + 1 > row1)) ? -CUDART_INF_F : sc[nt][3];
            sc[nt][0] = v0; sc[nt][1] = v1; sc[nt][2] = v2; sc[nt][3] = v3;
            m0 = fmaxf(m0, fmaxf(v0, v1));
            m1 = fmaxf(m1, fmaxf(v2, v3));
        }
        m0 = fmaxf(m0, __shfl_xor_sync(0xffffffffu, m0, 1));
        m0 = fmaxf(m0, __shfl_xor_sync(0xffffffffu, m0, 2));
        m1 = fmaxf(m1, __shfl_xor_sync(0xffffffffu, m1, 1));
        m1 = fmaxf(m1, __shfl_xor_sync(0xffffffffu, m1, 2));

        const float mn0 = fmaxf(m_i0, m0), mn1 = fmaxf(m_i1, m1);
        const float corr0 = (mn0 == -CUDART_INF_F) ? 1.f : fast_exp2(m_i0 - mn0);
        const float corr1 = (mn1 == -CUDART_INF_F) ? 1.f : fast_exp2(m_i1 - mn1);
        const float base0 = (mn0 == -CUDART_INF_F) ? 0.f : mn0;
        const float base1 = (mn1 == -CUDART_INF_F) ? 0.f : mn1;

        float psum0 = 0.f, psum1 = 0.f;
        uint32_t ptop_prev = 0, pbot_prev = 0;
        __syncwarp();
        #pragma unroll
        for (int nt = 0; nt < 8; nt++) {
            float p0 = (sc[nt][0] == -CUDART_INF_F) ? 0.f : fast_exp2(sc[nt][0] - base0);
            float p1 = (sc[nt][1] == -CUDART_INF_F) ? 0.f : fast_exp2(sc[nt][1] - base0);
            float p2 = (sc[nt][2] == -CUDART_INF_F) ? 0.f : fast_exp2(sc[nt][2] - base1);
            float p3 = (sc[nt][3] == -CUDART_INF_F) ? 0.f : fast_exp2(sc[nt][3] - base1);
            psum0 += p0 + p1;
            psum1 += p2 + p3;
            uint32_t top = FU(h2pack(p0, p1));
            uint32_t bot = FU(h2pack(p2, p3));
            if (nt & 1) {
                const int c = nt >> 1;
                pf2[(warp_m + g) * 20 + c * 4 + lq] =
                    make_float2(__uint_as_float(ptop_prev), __uint_as_float(top));
                pf2[(warp_m + g + 8) * 20 + c * 4 + lq] =
                    make_float2(__uint_as_float(pbot_prev), __uint_as_float(bot));
            } else { ptop_prev = top; pbot_prev = bot; }
        }
        psum0 += __shfl_xor_sync(0xffffffffu, psum0, 1);
        psum0 += __shfl_xor_sync(0xffffffffu, psum0, 2);
        psum1 += __shfl_xor_sync(0xffffffffu, psum1, 1);
        psum1 += __shfl_xor_sync(0xffffffffu, psum1, 2);
        l0 = l0 * corr0 + psum0;
        l1 = l1 * corr1 + psum1;
        m_i0 = mn0; m_i1 = mn1;

        #pragma unroll
        for (int nt = 0; nt < 16; nt++) {
            acc[nt][0] *= corr0; acc[nt][1] *= corr0;
            acc[nt][2] *= corr1; acc[nt][3] *= corr1;
        }
        __syncwarp();

        // ---- O += P @ V  (1x fp16, packed) ----
        #pragma unroll
        for (int c = 0; c < 4; c++) {
            float2 pa = pf2[(warp_m + g) * 20 + c * 4 + lq];
            float2 pb = pf2[(warp_m + g + 8) * 20 + c * 4 + lq];
            uint32_t A0 = FU(pa.x), A1 = FU(pb.x), A2 = FU(pa.y), A3 = FU(pb.y);
            const float2* vp = vf2 + (c * 4 + lq) * 132;
            #pragma unroll
            for (int nt = 0; nt < 16; nt++) {
                float2 vv = vp[nt * 8 + g];
                mma_f16(acc[nt], A0, A1, A2, A3, FU(vv.x), FU(vv.y));
            }
        }
    }

    // ---- epilogue: packed fragments (row stride 512 float4) ----
    const float inv0 = (l0 > 0.f) ? (1.f / l0) : 0.f;
    const float inv1 = (l1 > 0.f) ? (1.f / l1) : 0.f;
    const size_t fb0 = (size_t)(b * Sq + row0) * 512 + (h * 8) * 4 + lq;
    const size_t fb1 = (size_t)(b * Sq + row1) * 512 + (h * 8) * 4 + lq;
    #pragma unroll
    for (int c = 0; c < 8; c++) {
        apk[fb0 + c * 4] = pack_hl4(acc[2*c][0] * inv0, acc[2*c][1] * inv0,
                                    acc[2*c+1][0] * inv0, acc[2*c+1][1] * inv0);
        apk[fb1 + c * 4] = pack_hl4(acc[2*c][2] * inv1, acc[2*c][3] * inv1,
                                    acc[2*c+1][2] * inv1, acc[2*c+1][3] * inv1);
    }
}

// ---------------------------------------------------------------------------
// Launch — dependency DAG across streams (graph-capture-safe event fork/join)
// ---------------------------------------------------------------------------
extern "C" void kernel_launch(void* const* d_in, const int* in_sizes, int n_in,
                              void* d_out, int out_size)
{
    const float*         x        = (const float*)d_in[0];
    const unsigned char* mask     = (const unsigned char*)d_in[1];
    const float*         wq_down  = (const float*)d_in[2];
    const float*         bq_down  = (const float*)d_in[3];
    const float*         gq_ln    = (const float*)d_in[4];
    const float*         bq_ln    = (const float*)d_in[5];
    const float*         wq_up    = (const float*)d_in[6];
    const float*         bq_up    = (const float*)d_in[7];
    const float*         wkv_down = (const float*)d_in[8];
    const float*         bkv_down = (const float*)d_in[9];
    const float*         gkv_ln   = (const float*)d_in[10];
    const float*         bkv_ln   = (const float*)d_in[11];
    const float*         wkv_up   = (const float*)d_in[12];
    const float*         bkv_up   = (const float*)d_in[13];
    const float*         w_out    = (const float*)d_in[14];
    const float*         b_out    = (const float*)d_in[15];
    float* out = (float*)d_out;

    float *qlat, *qb, *kvlat, *kvb;
    float4 *apk, *lpkq, *lpkkv, *kpk, *wqd, *wkvd, *wqu, *wkvu, *wout;
    float2 *vpk;
    cudaGetSymbolAddress((void**)&qlat,  g_qlat);
    cudaGetSymbolAddress((void**)&qb,    g_q);
    cudaGetSymbolAddress((void**)&kvlat, g_kvlat);
    cudaGetSymbolAddress((void**)&kvb,   g_kv);
    cudaGetSymbolAddress((void**)&apk,   g_apk);
    cudaGetSymbolAddress((void**)&lpkq,  g_lpkq);
    cudaGetSymbolAddress((void**)&lpkkv, g_lpkkv);
    cudaGetSymbolAddress((void**)&kpk,   g_kpk);
    cudaGetSymbolAddress((void**)&vpk,   g_vpk);
    cudaGetSymbolAddress((void**)&wqd,   g_wqd_pk);
    cudaGetSymbolAddress((void**)&wkvd,  g_wkvd_pk);
    cudaGetSymbolAddress((void**)&wqu,   g_wqu_pk);
    cudaGetSymbolAddress((void**)&wkvu,  g_wkvu_pk);
    cudaGetSymbolAddress((void**)&wout,  g_wout_pk);

    cudaFuncSetAttribute(attn_mma,
                         cudaFuncAttributeMaxDynamicSharedMemorySize, ATT_SMEM);
    cudaFuncSetAttribute(gemm_hp<true>,
                         cudaFuncAttributeMaxDynamicSharedMemorySize, GEMM_SMEM);
    cudaFuncSetAttribute(gemm_hp<false>,
                         cudaFuncAttributeMaxDynamicSharedMemorySize, GEMM_SMEM);

    // streams / events (created once; safe — no device allocation)
    static cudaStream_t sA = nullptr, sB = nullptr, sC = nullptr;
    static cudaEvent_t eRoot, eApk, eWqU, eWkvU, eWout, eQb, eKV;
    if (!sA) {
        cudaStreamCreateWithFlags(&sA, cudaStreamNonBlocking);
        cudaStreamCreateWithFlags(&sB, cudaStreamNonBlocking);
        cudaStreamCreateWithFlags(&sC, cudaStreamNonBlocking);
        cudaEventCreateWithFlags(&eRoot, cudaEventDisableTiming);
        cudaEventCreateWithFlags(&eApk,  cudaEventDisableTiming);
        cudaEventCreateWithFlags(&eWqU,  cudaEventDisableTiming);
        cudaEventCreateWithFlags(&eWkvU, cudaEventDisableTiming);
        cudaEventCreateWithFlags(&eWout, cudaEventDisableTiming);
        cudaEventCreateWithFlags(&eQb,   cudaEventDisableTiming);
        cudaEventCreateWithFlags(&eKV,   cudaEventDisableTiming);
    }

    // fork
    cudaEventRecord(eRoot, 0);
    cudaStreamWaitEvent(sA, eRoot, 0);
    cudaStreamWaitEvent(sB, eRoot, 0);
    cudaStreamWaitEvent(sC, eRoot, 0);

    // stream 0: pack input activations
    {
        int tot = Mrows * Dm / 4;
        pack_act<<<tot / 256, 256, 0, 0>>>(x, apk, Dm, tot);
        cudaEventRecord(eApk, 0);
    }
    // sC: late weight packs (hidden under down-gemms)
    {
        int t1 = (Ll / 16) * 4 * Dm;
        pack_w<<<t1 / 256, 256, 0, sC>>>(wq_up, wqu, Dm, t1);
        cudaEventRecord(eWqU, sC);
        int t2 = (Ll / 16) * 4 * 2 * Dm;
        pack_w<<<t2 / 256, 256, 0, sC>>>(wkv_up, wkvu, 2 * Dm, t2);
        cudaEventRecord(eWkvU, sC);
        int t3 = (Dm / 16) * 4 * Dm;
        pack_w<<<t3 / 256, 256, 0, sC>>>(w_out, wout, Dm, t3);
        cudaEventRecord(eWout, sC);
    }
    const int totd = (Dm / 16) * 4 * Ll;
    // sA: Q path
    pack_w<<<totd / 256, 256, 0, sA>>>(wq_down, wqd, Ll, totd);
    cudaStreamWaitEvent(sA, eApk, 0);
    gemm_hp<true><<<dim3(Ll / 128, Mrows / 128), 256, GEMM_SMEM, sA>>>(
        Mrows, Ll, Dm, apk, wqd, bq_down, qlat);
    ln512_pack<<<Mrows, 256, 0, sA>>>(qlat, gq_ln, bq_ln, lpkq);
    cudaStreamWaitEvent(sA, eWqU, 0);
    gemm_hp<false><<<dim3(Dm / 128, Mrows / 128), 256, GEMM_SMEM, sA>>>(
        Mrows, Dm, Ll, lpkq, wqu, bq_up, qb);
    cudaEventRecord(eQb, sA);
    // sB: KV path
    pack_w<<<totd / 256, 256, 0, sB>>>(wkv_down, wkvd, Ll, totd);
    cudaStreamWaitEvent(sB, eApk, 0);
    gemm_hp<true><<<dim3(Ll / 128, Mrows / 128), 256, GEMM_SMEM, sB>>>(
        Mrows, Ll, Dm, apk, wkvd, bkv_down, kvlat);
    ln512_pack<<<Mrows, 256, 0, sB>>>(kvlat, gkv_ln, bkv_ln, lpkkv);
    cudaStreamWaitEvent(sB, eWkvU, 0);
    gemm_hp<false><<<dim3(2 * Dm / 128, Mrows / 128), 256, GEMM_SMEM, sB>>>(
        Mrows, 2 * Dm, Ll, lpkkv, wkvu, bkv_up, kvb);
    pack_kv<<<dim3(Sq / 64, Bsz * Hh), 256, 0, sB>>>(kvb, kpk, vpk);
    cudaEventRecord(eKV, sB);

    // join on stream 0: attention + output projection
    cudaStreamWaitEvent(0, eQb, 0);
    cudaStreamWaitEvent(0, eKV, 0);
    attn_mma<<<dim3(Sq / 128, Bsz * Hh), 256, ATT_SMEM, 0>>>(qb, kpk, vpk, mask, apk);
    cudaStreamWaitEvent(0, eWout, 0);
    gemm_hp<false><<<dim3(Dm / 128, Mrows / 128), 256, GEMM_SMEM, 0>>>(
        Mrows, Dm, Dm, apk, wout, b_out, out);
}

// round 14
// speedup vs baseline: 3.0747x; 1.0713x over previous
#include <cuda_runtime.h>
#include <cuda_fp16.h>
#include <math_constants.h>
#include <cstdint>

// Problem constants
#define Bsz 2
#define Sq  2048
#define Dm  2048
#define Hh  16
#define Ll  512
#define HDm 128
#define Mrows (Bsz*Sq)      // 4096

// ---------------------------------------------------------------------------
// Scratch (static device globals — no runtime allocation allowed)
// ---------------------------------------------------------------------------
__device__ float  g_qlat [(size_t)Mrows * Ll];
__device__ float  g_q    [(size_t)Mrows * Dm];
__device__ float  g_kvlat[(size_t)Mrows * Ll];
__device__ float  g_kv   [(size_t)Mrows * 2 * Dm];
__device__ float4 g_apk  [(size_t)Mrows * Dm / 4];    // packed acts (x, attn out)
__device__ float4 g_lpkq [(size_t)Mrows * Ll / 4];    // packed latent (q path)
__device__ float4 g_lpkkv[(size_t)Mrows * Ll / 4];    // packed latent (kv path)
__device__ float2 g_kpk  [(size_t)Mrows * Dm / 4];    // packed K hi-only half2 pairs
__device__ float2 g_vpk  [(size_t)Mrows * Dm / 4];    // packed V half2 pairs
// per-weight packed buffers (enable stream-parallel packing)
__device__ float4 g_wqd_pk [(size_t)Dm * Ll / 4];
__device__ float4 g_wkvd_pk[(size_t)Dm * Ll / 4];
__device__ float4 g_wqu_pk [(size_t)Ll * Dm / 4];
__device__ float4 g_wkvu_pk[(size_t)Ll * 2 * Dm / 4];
__device__ float4 g_wout_pk[(size_t)Dm * Dm / 4];

// ---------------------------------------------------------------------------
// Helpers
// ---------------------------------------------------------------------------
__device__ __forceinline__ uint32_t smem_u32(const void* p) {
    uint32_t a;
    asm("{ .reg .u64 t; cvta.to.shared.u64 t, %1; cvt.u32.u64 %0, t; }"
        : "=r"(a) : "l"(p));
    return a;
}
__device__ __forceinline__ void cp16(uint32_t dst, const void* src) {
    asm volatile("cp.async.cg.shared.global [%0], [%1], 16;"
                 :: "r"(dst), "l"(src) : "memory");
}
__device__ __forceinline__ float fast_exp2(float x) {
    float r;
    asm("ex2.approx.f32 %0, %1;" : "=f"(r) : "f"(x));
    return r;
}
__device__ __forceinline__ float h2pack(float a, float b) {
    __half2 h = __halves2half2(__float2half_rn(a), __float2half_rn(b));
    return __uint_as_float(*(uint32_t*)&h);
}
__device__ __forceinline__ float4 pack_hl4(float a0, float a1, float a2, float a3) {
    __half h0 = __float2half_rn(a0), h1 = __float2half_rn(a1);
    __half h2 = __float2half_rn(a2), h3 = __float2half_rn(a3);
    float4 r;
    __half2 p;
    p = __halves2half2(h0, h1); r.x = __uint_as_float(*(uint32_t*)&p);
    p = __halves2half2(h2, h3); r.y = __uint_as_float(*(uint32_t*)&p);
    r.z = h2pack(a0 - __half2float(h0), a1 - __half2float(h1));
    r.w = h2pack(a2 - __half2float(h2), a3 - __half2float(h3));
    return r;
}
__device__ __forceinline__ void mma_f16(
    float c[4], uint32_t a0, uint32_t a1, uint32_t a2, uint32_t a3,
    uint32_t b0, uint32_t b1)
{
    asm volatile(
        "mma.sync.aligned.m16n8k16.row.col.f32.f16.f16.f32 "
        "{%0,%1,%2,%3}, {%4,%5,%6,%7}, {%8,%9}, {%0,%1,%2,%3};"
        : "+f"(c[0]), "+f"(c[1]), "+f"(c[2]), "+f"(c[3])
        : "r"(a0), "r"(a1), "r"(a2), "r"(a3), "r"(b0), "r"(b1));
}
#define FU(x) __float_as_uint(x)

// ---------------------------------------------------------------------------
// Pack kernels
// ---------------------------------------------------------------------------
__global__ __launch_bounds__(256) void pack_act(
    const float* __restrict__ A, float4* __restrict__ out, int K, int total)
{
    int idx = blockIdx.x * 256 + threadIdx.x;
    if (idx >= total) return;
    int lq = idx & 3, rest = idx >> 2;
    int jc = rest % (K >> 4), m = rest / (K >> 4);
    const float* base = A + (size_t)m * K + 16 * jc + 2 * lq;
    float2 a = *(const float2*)base;
    float2 b = *(const float2*)(base + 8);
    out[idx] = pack_hl4(a.x, a.y, b.x, b.y);
}
__global__ __launch_bounds__(256) void pack_w(
    const float* __restrict__ W, float4* __restrict__ out, int N, int total)
{
    int idx = blockIdx.x * 256 + threadIdx.x;
    if (idx >= total) return;
    int n = idx % N, g2 = idx / N;
    int lq = g2 & 3, jc = g2 >> 2;
    size_t k = 16 * jc + 2 * lq;
    out[idx] = pack_hl4(W[k * N + n] * 256.f, W[(k + 1) * N + n] * 256.f,
                        W[(k + 8) * N + n] * 256.f, W[(k + 9) * N + n] * 256.f);
}
// KV pack: one block per (kt, bh) tile. K emitted hi-only (half2 pairs).
__global__ __launch_bounds__(256) void pack_kv(
    const float* __restrict__ kv, float2* __restrict__ kpk, float2* __restrict__ vpk)
{
    __shared__ float Kr[64 * 132];
    const int kt = blockIdx.x, bh = blockIdx.y;
    const int b = bh >> 4, h = bh & 15;
    const float* Kp = kv + (size_t)b * Sq * 2 * Dm + (size_t)h * HDm
                         + (size_t)kt * 64 * 2 * Dm;
    const float* Vp = Kp + Dm;
    const uint32_t smu = smem_u32(Kr);
    const int tid = threadIdx.x;

    #pragma unroll
    for (int t = 0; t < 8; t++) {
        int idx = tid + t * 256;
        int row = idx >> 5, c4 = (idx & 31) * 4;
        cp16(smu + (row * 132 + c4) * 4, Kp + (size_t)row * 2 * Dm + c4);
    }
    asm volatile("cp.async.commit_group;" ::: "memory");
    asm volatile("cp.async.wait_group 0;" ::: "memory");
    __syncthreads();

    const size_t obase = (size_t)(bh * 32 + kt) * 2048;
    #pragma unroll
    for (int t = 0; t < 8; t++) {
        int idx = tid + t * 256;
        int n = idx & 63, grp = idx >> 6;
        int c = grp >> 2, lqq = grp & 3;
        const float* kr = Kr + n * 132 + c * 16 + 2 * lqq;
        kpk[obase + grp * 64 + n] =
            make_float2(h2pack(kr[0], kr[1]), h2pack(kr[8], kr[9]));
    }
    #pragma unroll
    for (int t = 0; t < 8; t++) {
        int idx = tid + t * 256;
        int d = idx & 127, grp = idx >> 7;
        int c = grp >> 2, lqq = grp & 3;
        const float* vr = Vp + (size_t)(c * 16 + 2 * lqq) * 2 * Dm + d;
        vpk[obase + grp * 128 + d] =
            make_float2(h2pack(vr[0], vr[2 * Dm]),
                        h2pack(vr[8 * 2 * Dm], vr[9 * 2 * Dm]));
    }
}

// ---------------------------------------------------------------------------
// fp16 GEMM on pre-packed operands. FULL3: 3-term Markidis (hh+lh+hl);
// else 2-term (hh+hl). CTA 128x128, BK=16, 3-stage cp.async, 2 CTAs/SM.
// ---------------------------------------------------------------------------
#define GSTG 1032            // float4 per stage: 512 A + 520 B (stride 130)
#define GEMM_SMEM (3 * GSTG * 16)

template<bool FULL3>
__global__ __launch_bounds__(256, 2) void gemm_hp(
    int M, int N, int K,
    const float4* __restrict__ Apk,
    const float4* __restrict__ Bpk,
    const float* __restrict__ bias,
    float* __restrict__ C)
{
    extern __shared__ float4 gsm[];
    const uint32_t smu = smem_u32(gsm);
    const int tid = threadIdx.x;
    const int wid = tid >> 5, lid = tid & 31;
    const int g = lid >> 2, lq = lid & 3;
    const int m0 = blockIdx.y * 128, n0 = blockIdx.x * 128;
    const int warp_m = (wid & 1) * 64;
    const int warp_n = (wid >> 1) * 32;
    const int nc = K >> 4, K16 = K >> 4;

    float acc[4][4][4];
    #pragma unroll
    for (int mt = 0; mt < 4; mt++)
        #pragma unroll
        for (int nt = 0; nt < 4; nt++)
            #pragma unroll
            for (int e = 0; e < 4; e++) acc[mt][nt][e] = 0.f;

    auto load_tile = [&](int c, int s) {
        const uint32_t sb = smu + s * (GSTG * 16);
        #pragma unroll
        for (int t = 0; t < 2; t++) {
            int idx = tid + t * 256;
            int m = idx >> 2, j = idx & 3;
            cp16(sb + ((m * 4 + j) << 4),
                 Apk + ((size_t)(m0 + m) * K16 + c) * 4 + j);
        }
        #pragma unroll
        for (int t = 0; t < 2; t++) {
            int idx = tid + t * 256;
            int j = idx >> 7, n = idx & 127;
            cp16(sb + ((512 + j * 130 + n) << 4),
                 Bpk + (size_t)(c * 4 + j) * N + n0 + n);
        }
        asm volatile("cp.async.commit_group;" ::: "memory");
    };

    load_tile(0, 0);
    load_tile(1, 1);

    for (int c = 0; c < nc; ++c) {
        if (c + 1 < nc) { asm volatile("cp.async.wait_group 1;" ::: "memory"); }
        else            { asm volatile("cp.async.wait_group 0;" ::: "memory"); }
        __syncthreads();
        if (c + 2 < nc) load_tile(c + 2, (c + 2) % 3);

        const float4* AS_ = gsm + (c % 3) * GSTG;
        const float4* BS_ = AS_ + 512;

        uint32_t Ah[4][4], Al[4][4];
        #pragma unroll
        for (int mt = 0; mt < 4; mt++) {
            float4 fa = AS_[(warp_m + mt * 16 + g) * 4 + lq];
            float4 fb = AS_[(warp_m + mt * 16 + g + 8) * 4 + lq];
            Ah[mt][0] = FU(fa.x); Ah[mt][1] = FU(fb.x);
            Ah[mt][2] = FU(fa.y); Ah[mt][3] = FU(fb.y);
            if (FULL3) {
                Al[mt][0] = FU(fa.z); Al[mt][1] = FU(fb.z);
                Al[mt][2] = FU(fa.w); Al[mt][3] = FU(fb.w);
            }
        }
        uint32_t Bh[4][2], Bl[4][2];
        #pragma unroll
        for (int nt = 0; nt < 4; nt++) {
            float4 f = BS_[lq * 130 + warp_n + nt * 8 + g];
            Bh[nt][0] = FU(f.x); Bh[nt][1] = FU(f.y);
            Bl[nt][0] = FU(f.z); Bl[nt][1] = FU(f.w);
        }
        #pragma unroll
        for (int mt = 0; mt < 4; mt++)
            #pragma unroll
            for (int nt = 0; nt < 4; nt++) {
                mma_f16(acc[mt][nt], Ah[mt][0], Ah[mt][1], Ah[mt][2], Ah[mt][3],
                        Bl[nt][0], Bl[nt][1]);
                if (FULL3)
                    mma_f16(acc[mt][nt], Al[mt][0], Al[mt][1], Al[mt][2], Al[mt][3],
                            Bh[nt][0], Bh[nt][1]);
                mma_f16(acc[mt][nt], Ah[mt][0], Ah[mt][1], Ah[mt][2], Ah[mt][3],
                        Bh[nt][0], Bh[nt][1]);
            }
    }

    const float s = 1.f / 256.f;
    #pragma unroll
    for (int mt = 0; mt < 4; mt++) {
        const int r0 = m0 + warp_m + mt * 16 + g;
        #pragma unroll
        for (int nt = 0; nt < 4; nt++) {
            const int col = n0 + warp_n + nt * 8 + lq * 2;
            const float2 b2 = *(const float2*)(bias + col);
            float2 o;
            o.x = acc[mt][nt][0] * s + b2.x;
            o.y = acc[mt][nt][1] * s + b2.y;
            *(float2*)(C + (size_t)r0 * N + col) = o;
            o.x = acc[mt][nt][2] * s + b2.x;
            o.y = acc[mt][nt][3] * s + b2.y;
            *(float2*)(C + (size_t)(r0 + 8) * N + col) = o;
        }
    }
}

// ---------------------------------------------------------------------------
// LayerNorm over last dim (512), emitting packed fp16 hi/lo fragments.
// ---------------------------------------------------------------------------
__global__ __launch_bounds__(256) void ln512_pack(
    const float* __restrict__ x,
    const float* __restrict__ g,
    const float* __restrict__ b,
    float4* __restrict__ out)
{
    __shared__ float row_sh[512];
    const int row = blockIdx.x;
    const float* xr = x + (size_t)row * Ll;
    const int tid = threadIdx.x;

    float v0 = xr[tid];
    float v1 = xr[tid + 256];
    float s  = v0 + v1;
    float sq = v0 * v0 + v1 * v1;

    #pragma unroll
    for (int o = 16; o > 0; o >>= 1) {
        s  += __shfl_xor_sync(0xffffffffu, s,  o);
        sq += __shfl_xor_sync(0xffffffffu, sq, o);
    }
    __shared__ float ss[8], ssq[8];
    __shared__ float mean_sh, inv_sh;
    const int w = tid >> 5;
    if ((tid & 31) == 0) { ss[w] = s; ssq[w] = sq; }
    __syncthreads();
    if (tid == 0) {
        float S = 0.f, SQ = 0.f;
        #pragma unroll
        for (int i = 0; i < 8; i++) { S += ss[i]; SQ += ssq[i]; }
        float m = S * (1.f / Ll);
        float var = SQ * (1.f / Ll) - m * m;
        mean_sh = m;
        inv_sh = rsqrtf(var + 1e-5f);
    }
    __syncthreads();
    const float m = mean_sh, inv = inv_sh;
    row_sh[tid]       = (v0 - m) * inv * g[tid]       + b[tid];
    row_sh[tid + 256] = (v1 - m) * inv * g[tid + 256] + b[tid + 256];
    __syncthreads();
    if (tid < 128) {
        int jc = tid >> 2, lq = tid & 3;
        const float* p = row_sh + 16 * jc + 2 * lq;
        out[(size_t)row * 128 + tid] = pack_hl4(p[0], p[1], p[8], p[9]);
    }
}

// ---------------------------------------------------------------------------
// Flash attention, K hi-only. QK = 2-term (Qh+Ql vs Kh); PV = 1x fp16.
// Scores in log2 units. Output written as packed apk fragments.
// ---------------------------------------------------------------------------
#define STG_F  8448                  // floats per stage: K 4224 + V 4224
#define KS_F(s) ((s) * STG_F)
#define VS_F(s) ((s) * STG_F + 4224)
#define P_F    25344
#define MASK_B 121856                // bytes (P ends at 30464 floats)
#define ATT_SMEM 122048

__global__ __launch_bounds__(256, 1) void attn_mma(
    const float* __restrict__ q,
    const float2* __restrict__ kpk,
    const float2* __restrict__ vpk,
    const unsigned char* __restrict__ mask,
    float4* __restrict__ apk)
{
    extern __shared__ float sm[];
    unsigned char* smb = (unsigned char*)sm;

    const int bh = blockIdx.y;
    const int b = bh >> 4, h = bh & 15;
    const int qb = gridDim.x - 1 - blockIdx.x;   // heavy blocks first
    const int q0 = qb * 128;
    const int ktmax = 2 * qb + 1;

    const int tid = threadIdx.x;
    const int wid = tid >> 5, lid = tid & 31;
    const int g = lid >> 2, lq = lid & 3;
    const int warp_m = wid * 16;

    const float* Qp = q + (size_t)b * Sq * Dm + (size_t)h * HDm;
    const unsigned char* mp = mask + (size_t)b * Sq;

    const uint32_t smu = smem_u32(sm);
    // 1/sqrt(128) * log2(e) folded into Q
    const float SCL2 = 0.08838834764831845f * 1.4426950408889634f;

    // ---- stage Q raw (fits inside stage area; done before any load_kv) ----
    #pragma unroll
    for (int t = 0; t < 16; t++) {
        int idx = tid + t * 256;
        int row = idx >> 5, c4 = (idx & 31) << 2;
        cp16(smu + (row * 132 + c4) * 4, Qp + (size_t)(q0 + row) * Dm + c4);
    }
    asm volatile("cp.async.commit_group;" ::: "memory");
    asm volatile("cp.async.wait_group 0;" ::: "memory");
    __syncthreads();

    uint32_t Qh[8][4], Ql[8][4];
    #pragma unroll
    for (int c = 0; c < 8; c++)
        #pragma unroll
        for (int e = 0; e < 4; e++) {
            int row = warp_m + g + (e & 1) * 8;
            int col = c * 16 + 2 * lq + (e >> 1) * 8;
            float a0 = sm[row * 132 + col] * SCL2;
            float a1 = sm[row * 132 + col + 1] * SCL2;
            __half h0 = __float2half_rn(a0), h1 = __float2half_rn(a1);
            __half2 hp = __halves2half2(h0, h1);
            Qh[c][e] = *(uint32_t*)&hp;
            Ql[c][e] = FU(h2pack(a0 - __half2float(h0), a1 - __half2float(h1)));
        }
    __syncthreads();

    auto load_kv = [&](int kt, int s) {
        const float2* kg = kpk + (size_t)(bh * 32 + kt) * 2048;
        const float2* vg = vpk + (size_t)(bh * 32 + kt) * 2048;
        // K: 2048 float2, group stride 66 float2 (n 0..63)
        #pragma unroll
        for (int t = 0; t < 4; t++) {
            int idx = tid + t * 256;
            int grp = idx >> 5, np = idx & 31;
            cp16(smu + KS_F(s) * 4 + (grp * 66 + 2 * np) * 8, kg + grp * 64 + 2 * np);
        }
        // V: 2048 float2, group stride 132 float2 (d 0..127)
        #pragma unroll
        for (int t = 0; t < 4; t++) {
            int idx = tid + t * 256;
            int r = idx >> 6, dd = idx & 63;
            cp16(smu + VS_F(s) * 4 + (r * 132 + 2 * dd) * 8, vg + r * 128 + 2 * dd);
        }
        if (tid < 4)
            cp16(smu + MASK_B + s * 64 + tid * 16, mp + kt * 64 + tid * 16);
        asm volatile("cp.async.commit_group;" ::: "memory");
    };

    load_kv(0, 0);
    load_kv(1, 1);

    const int row0 = q0 + warp_m + g;
    const int row1 = row0 + 8;
    float m_i0 = -CUDART_INF_F, m_i1 = -CUDART_INF_F;
    float l0 = 0.f, l1 = 0.f;
    float acc[16][4];
    #pragma unroll
    for (int nt = 0; nt < 16; nt++)
        #pragma unroll
        for (int e = 0; e < 4; e++) acc[nt][e] = 0.f;

    float2* pf2 = (float2*)(sm + P_F);

    for (int kt = 0; kt <= ktmax; ++kt) {
        const int st = kt % 3;
        if (kt < ktmax) { asm volatile("cp.async.wait_group 1;" ::: "memory"); }
        else            { asm volatile("cp.async.wait_group 0;" ::: "memory"); }
        __syncthreads();
        if (kt + 2 <= ktmax) load_kv(kt + 2, (kt + 2) % 3);

        const float2* kf2 = (const float2*)(sm + KS_F(st));
        const float2* vf2 = (const float2*)(sm + VS_F(st));
        const unsigned char* mk = smb + MASK_B + st * 64;

        // ---- scores: S = Q @ K^T  (2-term fp16, K hi-only, log2 units) ----
        float sc[8][4];
        #pragma unroll
        for (int nt = 0; nt < 8; nt++)
            #pragma unroll
            for (int e = 0; e < 4; e++) sc[nt][e] = 0.f;

        #pragma unroll 4
        for (int c = 0; c < 8; c++) {
            const float2* kp_ = kf2 + (c * 4 + lq) * 66;
            #pragma unroll
            for (int nt = 0; nt < 8; nt++) {
                float2 kk = kp_[nt * 8 + g];
                mma_f16(sc[nt], Ql[c][0], Ql[c][1], Ql[c][2], Ql[c][3],
                        FU(kk.x), FU(kk.y));
                mma_f16(sc[nt], Qh[c][0], Qh[c][1], Qh[c][2], Qh[c][3],
                        FU(kk.x), FU(kk.y));
            }
        }

        // ---- mask + row max (no scale mul; Q carries it) ----
        const bool diag = (kt >= 2 * qb);
        float m0 = -CUDART_INF_F, m1 = -CUDART_INF_F;
        #pragma unroll
        for (int nt = 0; nt < 8; nt++) {
            const int cl = nt * 8 + 2 * lq;
            const int cg = kt * 64 + cl;
            const bool pk0 = mk[cl] != 0, pk1 = mk[cl + 1] != 0;
            float v0 = (pk0 || (diag && cg     > row0)) ? -CUDART_INF_F : sc[nt][0];
            float v1 = (pk1 || (diag && cg + 1 > row0)) ? -CUDART_INF_F : sc[nt][1];
            float v2 = (pk0 || (diag && cg     > row1)) ? -CUDART_INF_F : sc[nt][2];
            float v3 = (pk1 || (diag && cg + 1 > row1)) ? -CUDART_INF_F : sc[nt][3];
            sc[nt][0] = v0; sc[nt][1] = v1; sc[nt][2] = v2; sc[nt][3] = v3;
            m0 = fmaxf(m0, fmaxf(v0, v1));
            m1 = fmaxf(m1, fmaxf(v2, v3));
        }
        m0 = fmaxf(m0, __shfl_xor_sync(0xffffffffu, m0, 1));
        m0 = fmaxf(m0, __shfl_xor_sync(0xffffffffu, m0, 2));
        m1 = fmaxf(m1, __shfl_xor_sync(0xffffffffu, m1, 1));
        m1 = fmaxf(m1, __shfl_xor_sync(0xffffffffu, m1, 2));

        const float mn0 = fmaxf(m_i0, m0), mn1 = fmaxf(m_i1, m1);
        const float corr0 = (mn0 == -CUDART_INF_F) ? 1.f : fast_exp2(m_i0 - mn0);
        const float corr1 = (mn1 == -CUDART_INF_F) ? 1.f : fast_exp2(m_i1 - mn1);
        const float base0 = (mn0 == -CUDART_INF_F) ? 0.f : mn0;
        const float base1 = (mn1 == -CUDART_INF_F) ? 0.f : mn1;

        float psum0 = 0.f, psum1 = 0.f;
        uint32_t ptop_prev = 0, pbot_prev = 0;
        __syncwarp();
        #pragma unroll
        for (int nt = 0; nt < 8; nt++) {
            float p0 = (sc[nt][0] == -CUDART_INF_F) ? 0.f : fast_exp2(sc[nt][0] - base0);
            float p1 = (sc[nt][1] == -CUDART_INF_F) ? 0.f : fast_exp2(sc[nt][1] - base0);
            float p2 = (sc[nt][2] == -CUDART_INF_F) ? 0.f : fast_exp2(sc[nt][2] - base1);
            float p3 = (sc[nt][3] == -CUDART_INF_F) ? 0.f : fast_exp2(sc[nt][3] - base1);
            psum0 += p0 + p1;
            psum1 += p2 + p3;
            uint32_t top = FU(h2pack(p0, p1));
            uint32_t bot = FU(h2pack(p2, p3));
            if (nt & 1) {
                const int c = nt >> 1;
                pf2[(warp_m + g) * 20 + c * 4 + lq] =
                    make_float2(__uint_as_float(ptop_prev), __uint_as_float(top));
                pf2[(warp_m + g + 8) * 20 + c * 4 + lq] =
                    make_float2(__uint_as_float(pbot_prev), __uint_as_float(bot));
            } else { ptop_prev = top; pbot_prev = bot; }
        }
        psum0 += __shfl_xor_sync(0xffffffffu, psum0, 1);
        psum0 += __shfl_xor_sync(0xffffffffu, psum0, 2);
        psum1 += __shfl_xor_sync(0xffffffffu, psum1, 1);
        psum1 += __shfl_xor_sync(0xffffffffu, psum1, 2);
        l0 = l0 * corr0 + psum0;
        l1 = l1 * corr1 + psum1;
        m_i0 = mn0; m_i1 = mn1;

        #pragma unroll
        for (int nt = 0; nt < 16; nt++) {
            acc[nt][0] *= corr0; acc[nt][1] *= corr0;
            acc[nt][2] *= corr1; acc[nt][3] *= corr1;
        }
        __syncwarp();

        // ---- O += P @ V  (1x fp16, packed) ----
        #pragma unroll
        for (int c = 0; c < 4; c++) {
            float2 pa = pf2[(warp_m + g) * 20 + c * 4 + lq];
            float2 pb = pf2[(warp_m + g + 8) * 20 + c * 4 + lq];
            uint32_t A0 = FU(pa.x), A1 = FU(pb.x), A2 = FU(pa.y), A3 = FU(pb.y);
            const float2* vp = vf2 + (c * 4 + lq) * 132;
            #pragma unroll
            for (int nt = 0; nt < 16; nt++) {
                float2 vv = vp[nt * 8 + g];
                mma_f16(acc[nt], A0, A1, A2, A3, FU(vv.x), FU(vv.y));
            }
        }
    }

    // ---- epilogue: packed fragments (row stride 512 float4) ----
    const float inv0 = (l0 > 0.f) ? (1.f / l0) : 0.f;
    const float inv1 = (l1 > 0.f) ? (1.f / l1) : 0.f;
    const size_t fb0 = (size_t)(b * Sq + row0) * 512 + (h * 8) * 4 + lq;
    const size_t fb1 = (size_t)(b * Sq + row1) * 512 + (h * 8) * 4 + lq;
    #pragma unroll
    for (int c = 0; c < 8; c++) {
        apk[fb0 + c * 4] = pack_hl4(acc[2*c][0] * inv0, acc[2*c][1] * inv0,
                                    acc[2*c+1][0] * inv0, acc[2*c+1][1] * inv0);
        apk[fb1 + c * 4] = pack_hl4(acc[2*c][2] * inv1, acc[2*c][3] * inv1,
                                    acc[2*c+1][2] * inv1, acc[2*c+1][3] * inv1);
    }
}

// ---------------------------------------------------------------------------
// Launch — dependency DAG across streams (graph-capture-safe event fork/join)
// ---------------------------------------------------------------------------
extern "C" void kernel_launch(void* const* d_in, const int* in_sizes, int n_in,
                              void* d_out, int out_size)
{
    const float*         x        = (const float*)d_in[0];
    const unsigned char* mask     = (const unsigned char*)d_in[1];
    const float*         wq_down  = (const float*)d_in[2];
    const float*         bq_down  = (const float*)d_in[3];
    const float*         gq_ln    = (const float*)d_in[4];
    const float*         bq_ln    = (const float*)d_in[5];
    const float*         wq_up    = (const float*)d_in[6];
    const float*         bq_up    = (const float*)d_in[7];
    const float*         wkv_down = (const float*)d_in[8];
    const float*         bkv_down = (const float*)d_in[9];
    const float*         gkv_ln   = (const float*)d_in[10];
    const float*         bkv_ln   = (const float*)d_in[11];
    const float*         wkv_up   = (const float*)d_in[12];
    const float*         bkv_up   = (const float*)d_in[13];
    const float*         w_out    = (const float*)d_in[14];
    const float*         b_out    = (const float*)d_in[15];
    float* out = (float*)d_out;

    float *qlat, *qb, *kvlat, *kvb;
    float4 *apk, *lpkq, *lpkkv, *wqd, *wkvd, *wqu, *wkvu, *wout;
    float2 *kpk, *vpk;
    cudaGetSymbolAddress((void**)&qlat,  g_qlat);
    cudaGetSymbolAddress((void**)&qb,    g_q);
    cudaGetSymbolAddress((void**)&kvlat, g_kvlat);
    cudaGetSymbolAddress((void**)&kvb,   g_kv);
    cudaGetSymbolAddress((void**)&apk,   g_apk);
    cudaGetSymbolAddress((void**)&lpkq,  g_lpkq);
    cudaGetSymbolAddress((void**)&lpkkv, g_lpkkv);
    cudaGetSymbolAddress((void**)&kpk,   g_kpk);
    cudaGetSymbolAddress((void**)&vpk,   g_vpk);
    cudaGetSymbolAddress((void**)&wqd,   g_wqd_pk);
    cudaGetSymbolAddress((void**)&wkvd,  g_wkvd_pk);
    cudaGetSymbolAddress((void**)&wqu,   g_wqu_pk);
    cudaGetSymbolAddress((void**)&wkvu,  g_wkvu_pk);
    cudaGetSymbolAddress((void**)&wout,  g_wout_pk);

    cudaFuncSetAttribute(attn_mma,
                         cudaFuncAttributeMaxDynamicSharedMemorySize, ATT_SMEM);
    cudaFuncSetAttribute(gemm_hp<true>,
                         cudaFuncAttributeMaxDynamicSharedMemorySize, GEMM_SMEM);
    cudaFuncSetAttribute(gemm_hp<false>,
                         cudaFuncAttributeMaxDynamicSharedMemorySize, GEMM_SMEM);

    // streams / events (created once; safe — no device allocation)
    static cudaStream_t sA = nullptr, sB = nullptr, sC = nullptr;
    static cudaEvent_t eRoot, eApk, eWqU, eWkvU, eWout, eQb, eKV;
    if (!sA) {
        cudaStreamCreateWithFlags(&sA, cudaStreamNonBlocking);
        cudaStreamCreateWithFlags(&sB, cudaStreamNonBlocking);
        cudaStreamCreateWithFlags(&sC, cudaStreamNonBlocking);
        cudaEventCreateWithFlags(&eRoot, cudaEventDisableTiming);
        cudaEventCreateWithFlags(&eApk,  cudaEventDisableTiming);
        cudaEventCreateWithFlags(&eWqU,  cudaEventDisableTiming);
        cudaEventCreateWithFlags(&eWkvU, cudaEventDisableTiming);
        cudaEventCreateWithFlags(&eWout, cudaEventDisableTiming);
        cudaEventCreateWithFlags(&eQb,   cudaEventDisableTiming);
        cudaEventCreateWithFlags(&eKV,   cudaEventDisableTiming);
    }

    // fork
    cudaEventRecord(eRoot, 0);
    cudaStreamWaitEvent(sA, eRoot, 0);
    cudaStreamWaitEvent(sB, eRoot, 0);
    cudaStreamWaitEvent(sC, eRoot, 0);

    // stream 0: pack input activations
    {
        int tot = Mrows * Dm / 4;
        pack_act<<<tot / 256, 256, 0, 0>>>(x, apk, Dm, tot);
        cudaEventRecord(eApk, 0);
    }
    // sC: late weight packs (hidden under down-gemms)
    {
        int t1 = (Ll / 16) * 4 * Dm;
        pack_w<<<t1 / 256, 256, 0, sC>>>(wq_up, wqu, Dm, t1);
        cudaEventRecord(eWqU, sC);
        int t2 = (Ll / 16) * 4 * 2 * Dm;
        pack_w<<<t2 / 256, 256, 0, sC>>>(wkv_up, wkvu, 2 * Dm, t2);
        cudaEventRecord(eWkvU, sC);
        int t3 = (Dm / 16) * 4 * Dm;
        pack_w<<<t3 / 256, 256, 0, sC>>>(w_out, wout, Dm, t3);
        cudaEventRecord(eWout, sC);
    }
    const int totd = (Dm / 16) * 4 * Ll;
    // sA: Q path
    pack_w<<<totd / 256, 256, 0, sA>>>(wq_down, wqd, Ll, totd);
    cudaStreamWaitEvent(sA, eApk, 0);
    gemm_hp<true><<<dim3(Ll / 128, Mrows / 128), 256, GEMM_SMEM, sA>>>(
        Mrows, Ll, Dm, apk, wqd, bq_down, qlat);
    ln512_pack<<<Mrows, 256, 0, sA>>>(qlat, gq_ln, bq_ln, lpkq);
    cudaStreamWaitEvent(sA, eWqU, 0);
    gemm_hp<false><<<dim3(Dm / 128, Mrows / 128), 256, GEMM_SMEM, sA>>>(
        Mrows, Dm, Ll, lpkq, wqu, bq_up, qb);
    cudaEventRecord(eQb, sA);
    // sB: KV path
    pack_w<<<totd / 256, 256, 0, sB>>>(wkv_down, wkvd, Ll, totd);
    cudaStreamWaitEvent(sB, eApk, 0);
    gemm_hp<true><<<dim3(Ll / 128, Mrows / 128), 256, GEMM_SMEM, sB>>>(
        Mrows, Ll, Dm, apk, wkvd, bkv_down, kvlat);
    ln512_pack<<<Mrows, 256, 0, sB>>>(kvlat, gkv_ln, bkv_ln, lpkkv);
    cudaStreamWaitEvent(sB, eWkvU, 0);
    gemm_hp<false><<<dim3(2 * Dm / 128, Mrows / 128), 256, GEMM_SMEM, sB>>>(
        Mrows, 2 * Dm, Ll, lpkkv, wkvu, bkv_up, kvb);
    pack_kv<<<dim3(Sq / 64, Bsz * Hh), 256, 0, sB>>>(kvb, kpk, vpk);
    cudaEventRecord(eKV, sB);

    // join on stream 0: attention + output projection
    cudaStreamWaitEvent(0, eQb, 0);
    cudaStreamWaitEvent(0, eKV, 0);
    attn_mma<<<dim3(Sq / 128, Bsz * Hh), 256, ATT_SMEM, 0>>>(qb, kpk, vpk, mask, apk);
    cudaStreamWaitEvent(0, eWout, 0);
    gemm_hp<false><<<dim3(Dm / 128, Mrows / 128), 256, GEMM_SMEM, 0>>>(
        Mrows, Dm, Dm, apk, wout, b_out, out);
}

// round 17
// speedup vs baseline: 3.2746x; 1.0650x over previous
#include <cuda_runtime.h>
#include <cuda_fp16.h>
#include <math_constants.h>
#include <cstdint>

// Problem constants
#define Bsz 2
#define Sq  2048
#define Dm  2048
#define Hh  16
#define Ll  512
#define HDm 128
#define Mrows (Bsz*Sq)      // 4096

// ---------------------------------------------------------------------------
// Scratch (static device globals — no runtime allocation allowed)
// ---------------------------------------------------------------------------
__device__ float  g_qlat [(size_t)Mrows * Ll];
__device__ float  g_q    [(size_t)Mrows * Dm];
__device__ float  g_kvlat[(size_t)Mrows * Ll];
__device__ float  g_kv   [(size_t)Mrows * 2 * Dm];
__device__ float4 g_apk  [(size_t)Mrows * Dm / 4];    // packed acts (x, attn out)
__device__ float4 g_lpkq [(size_t)Mrows * Ll / 4];    // packed latent (q path)
__device__ float4 g_lpkkv[(size_t)Mrows * Ll / 4];    // packed latent (kv path)
__device__ float2 g_kpk  [(size_t)Mrows * Dm / 4];    // packed K hi-only half2 pairs
__device__ float2 g_vpk  [(size_t)Mrows * Dm / 4];    // packed V half2 pairs
// per-weight packed buffers (enable stream-parallel packing)
__device__ float4 g_wqd_pk [(size_t)Dm * Ll / 4];
__device__ float4 g_wkvd_pk[(size_t)Dm * Ll / 4];
__device__ float4 g_wqu_pk [(size_t)Ll * Dm / 4];
__device__ float4 g_wkvu_pk[(size_t)Ll * 2 * Dm / 4];
__device__ float4 g_wout_pk[(size_t)Dm * Dm / 4];

// ---------------------------------------------------------------------------
// Helpers
// ---------------------------------------------------------------------------
__device__ __forceinline__ uint32_t smem_u32(const void* p) {
    uint32_t a;
    asm("{ .reg .u64 t; cvta.to.shared.u64 t, %1; cvt.u32.u64 %0, t; }"
        : "=r"(a) : "l"(p));
    return a;
}
__device__ __forceinline__ void cp16(uint32_t dst, const void* src) {
    asm volatile("cp.async.cg.shared.global [%0], [%1], 16;"
                 :: "r"(dst), "l"(src) : "memory");
}
__device__ __forceinline__ float fast_exp2(float x) {
    float r;
    asm("ex2.approx.f32 %0, %1;" : "=f"(r) : "f"(x));
    return r;
}
__device__ __forceinline__ float h2pack(float a, float b) {
    __half2 h = __halves2half2(__float2half_rn(a), __float2half_rn(b));
    return __uint_as_float(*(uint32_t*)&h);
}
__device__ __forceinline__ float4 pack_hl4(float a0, float a1, float a2, float a3) {
    __half h0 = __float2half_rn(a0), h1 = __float2half_rn(a1);
    __half h2 = __float2half_rn(a2), h3 = __float2half_rn(a3);
    float4 r;
    __half2 p;
    p = __halves2half2(h0, h1); r.x = __uint_as_float(*(uint32_t*)&p);
    p = __halves2half2(h2, h3); r.y = __uint_as_float(*(uint32_t*)&p);
    r.z = h2pack(a0 - __half2float(h0), a1 - __half2float(h1));
    r.w = h2pack(a2 - __half2float(h2), a3 - __half2float(h3));
    return r;
}
__device__ __forceinline__ void mma_f16(
    float c[4], uint32_t a0, uint32_t a1, uint32_t a2, uint32_t a3,
    uint32_t b0, uint32_t b1)
{
    asm volatile(
        "mma.sync.aligned.m16n8k16.row.col.f32.f16.f16.f32 "
        "{%0,%1,%2,%3}, {%4,%5,%6,%7}, {%8,%9}, {%0,%1,%2,%3};"
        : "+f"(c[0]), "+f"(c[1]), "+f"(c[2]), "+f"(c[3])
        : "r"(a0), "r"(a1), "r"(a2), "r"(a3), "r"(b0), "r"(b1));
}
#define FU(x) __float_as_uint(x)

// ---------------------------------------------------------------------------
// Pack kernels
// ---------------------------------------------------------------------------
__global__ __launch_bounds__(256) void pack_act(
    const float* __restrict__ A, float4* __restrict__ out, int K, int total)
{
    int idx = blockIdx.x * 256 + threadIdx.x;
    if (idx >= total) return;
    int lq = idx & 3, rest = idx >> 2;
    int jc = rest % (K >> 4), m = rest / (K >> 4);
    const float* base = A + (size_t)m * K + 16 * jc + 2 * lq;
    float2 a = *(const float2*)base;
    float2 b = *(const float2*)(base + 8);
    out[idx] = pack_hl4(a.x, a.y, b.x, b.y);
}
__global__ __launch_bounds__(256) void pack_w(
    const float* __restrict__ W, float4* __restrict__ out, int N, int total)
{
    int idx = blockIdx.x * 256 + threadIdx.x;
    if (idx >= total) return;
    int n = idx % N, g2 = idx / N;
    int lq = g2 & 3, jc = g2 >> 2;
    size_t k = 16 * jc + 2 * lq;
    out[idx] = pack_hl4(W[k * N + n] * 256.f, W[(k + 1) * N + n] * 256.f,
                        W[(k + 8) * N + n] * 256.f, W[(k + 9) * N + n] * 256.f);
}
// KV pack: one block per (kt, h) tile of batch bsel. K emitted hi-only.
__global__ __launch_bounds__(256) void pack_kv(
    const float* __restrict__ kv, float2* __restrict__ kpk, float2* __restrict__ vpk,
    int bsel)
{
    __shared__ float Kr[64 * 132];
    const int kt = blockIdx.x, h = blockIdx.y;
    const int b = bsel, bh = b * Hh + h;
    const float* Kp = kv + (size_t)b * Sq * 2 * Dm + (size_t)h * HDm
                         + (size_t)kt * 64 * 2 * Dm;
    const float* Vp = Kp + Dm;
    const uint32_t smu = smem_u32(Kr);
    const int tid = threadIdx.x;

    #pragma unroll
    for (int t = 0; t < 8; t++) {
        int idx = tid + t * 256;
        int row = idx >> 5, c4 = (idx & 31) * 4;
        cp16(smu + (row * 132 + c4) * 4, Kp + (size_t)row * 2 * Dm + c4);
    }
    asm volatile("cp.async.commit_group;" ::: "memory");
    asm volatile("cp.async.wait_group 0;" ::: "memory");
    __syncthreads();

    const size_t obase = (size_t)(bh * 32 + kt) * 2048;
    #pragma unroll
    for (int t = 0; t < 8; t++) {
        int idx = tid + t * 256;
        int n = idx & 63, grp = idx >> 6;
        int c = grp >> 2, lqq = grp & 3;
        const float* kr = Kr + n * 132 + c * 16 + 2 * lqq;
        kpk[obase + grp * 64 + n] =
            make_float2(h2pack(kr[0], kr[1]), h2pack(kr[8], kr[9]));
    }
    #pragma unroll
    for (int t = 0; t < 8; t++) {
        int idx = tid + t * 256;
        int d = idx & 127, grp = idx >> 7;
        int c = grp >> 2, lqq = grp & 3;
        const float* vr = Vp + (size_t)(c * 16 + 2 * lqq) * 2 * Dm + d;
        vpk[obase + grp * 128 + d] =
            make_float2(h2pack(vr[0], vr[2 * Dm]),
                        h2pack(vr[8 * 2 * Dm], vr[9 * 2 * Dm]));
    }
}

// ---------------------------------------------------------------------------
// fp16 GEMM on pre-packed operands. FULL3: 3-term Markidis; else 2-term.
// m_base: row offset (batch-split launches). CTA 128x128, BK=16, 2 CTAs/SM.
// ---------------------------------------------------------------------------
#define GSTG 1032            // float4 per stage: 512 A + 520 B (stride 130)
#define GEMM_SMEM (3 * GSTG * 16)

template<bool FULL3>
__global__ __launch_bounds__(256, 2) void gemm_hp(
    int m_base, int N, int K,
    const float4* __restrict__ Apk,
    const float4* __restrict__ Bpk,
    const float* __restrict__ bias,
    float* __restrict__ C)
{
    extern __shared__ float4 gsm[];
    const uint32_t smu = smem_u32(gsm);
    const int tid = threadIdx.x;
    const int wid = tid >> 5, lid = tid & 31;
    const int g = lid >> 2, lq = lid & 3;
    const int m0 = m_base + blockIdx.y * 128, n0 = blockIdx.x * 128;
    const int warp_m = (wid & 1) * 64;
    const int warp_n = (wid >> 1) * 32;
    const int nc = K >> 4, K16 = K >> 4;

    float acc[4][4][4];
    #pragma unroll
    for (int mt = 0; mt < 4; mt++)
        #pragma unroll
        for (int nt = 0; nt < 4; nt++)
            #pragma unroll
            for (int e = 0; e < 4; e++) acc[mt][nt][e] = 0.f;

    auto load_tile = [&](int c, int s) {
        const uint32_t sb = smu + s * (GSTG * 16);
        #pragma unroll
        for (int t = 0; t < 2; t++) {
            int idx = tid + t * 256;
            int m = idx >> 2, j = idx & 3;
            cp16(sb + ((m * 4 + j) << 4),
                 Apk + ((size_t)(m0 + m) * K16 + c) * 4 + j);
        }
        #pragma unroll
        for (int t = 0; t < 2; t++) {
            int idx = tid + t * 256;
            int j = idx >> 7, n = idx & 127;
            cp16(sb + ((512 + j * 130 + n) << 4),
                 Bpk + (size_t)(c * 4 + j) * N + n0 + n);
        }
        asm volatile("cp.async.commit_group;" ::: "memory");
    };

    load_tile(0, 0);
    load_tile(1, 1);

    for (int c = 0; c < nc; ++c) {
        if (c + 1 < nc) { asm volatile("cp.async.wait_group 1;" ::: "memory"); }
        else            { asm volatile("cp.async.wait_group 0;" ::: "memory"); }
        __syncthreads();
        if (c + 2 < nc) load_tile(c + 2, (c + 2) % 3);

        const float4* AS_ = gsm + (c % 3) * GSTG;
        const float4* BS_ = AS_ + 512;

        uint32_t Ah[4][4], Al[4][4];
        #pragma unroll
        for (int mt = 0; mt < 4; mt++) {
            float4 fa = AS_[(warp_m + mt * 16 + g) * 4 + lq];
            float4 fb = AS_[(warp_m + mt * 16 + g + 8) * 4 + lq];
            Ah[mt][0] = FU(fa.x); Ah[mt][1] = FU(fb.x);
            Ah[mt][2] = FU(fa.y); Ah[mt][3] = FU(fb.y);
            if (FULL3) {
                Al[mt][0] = FU(fa.z); Al[mt][1] = FU(fb.z);
                Al[mt][2] = FU(fa.w); Al[mt][3] = FU(fb.w);
            }
        }
        uint32_t Bh[4][2], Bl[4][2];
        #pragma unroll
        for (int nt = 0; nt < 4; nt++) {
            float4 f = BS_[lq * 130 + warp_n + nt * 8 + g];
            Bh[nt][0] = FU(f.x); Bh[nt][1] = FU(f.y);
            Bl[nt][0] = FU(f.z); Bl[nt][1] = FU(f.w);
        }
        #pragma unroll
        for (int mt = 0; mt < 4; mt++)
            #pragma unroll
            for (int nt = 0; nt < 4; nt++) {
                mma_f16(acc[mt][nt], Ah[mt][0], Ah[mt][1], Ah[mt][2], Ah[mt][3],
                        Bl[nt][0], Bl[nt][1]);
                if (FULL3)
                    mma_f16(acc[mt][nt], Al[mt][0], Al[mt][1], Al[mt][2], Al[mt][3],
                            Bh[nt][0], Bh[nt][1]);
                mma_f16(acc[mt][nt], Ah[mt][0], Ah[mt][1], Ah[mt][2], Ah[mt][3],
                        Bh[nt][0], Bh[nt][1]);
            }
    }

    const float s = 1.f / 256.f;
    #pragma unroll
    for (int mt = 0; mt < 4; mt++) {
        const int r0 = m0 + warp_m + mt * 16 + g;
        #pragma unroll
        for (int nt = 0; nt < 4; nt++) {
            const int col = n0 + warp_n + nt * 8 + lq * 2;
            const float2 b2 = *(const float2*)(bias + col);
            float2 o;
            o.x = acc[mt][nt][0] * s + b2.x;
            o.y = acc[mt][nt][1] * s + b2.y;
            *(float2*)(C + (size_t)r0 * N + col) = o;
            o.x = acc[mt][nt][2] * s + b2.x;
            o.y = acc[mt][nt][3] * s + b2.y;
            *(float2*)(C + (size_t)(r0 + 8) * N + col) = o;
        }
    }
}

// ---------------------------------------------------------------------------
// LayerNorm over last dim (512), emitting packed fp16 hi/lo fragments.
// row = row_base + blockIdx.x (batch-split launches).
// ---------------------------------------------------------------------------
__global__ __launch_bounds__(256) void ln512_pack(
    const float* __restrict__ x,
    const float* __restrict__ g,
    const float* __restrict__ b,
    float4* __restrict__ out,
    int row_base)
{
    __shared__ float row_sh[512];
    const int row = row_base + blockIdx.x;
    const float* xr = x + (size_t)row * Ll;
    const int tid = threadIdx.x;

    float v0 = xr[tid];
    float v1 = xr[tid + 256];
    float s  = v0 + v1;
    float sq = v0 * v0 + v1 * v1;

    #pragma unroll
    for (int o = 16; o > 0; o >>= 1) {
        s  += __shfl_xor_sync(0xffffffffu, s,  o);
        sq += __shfl_xor_sync(0xffffffffu, sq, o);
    }
    __shared__ float ss[8], ssq[8];
    __shared__ float mean_sh, inv_sh;
    const int w = tid >> 5;
    if ((tid & 31) == 0) { ss[w] = s; ssq[w] = sq; }
    __syncthreads();
    if (tid == 0) {
        float S = 0.f, SQ = 0.f;
        #pragma unroll
        for (int i = 0; i < 8; i++) { S += ss[i]; SQ += ssq[i]; }
        float m = S * (1.f / Ll);
        float var = SQ * (1.f / Ll) - m * m;
        mean_sh = m;
        inv_sh = rsqrtf(var + 1e-5f);
    }
    __syncthreads();
    const float m = mean_sh, inv = inv_sh;
    row_sh[tid]       = (v0 - m) * inv * g[tid]       + b[tid];
    row_sh[tid + 256] = (v1 - m) * inv * g[tid + 256] + b[tid + 256];
    __syncthreads();
    if (tid < 128) {
        int jc = tid >> 2, lq = tid & 3;
        const float* p = row_sh + 16 * jc + 2 * lq;
        out[(size_t)row * 128 + tid] = pack_hl4(p[0], p[1], p[8], p[9]);
    }
}

// ---------------------------------------------------------------------------
// Flash attention (single batch bsel), K hi-only 2-term QK, 1x fp16 PV.
// Scores in log2 units. Output written as packed apk fragments.
// ---------------------------------------------------------------------------
#define STG_F  8448                  // floats per stage: K 4224 + V 4224
#define KS_F(s) ((s) * STG_F)
#define VS_F(s) ((s) * STG_F + 4224)
#define P_F    25344
#define MASK_B 121856                // bytes
#define ATT_SMEM 122048

__global__ __launch_bounds__(256, 1) void attn_mma(
    const float* __restrict__ q,
    const float2* __restrict__ kpk,
    const float2* __restrict__ vpk,
    const unsigned char* __restrict__ mask,
    float4* __restrict__ apk,
    int bsel)
{
    extern __shared__ float sm[];
    unsigned char* smb = (unsigned char*)sm;

    const int b = bsel, h = blockIdx.y;
    const int bh = b * Hh + h;
    const int qb = gridDim.x - 1 - blockIdx.x;   // heavy blocks first
    const int q0 = qb * 128;
    const int ktmax = 2 * qb + 1;

    const int tid = threadIdx.x;
    const int wid = tid >> 5, lid = tid & 31;
    const int g = lid >> 2, lq = lid & 3;
    const int warp_m = wid * 16;

    const float* Qp = q + (size_t)b * Sq * Dm + (size_t)h * HDm;
    const unsigned char* mp = mask + (size_t)b * Sq;

    const uint32_t smu = smem_u32(sm);
    const float SCL2 = 0.08838834764831845f * 1.4426950408889634f;

    // ---- stage Q raw (fits inside stage area; done before any load_kv) ----
    #pragma unroll
    for (int t = 0; t < 16; t++) {
        int idx = tid + t * 256;
        int row = idx >> 5, c4 = (idx & 31) << 2;
        cp16(smu + (row * 132 + c4) * 4, Qp + (size_t)(q0 + row) * Dm + c4);
    }
    asm volatile("cp.async.commit_group;" ::: "memory");
    asm volatile("cp.async.wait_group 0;" ::: "memory");
    __syncthreads();

    uint32_t Qh[8][4], Ql[8][4];
    #pragma unroll
    for (int c = 0; c < 8; c++)
        #pragma unroll
        for (int e = 0; e < 4; e++) {
            int row = warp_m + g + (e & 1) * 8;
            int col = c * 16 + 2 * lq + (e >> 1) * 8;
            float a0 = sm[row * 132 + col] * SCL2;
            float a1 = sm[row * 132 + col + 1] * SCL2;
            __half h0 = __float2half_rn(a0), h1 = __float2half_rn(a1);
            __half2 hp = __halves2half2(h0, h1);
            Qh[c][e] = *(uint32_t*)&hp;
            Ql[c][e] = FU(h2pack(a0 - __half2float(h0), a1 - __half2float(h1)));
        }
    __syncthreads();

    auto load_kv = [&](int kt, int s) {
        const float2* kg = kpk + (size_t)(bh * 32 + kt) * 2048;
        const float2* vg = vpk + (size_t)(bh * 32 + kt) * 2048;
        #pragma unroll
        for (int t = 0; t < 4; t++) {
            int idx = tid + t * 256;
            int grp = idx >> 5, np = idx & 31;
            cp16(smu + KS_F(s) * 4 + (grp * 66 + 2 * np) * 8, kg + grp * 64 + 2 * np);
        }
        #pragma unroll
        for (int t = 0; t < 4; t++) {
            int idx = tid + t * 256;
            int r = idx >> 6, dd = idx & 63;
            cp16(smu + VS_F(s) * 4 + (r * 132 + 2 * dd) * 8, vg + r * 128 + 2 * dd);
        }
        if (tid < 4)
            cp16(smu + MASK_B + s * 64 + tid * 16, mp + kt * 64 + tid * 16);
        asm volatile("cp.async.commit_group;" ::: "memory");
    };

    load_kv(0, 0);
    load_kv(1, 1);

    const int row0 = q0 + warp_m + g;
    const int row1 = row0 + 8;
    float m_i0 = -CUDART_INF_F, m_i1 = -CUDART_INF_F;
    float l0 = 0.f, l1 = 0.f;
    float acc[16][4];
    #pragma unroll
    for (int nt = 0; nt < 16; nt++)
        #pragma unroll
        for (int e = 0; e < 4; e++) acc[nt][e] = 0.f;

    float2* pf2 = (float2*)(sm + P_F);

    for (int kt = 0; kt <= ktmax; ++kt) {
        const int st = kt % 3;
        if (kt < ktmax) { asm volatile("cp.async.wait_group 1;" ::: "memory"); }
        else            { asm volatile("cp.async.wait_group 0;" ::: "memory"); }
        __syncthreads();
        if (kt + 2 <= ktmax) load_kv(kt + 2, (kt + 2) % 3);

        const float2* kf2 = (const float2*)(sm + KS_F(st));
        const float2* vf2 = (const float2*)(sm + VS_F(st));
        const unsigned char* mk = smb + MASK_B + st * 64;

        // ---- scores: S = Q @ K^T  (2-term fp16, K hi-only, log2 units) ----
        float sc[8][4];
        #pragma unroll
        for (int nt = 0; nt < 8; nt++)
            #pragma unroll
            for (int e = 0; e < 4; e++) sc[nt][e] = 0.f;

        #pragma unroll 4
        for (int c = 0; c < 8; c++) {
            const float2* kp_ = kf2 + (c * 4 + lq) * 66;
            #pragma unroll
            for (int nt = 0; nt < 8; nt++) {
                float2 kk = kp_[nt * 8 + g];
                mma_f16(sc[nt], Ql[c][0], Ql[c][1], Ql[c][2], Ql[c][3],
                        FU(kk.x), FU(kk.y));
                mma_f16(sc[nt], Qh[c][0], Qh[c][1], Qh[c][2], Qh[c][3],
                        FU(kk.x), FU(kk.y));
            }
        }

        // ---- mask + row max (no scale mul; Q carries it) ----
        const bool diag = (kt >= 2 * qb);
        float m0 = -CUDART_INF_F, m1 = -CUDART_INF_F;
        #pragma unroll
        for (int nt = 0; nt < 8; nt++) {
            const int cl = nt * 8 + 2 * lq;
            const int cg = kt * 64 + cl;
            const bool pk0 = mk[cl] != 0, pk1 = mk[cl + 1] != 0;
            float v0 = (pk0 || (diag && cg     > row0)) ? -CUDART_INF_F : sc[nt][0];
            float v1 = (pk1 || (diag && cg + 1 > row0)) ? -CUDART_INF_F : sc[nt][1];
            float v2 = (pk0 || (diag && cg     > row1)) ? -CUDART_INF_F : sc[nt][2];
            float v3 = (pk1 || (diag && cg + 1 > row1)) ? -CUDART_INF_F : sc[nt][3];
            sc[nt][0] = v0; sc[nt][1] = v1; sc[nt][2] = v2; sc[nt][3] = v3;
            m0 = fmaxf(m0, fmaxf(v0, v1));
            m1 = fmaxf(m1, fmaxf(v2, v3));
        }
        m0 = fmaxf(m0, __shfl_xor_sync(0xffffffffu, m0, 1));
        m0 = fmaxf(m0, __shfl_xor_sync(0xffffffffu, m0, 2));
        m1 = fmaxf(m1, __shfl_xor_sync(0xffffffffu, m1, 1));
        m1 = fmaxf(m1, __shfl_xor_sync(0xffffffffu, m1, 2));

        const float mn0 = fmaxf(m_i0, m0), mn1 = fmaxf(m_i1, m1);
        const float corr0 = (mn0 == -CUDART_INF_F) ? 1.f : fast_exp2(m_i0 - mn0);
        const float corr1 = (mn1 == -CUDART_INF_F) ? 1.f : fast_exp2(m_i1 - mn1);
        const float base0 = (mn0 == -CUDART_INF_F) ? 0.f : mn0;
        const float base1 = (mn1 == -CUDART_INF_F) ? 0.f : mn1;

        float psum0 = 0.f, psum1 = 0.f;
        uint32_t ptop_prev = 0, pbot_prev = 0;
        __syncwarp();
        #pragma unroll
        for (int nt = 0; nt < 8; nt++) {
            float p0 = (sc[nt][0] == -CUDART_INF_F) ? 0.f : fast_exp2(sc[nt][0] - base0);
            float p1 = (sc[nt][1] == -CUDART_INF_F) ? 0.f : fast_exp2(sc[nt][1] - base0);
            float p2 = (sc[nt][2] == -CUDART_INF_F) ? 0.f : fast_exp2(sc[nt][2] - base1);
            float p3 = (sc[nt][3] == -CUDART_INF_F) ? 0.f : fast_exp2(sc[nt][3] - base1);
            psum0 += p0 + p1;
            psum1 += p2 + p3;
            uint32_t top = FU(h2pack(p0, p1));
            uint32_t bot = FU(h2pack(p2, p3));
            if (nt & 1) {
                const int c = nt >> 1;
                pf2[(warp_m + g) * 20 + c * 4 + lq] =
                    make_float2(__uint_as_float(ptop_prev), __uint_as_float(top));
                pf2[(warp_m + g + 8) * 20 + c * 4 + lq] =
                    make_float2(__uint_as_float(pbot_prev), __uint_as_float(bot));
            } else { ptop_prev = top; pbot_prev = bot; }
        }
        psum0 += __shfl_xor_sync(0xffffffffu, psum0, 1);
        psum0 += __shfl_xor_sync(0xffffffffu, psum0, 2);
        psum1 += __shfl_xor_sync(0xffffffffu, psum1, 1);
        psum1 += __shfl_xor_sync(0xffffffffu, psum1, 2);
        l0 = l0 * corr0 + psum0;
        l1 = l1 * corr1 + psum1;
        m_i0 = mn0; m_i1 = mn1;

        #pragma unroll
        for (int nt = 0; nt < 16; nt++) {
            acc[nt][0] *= corr0; acc[nt][1] *= corr0;
            acc[nt][2] *= corr1; acc[nt][3] *= corr1;
        }
        __syncwarp();

        // ---- O += P @ V  (1x fp16, packed) ----
        #pragma unroll
        for (int c = 0; c < 4; c++) {
            float2 pa = pf2[(warp_m + g) * 20 + c * 4 + lq];
            float2 pb = pf2[(warp_m + g + 8) * 20 + c * 4 + lq];
            uint32_t A0 = FU(pa.x), A1 = FU(pb.x), A2 = FU(pa.y), A3 = FU(pb.y);
            const float2* vp = vf2 + (c * 4 + lq) * 132;
            #pragma unroll
            for (int nt = 0; nt < 16; nt++) {
                float2 vv = vp[nt * 8 + g];
                mma_f16(acc[nt], A0, A1, A2, A3, FU(vv.x), FU(vv.y));
            }
        }
    }

    // ---- epilogue: packed fragments (row stride 512 float4) ----
    const float inv0 = (l0 > 0.f) ? (1.f / l0) : 0.f;
    const float inv1 = (l1 > 0.f) ? (1.f / l1) : 0.f;
    const size_t fb0 = (size_t)(b * Sq + row0) * 512 + (h * 8) * 4 + lq;
    const size_t fb1 = (size_t)(b * Sq + row1) * 512 + (h * 8) * 4 + lq;
    #pragma unroll
    for (int c = 0; c < 8; c++) {
        apk[fb0 + c * 4] = pack_hl4(acc[2*c][0] * inv0, acc[2*c][1] * inv0,
                                    acc[2*c+1][0] * inv0, acc[2*c+1][1] * inv0);
        apk[fb1 + c * 4] = pack_hl4(acc[2*c][2] * inv1, acc[2*c][3] * inv1,
                                    acc[2*c+1][2] * inv1, acc[2*c+1][3] * inv1);
    }
}

// ---------------------------------------------------------------------------
// Launch — batch-split pipelined DAG, 3 streams, each event recorded once
// ---------------------------------------------------------------------------
extern "C" void kernel_launch(void* const* d_in, const int* in_sizes, int n_in,
                              void* d_out, int out_size)
{
    const float*         x        = (const float*)d_in[0];
    const unsigned char* mask     = (const unsigned char*)d_in[1];
    const float*         wq_down  = (const float*)d_in[2];
    const float*         bq_down  = (const float*)d_in[3];
    const float*         gq_ln    = (const float*)d_in[4];
    const float*         bq_ln    = (const float*)d_in[5];
    const float*         wq_up    = (const float*)d_in[6];
    const float*         bq_up    = (const float*)d_in[7];
    const float*         wkv_down = (const float*)d_in[8];
    const float*         bkv_down = (const float*)d_in[9];
    const float*         gkv_ln   = (const float*)d_in[10];
    const float*         bkv_ln   = (const float*)d_in[11];
    const float*         wkv_up   = (const float*)d_in[12];
    const float*         bkv_up   = (const float*)d_in[13];
    const float*         w_out    = (const float*)d_in[14];
    const float*         b_out    = (const float*)d_in[15];
    float* out = (float*)d_out;

    float *qlat, *qb, *kvlat, *kvb;
    float4 *apk, *lpkq, *lpkkv, *wqd, *wkvd, *wqu, *wkvu, *wout;
    float2 *kpk, *vpk;
    cudaGetSymbolAddress((void**)&qlat,  g_qlat);
    cudaGetSymbolAddress((void**)&qb,    g_q);
    cudaGetSymbolAddress((void**)&kvlat, g_kvlat);
    cudaGetSymbolAddress((void**)&kvb,   g_kv);
    cudaGetSymbolAddress((void**)&apk,   g_apk);
    cudaGetSymbolAddress((void**)&lpkq,  g_lpkq);
    cudaGetSymbolAddress((void**)&lpkkv, g_lpkkv);
    cudaGetSymbolAddress((void**)&kpk,   g_kpk);
    cudaGetSymbolAddress((void**)&vpk,   g_vpk);
    cudaGetSymbolAddress((void**)&wqd,   g_wqd_pk);
    cudaGetSymbolAddress((void**)&wkvd,  g_wkvd_pk);
    cudaGetSymbolAddress((void**)&wqu,   g_wqu_pk);
    cudaGetSymbolAddress((void**)&wkvu,  g_wkvu_pk);
    cudaGetSymbolAddress((void**)&wout,  g_wout_pk);

    cudaFuncSetAttribute(attn_mma,
                         cudaFuncAttributeMaxDynamicSharedMemorySize, ATT_SMEM);
    cudaFuncSetAttribute(gemm_hp<true>,
                         cudaFuncAttributeMaxDynamicSharedMemorySize, GEMM_SMEM);
    cudaFuncSetAttribute(gemm_hp<false>,
                         cudaFuncAttributeMaxDynamicSharedMemorySize, GEMM_SMEM);

    // streams / events (created once; safe — no device allocation rules touched)
    static cudaStream_t sA = nullptr, sB = nullptr, sC = nullptr;
    static cudaEvent_t eRoot, eApk, eWqU, eWkvU, eWout, eQb, eKVd, eEnd0, eEnd1;
    if (!sA) {
        cudaStreamCreateWithFlags(&sA, cudaStreamNonBlocking);
        cudaStreamCreateWithFlags(&sB, cudaStreamNonBlocking);
        cudaStreamCreateWithFlags(&sC, cudaStreamNonBlocking);
        cudaEventCreateWithFlags(&eRoot, cudaEventDisableTiming);
        cudaEventCreateWithFlags(&eApk,  cudaEventDisableTiming);
        cudaEventCreateWithFlags(&eWqU,  cudaEventDisableTiming);
        cudaEventCreateWithFlags(&eWkvU, cudaEventDisableTiming);
        cudaEventCreateWithFlags(&eWout, cudaEventDisableTiming);
        cudaEventCreateWithFlags(&eQb,   cudaEventDisableTiming);
        cudaEventCreateWithFlags(&eKVd,  cudaEventDisableTiming);
        cudaEventCreateWithFlags(&eEnd0, cudaEventDisableTiming);
        cudaEventCreateWithFlags(&eEnd1, cudaEventDisableTiming);
    }

    // fork
    cudaEventRecord(eRoot, 0);
    cudaStreamWaitEvent(sA, eRoot, 0);
    cudaStreamWaitEvent(sB, eRoot, 0);
    cudaStreamWaitEvent(sC, eRoot, 0);

    // stream 0: pack input activations
    {
        int tot = Mrows * Dm / 4;
        pack_act<<<tot / 256, 256, 0, 0>>>(x, apk, Dm, tot);
        cudaEventRecord(eApk, 0);
    }
    // sC: late weight packs (hidden under down-gemms)
    {
        int t1 = (Ll / 16) * 4 * Dm;
        pack_w<<<t1 / 256, 256, 0, sC>>>(wq_up, wqu, Dm, t1);
        cudaEventRecord(eWqU, sC);
        int t2 = (Ll / 16) * 4 * 2 * Dm;
        pack_w<<<t2 / 256, 256, 0, sC>>>(wkv_up, wkvu, 2 * Dm, t2);
        cudaEventRecord(eWkvU, sC);
        int t3 = (Dm / 16) * 4 * Dm;
        pack_w<<<t3 / 256, 256, 0, sC>>>(w_out, wout, Dm, t3);
        cudaEventRecord(eWout, sC);
    }
    const int totd = (Dm / 16) * 4 * Ll;
    // sA: Q path (full M)
    pack_w<<<totd / 256, 256, 0, sA>>>(wq_down, wqd, Ll, totd);
    cudaStreamWaitEvent(sA, eApk, 0);
    gemm_hp<true><<<dim3(Ll / 128, Mrows / 128), 256, GEMM_SMEM, sA>>>(
        0, Ll, Dm, apk, wqd, bq_down, qlat);
    ln512_pack<<<Mrows, 256, 0, sA>>>(qlat, gq_ln, bq_ln, lpkq, 0);
    cudaStreamWaitEvent(sA, eWqU, 0);
    gemm_hp<false><<<dim3(Dm / 128, Mrows / 128), 256, GEMM_SMEM, sA>>>(
        0, Dm, Ll, lpkq, wqu, bq_up, qb);
    cudaEventRecord(eQb, sA);

    // sB: KV down (full M), then batch-0 pipeline
    pack_w<<<totd / 256, 256, 0, sB>>>(wkv_down, wkvd, Ll, totd);
    cudaStreamWaitEvent(sB, eApk, 0);
    gemm_hp<true><<<dim3(Ll / 128, Mrows / 128), 256, GEMM_SMEM, sB>>>(
        0, Ll, Dm, apk, wkvd, bkv_down, kvlat);
    cudaEventRecord(eKVd, sB);

    // batch 0 on sB
    ln512_pack<<<Sq, 256, 0, sB>>>(kvlat, gkv_ln, bkv_ln, lpkkv, 0);
    cudaStreamWaitEvent(sB, eWkvU, 0);
    gemm_hp<false><<<dim3(2 * Dm / 128, Sq / 128), 256, GEMM_SMEM, sB>>>(
        0, 2 * Dm, Ll, lpkkv, wkvu, bkv_up, kvb);
    pack_kv<<<dim3(Sq / 64, Hh), 256, 0, sB>>>(kvb, kpk, vpk, 0);
    cudaStreamWaitEvent(sB, eQb, 0);
    attn_mma<<<dim3(Sq / 128, Hh), 256, ATT_SMEM, sB>>>(qb, kpk, vpk, mask, apk, 0);
    cudaStreamWaitEvent(sB, eWout, 0);
    gemm_hp<false><<<dim3(Dm / 128, Sq / 128), 256, GEMM_SMEM, sB>>>(
        0, Dm, Dm, apk, wout, b_out, out);
    cudaEventRecord(eEnd0, sB);

    // batch 1 on sA (sA already produced qb; kv_down via eKVd)
    cudaStreamWaitEvent(sA, eKVd, 0);
    ln512_pack<<<Sq, 256, 0, sA>>>(kvlat, gkv_ln, bkv_ln, lpkkv, Sq);
    cudaStreamWaitEvent(sA, eWkvU, 0);
    gemm_hp<false><<<dim3(2 * Dm / 128, Sq / 128), 256, GEMM_SMEM, sA>>>(
        Sq, 2 * Dm, Ll, lpkkv, wkvu, bkv_up, kvb);
    pack_kv<<<dim3(Sq / 64, Hh), 256, 0, sA>>>(kvb, kpk, vpk, 1);
    attn_mma<<<dim3(Sq / 128, Hh), 256, ATT_SMEM, sA>>>(qb, kpk, vpk, mask, apk, 1);
    cudaStreamWaitEvent(sA, eWout, 0);
    gemm_hp<false><<<dim3(Dm / 128, Sq / 128), 256, GEMM_SMEM, sA>>>(
        Sq, Dm, Dm, apk, wout, b_out, out);
    cudaEventRecord(eEnd1, sA);

    // join both pipelines back onto stream 0 (harness observes stream 0)
    cudaStreamWaitEvent(0, eEnd0, 0);
    cudaStreamWaitEvent(0, eEnd1, 0);
}